// round 6
// baseline (speedup 1.0000x reference)
#include <cuda_runtime.h>
#include <cuda_bf16.h>
#include <cstdint>
#include <math.h>

// ---------------- problem constants ----------------
#define B_    8
#define S_    1024
#define HID_  2048
#define H_    16
#define D_    128
#define M_    (B_*S_)      // 8192 token rows
#define FF_   (4*HID_)     // 8192

// weight plane offsets (elements)
#define OFF_Q   0L
#define OFF_K   4194304L
#define OFF_V   8388608L
#define OFF_O   12582912L
#define OFF_W1  16777216L
#define OFF_W2  33554432L
#define W_TOTAL 50331648L

// ---------------- scratch (device globals; no allocations allowed) --------
__device__ float g_q   [(size_t)M_*HID_];
__device__ float g_k   [(size_t)M_*HID_];
__device__ float g_v   [(size_t)M_*HID_];
__device__ float g_qt  [(size_t)M_*HID_];
__device__ float g_kt  [(size_t)M_*HID_];
__device__ float g_vt  [(size_t)M_*HID_];
__device__ float g_acts[(size_t)M_*HID_];
__device__ __nv_bfloat16 g_wh  [W_TOTAL];
__device__ __nv_bfloat16 g_wl  [W_TOTAL];
__device__ __nv_bfloat16 g_xnh [(size_t)M_*HID_];
__device__ __nv_bfloat16 g_xnl [(size_t)M_*HID_];
__device__ __nv_bfloat16 g_ctxh[(size_t)M_*HID_];
__device__ __nv_bfloat16 g_ctxl[(size_t)M_*HID_];
__device__ __nv_bfloat16 g_hh  [(size_t)M_*FF_];
__device__ __nv_bfloat16 g_hl  [(size_t)M_*FF_];

// ---------------- helpers ---------------------------------------------------
__device__ __forceinline__ uint32_t hx_smem_u32(const void* p) {
    uint32_t a;
    asm("{ .reg .u64 t; cvta.to.shared.u64 t, %1; cvt.u32.u64 %0, t; }" : "=r"(a) : "l"(p));
    return a;
}
#define HX_LDSM4(r, addr) \
    asm volatile("ldmatrix.sync.aligned.m8n8.x4.shared.b16 {%0,%1,%2,%3}, [%4];" \
        : "=r"((r)[0]), "=r"((r)[1]), "=r"((r)[2]), "=r"((r)[3]) : "r"(addr))

#define HX_MMA(d, a, b0, b1) \
    asm volatile("mma.sync.aligned.m16n8k16.row.col.f32.bf16.bf16.f32 " \
        "{%0,%1,%2,%3}, {%4,%5,%6,%7}, {%8,%9}, {%0,%1,%2,%3};" \
        : "+f"((d)[0]), "+f"((d)[1]), "+f"((d)[2]), "+f"((d)[3]) \
        : "r"((a)[0]), "r"((a)[1]), "r"((a)[2]), "r"((a)[3]), "r"(b0), "r"(b1))

#define HX_CPASYNC16(dst, src) \
    asm volatile("cp.async.cg.shared.global [%0], [%1], 16;" :: "r"(dst), "l"(src) : "memory")
#define HX_CPCOMMIT() asm volatile("cp.async.commit_group;" ::: "memory")

__device__ __forceinline__ uint32_t hx_pk2(float a, float b) {
    __nv_bfloat162 t; t.x = __float2bfloat16(a); t.y = __float2bfloat16(b);
    return *(uint32_t*)&t;
}
// split float4 -> hi uint2, lo uint2 (4 bf16 each)
__device__ __forceinline__ void hx_split4(float4 v, uint2& h, uint2& l) {
    __nv_bfloat16 h0 = __float2bfloat16(v.x), h1 = __float2bfloat16(v.y);
    __nv_bfloat16 h2 = __float2bfloat16(v.z), h3 = __float2bfloat16(v.w);
    __nv_bfloat162 p0; p0.x = h0; p0.y = h1;
    __nv_bfloat162 p1; p1.x = h2; p1.y = h3;
    h.x = *(uint32_t*)&p0; h.y = *(uint32_t*)&p1;
    l.x = hx_pk2(v.x - __bfloat162float(h0), v.y - __bfloat162float(h1));
    l.y = hx_pk2(v.z - __bfloat162float(h2), v.w - __bfloat162float(h3));
}

// ---------------- weight pre-split ------------------------------------------
__global__ void __launch_bounds__(256) hx_wsplit(
    const float* __restrict__ qw, const float* __restrict__ kw,
    const float* __restrict__ vw, const float* __restrict__ ow,
    const float* __restrict__ w1, const float* __restrict__ w2,
    __nv_bfloat16* __restrict__ wh, __nv_bfloat16* __restrict__ wl)
{
    const long stride = (long)gridDim.x * blockDim.x;
    for (long i = (long)blockIdx.x * blockDim.x + threadIdx.x;
         i * 4 < W_TOTAL; i += stride) {
        const long e = i * 4;
        const float* src; long off;
        if (e < OFF_W1) {
            const int m = (int)(e >> 22);
            src = (m == 0) ? qw : (m == 1) ? kw : (m == 2) ? vw : ow;
            off = e & 4194303L;
        } else if (e < OFF_W2) { src = w1; off = e - OFF_W1; }
        else                   { src = w2; off = e - OFF_W2; }
        float4 v = *(const float4*)(src + off);
        uint2 h, l;
        hx_split4(v, h, l);
        *(uint2*)(wh + e) = h;
        *(uint2*)(wl + e) = l;
    }
}

// ---------------- split-bf16 tensor-core GEMM v3 ----------------------------
// C[M,N] = A[M,K] @ B[N,K]^T. Pre-split hi/lo bf16 planes, K-major.
// CTA 128x256, warp tile 64x64 (8 warps, 2m x 4n), K-chunk 64, 2 stages.
// Stage: Ah/Al 128x144B, Bh/Bl 256x144B.
// EPI: 0 = none (fp32 C), 1 = +Res (fp32 C), 2 = exact gelu -> bf16 hi/lo planes
#define MM3_APL   18432
#define MM3_BPL   36864
#define MM3_STAGE (2*MM3_APL + 2*MM3_BPL)   // 110592
#define MM3_SMEM  (2*MM3_STAGE)             // 221184

template<int EPI, bool QKV>
__global__ void __launch_bounds__(256, 1) mm3(
    int M, int N, int K,
    const __nv_bfloat16* __restrict__ Ah, const __nv_bfloat16* __restrict__ Al,
    const __nv_bfloat16* __restrict__ Bh, const __nv_bfloat16* __restrict__ Bl,
    const float* __restrict__ Res,
    float* __restrict__ C0, float* __restrict__ C1, float* __restrict__ C2,
    __nv_bfloat16* __restrict__ Chh, __nv_bfloat16* __restrict__ Chl,
    int tiles_n)
{
    extern __shared__ char smc[];
    const uint32_t smb = hx_smem_u32(smc);
    const int tid  = threadIdx.x;
    const int lane = tid & 31;
    const int warp = tid >> 5;
    const int wm = warp & 1;      // m offset wm*64
    const int wn = warp >> 1;     // n offset wn*64

    // supertile raster: 16 m-tiles per band
    const int SUPER = 16;
    const int per  = SUPER * tiles_n;
    const int band = blockIdx.x / per;
    const int rem  = blockIdx.x % per;
    const int mt  = band * SUPER + (rem % SUPER);
    int ntg = rem / SUPER;

    int sel = 0;
    if (QKV) { sel = ntg >> 3; ntg &= 7; }
    const int nt = ntg;

    const long boff = QKV ? (long)sel * 4194304L : 0L;
    const __nv_bfloat16* pAh = Ah + (long)mt * 128 * K;
    const __nv_bfloat16* pAl = Al + (long)mt * 128 * K;
    const __nv_bfloat16* pBh = Bh + boff + (long)nt * 256 * K;
    const __nv_bfloat16* pBl = Bl + boff + (long)nt * 256 * K;
    float* Cw = QKV ? (sel == 0 ? C0 : sel == 1 ? C1 : C2) : C0;

    float acc[4][8][4];
#pragma unroll
    for (int i = 0; i < 4; i++)
#pragma unroll
        for (int j = 0; j < 8; j++)
#pragma unroll
            for (int r = 0; r < 4; r++) acc[i][j][r] = 0.f;

    auto issue_chunk = [&](int c, int st) {
        const uint32_t sb = smb + st * MM3_STAGE;
        // A planes: 2048 ops (2 planes x 128 rows x 8 segs)
#pragma unroll
        for (int q = 0; q < 8; q++) {
            const int op  = tid + q * 256;
            const int pl  = op >> 10;
            const int rm  = op & 1023;
            const int r   = rm >> 3;
            const int s   = rm & 7;
            const __nv_bfloat16* src = (pl ? pAl : pAh) + (long)r * K + c * 64 + s * 8;
            const uint32_t dst = sb + pl * MM3_APL + r * 144 + s * 16;
            HX_CPASYNC16(dst, src);
        }
        // B planes: 4096 ops (2 planes x 256 rows x 8 segs)
#pragma unroll
        for (int q = 0; q < 16; q++) {
            const int op  = tid + q * 256;
            const int pl  = op >> 11;
            const int rm  = op & 2047;
            const int r   = rm >> 3;
            const int s   = rm & 7;
            const __nv_bfloat16* src = (pl ? pBl : pBh) + (long)r * K + c * 64 + s * 8;
            const uint32_t dst = sb + 2 * MM3_APL + pl * MM3_BPL + r * 144 + s * 16;
            HX_CPASYNC16(dst, src);
        }
        HX_CPCOMMIT();
    };

    const int nch = K / 64;
    issue_chunk(0, 0);
    if (nch > 1) issue_chunk(1, 1);

    for (int c = 0; c < nch; c++) {
        const int st = c & 1;
        if (c + 1 < nch) { asm volatile("cp.async.wait_group 1;" ::: "memory"); }
        else             { asm volatile("cp.async.wait_group 0;" ::: "memory"); }
        __syncthreads();

        const uint32_t stb = smb + st * MM3_STAGE;
#pragma unroll
        for (int ks = 0; ks < 4; ks++) {
            const uint32_t colb = ks * 32 + (lane >> 4) * 16;
            uint32_t ah[4][4], al[4][4], bh[4][4], bl[4][4];
#pragma unroll
            for (int im = 0; im < 4; im++) {
                const uint32_t row = wm * 64 + im * 16 + (lane & 15);
                const uint32_t ad = stb + row * 144 + colb;
                HX_LDSM4(ah[im], ad);
                HX_LDSM4(al[im], ad + MM3_APL);
            }
#pragma unroll
            for (int ib = 0; ib < 4; ib++) {
                const uint32_t row = wn * 64 + ib * 16 + (lane & 15);
                const uint32_t bd = stb + 2 * MM3_APL + row * 144 + colb;
                HX_LDSM4(bh[ib], bd);
                HX_LDSM4(bl[ib], bd + MM3_BPL);
            }
            // product-outermost: long RAW reuse distance on each acc
#pragma unroll
            for (int im = 0; im < 4; im++)
#pragma unroll
                for (int ib = 0; ib < 4; ib++)
#pragma unroll
                    for (int t = 0; t < 2; t++)
                        HX_MMA(acc[im][ib*2+t], ah[im], bh[ib][t], bh[ib][t+2]);
#pragma unroll
            for (int im = 0; im < 4; im++)
#pragma unroll
                for (int ib = 0; ib < 4; ib++)
#pragma unroll
                    for (int t = 0; t < 2; t++)
                        HX_MMA(acc[im][ib*2+t], ah[im], bl[ib][t], bl[ib][t+2]);
#pragma unroll
            for (int im = 0; im < 4; im++)
#pragma unroll
                for (int ib = 0; ib < 4; ib++)
#pragma unroll
                    for (int t = 0; t < 2; t++)
                        HX_MMA(acc[im][ib*2+t], al[im], bh[ib][t], bh[ib][t+2]);
        }
        __syncthreads();
        if (c + 2 < nch) issue_chunk(c + 2, st);
    }

    // ---- epilogue ----
#pragma unroll
    for (int im = 0; im < 4; im++)
#pragma unroll
        for (int j = 0; j < 8; j++) {
            const long row0 = (long)mt * 128 + wm * 64 + im * 16 + (lane >> 2);
            const long col  = (long)nt * 256 + wn * 64 + j * 8 + (lane & 3) * 2;
            const long o0 = row0 * N + col;
            const long o1 = (row0 + 8) * N + col;
            float2 v0 = { acc[im][j][0], acc[im][j][1] };
            float2 v1 = { acc[im][j][2], acc[im][j][3] };
            if (EPI == 2) {
                v0.x = 0.5f*v0.x*(1.0f + erff(v0.x*0.70710678118654752f));
                v0.y = 0.5f*v0.y*(1.0f + erff(v0.y*0.70710678118654752f));
                v1.x = 0.5f*v1.x*(1.0f + erff(v1.x*0.70710678118654752f));
                v1.y = 0.5f*v1.y*(1.0f + erff(v1.y*0.70710678118654752f));
                __nv_bfloat16 h0 = __float2bfloat16(v0.x), h1 = __float2bfloat16(v0.y);
                __nv_bfloat16 h2 = __float2bfloat16(v1.x), h3 = __float2bfloat16(v1.y);
                __nv_bfloat162 ph0; ph0.x = h0; ph0.y = h1;
                __nv_bfloat162 ph1; ph1.x = h2; ph1.y = h3;
                *(__nv_bfloat162*)(Chh + o0) = ph0;
                *(__nv_bfloat162*)(Chh + o1) = ph1;
                __nv_bfloat162 pl0, pl1;
                pl0.x = __float2bfloat16(v0.x - __bfloat162float(h0));
                pl0.y = __float2bfloat16(v0.y - __bfloat162float(h1));
                pl1.x = __float2bfloat16(v1.x - __bfloat162float(h2));
                pl1.y = __float2bfloat16(v1.y - __bfloat162float(h3));
                *(__nv_bfloat162*)(Chl + o0) = pl0;
                *(__nv_bfloat162*)(Chl + o1) = pl1;
            } else {
                if (EPI == 1) {
                    const float2 r0 = *(const float2*)(Res + o0);
                    const float2 r1 = *(const float2*)(Res + o1);
                    v0.x += r0.x; v0.y += r0.y; v1.x += r1.x; v1.y += r1.y;
                }
                *(float2*)(Cw + o0) = v0;
                *(float2*)(Cw + o1) = v1;
            }
        }
}

// ---------------- LayerNorm -> hi/lo bf16 planes ----------------------------
__global__ void __launch_bounds__(256) hx_ln(const float* __restrict__ x,
                                             const float* __restrict__ w,
                                             __nv_bfloat16* __restrict__ outh,
                                             __nv_bfloat16* __restrict__ outl)
{
    const int row = blockIdx.x;
    const int tid = threadIdx.x;
    const float4* xr = (const float4*)(x + (long)row*HID_);
    float4 a = xr[tid];
    float4 b = xr[tid + 256];
    float s  = a.x+a.y+a.z+a.w + b.x+b.y+b.z+b.w;
    float s2 = a.x*a.x+a.y*a.y+a.z*a.z+a.w*a.w
             + b.x*b.x+b.y*b.y+b.z*b.z+b.w*b.w;
#pragma unroll
    for (int o = 16; o; o >>= 1) {
        s  += __shfl_xor_sync(0xffffffffu, s,  o);
        s2 += __shfl_xor_sync(0xffffffffu, s2, o);
    }
    __shared__ float sh[16];
    if ((tid & 31) == 0) { sh[tid >> 5] = s; sh[(tid >> 5) + 8] = s2; }
    __syncthreads();
    float ts = 0.f, ts2 = 0.f;
#pragma unroll
    for (int i = 0; i < 8; i++) { ts += sh[i]; ts2 += sh[i + 8]; }
    const float mean = ts * (1.0f/HID_);
    const float var  = ts2 * (1.0f/HID_) - mean*mean;
    const float rstd = rsqrtf(var + 1e-5f);

    const float4* wr = (const float4*)w;
    float4 w0 = wr[tid], w1v = wr[tid + 256];
    float4 o0, o1;
    o0.x = (a.x-mean)*rstd*w0.x;  o0.y = (a.y-mean)*rstd*w0.y;
    o0.z = (a.z-mean)*rstd*w0.z;  o0.w = (a.w-mean)*rstd*w0.w;
    o1.x = (b.x-mean)*rstd*w1v.x; o1.y = (b.y-mean)*rstd*w1v.y;
    o1.z = (b.z-mean)*rstd*w1v.z; o1.w = (b.w-mean)*rstd*w1v.w;

    uint2 h, l;
    hx_split4(o0, h, l);
    *(uint2*)(outh + (long)row*HID_ + tid*4) = h;
    *(uint2*)(outl + (long)row*HID_ + tid*4) = l;
    hx_split4(o1, h, l);
    *(uint2*)(outh + (long)row*HID_ + (tid+256)*4) = h;
    *(uint2*)(outl + (long)row*HID_ + (tid+256)*4) = l;
}

// ---------------- xPos rotary on K,V + transpose Q/K/V to [B*H,S,D] --------
__global__ void hx_rope(const float* __restrict__ q, const float* __restrict__ k,
                        const float* __restrict__ v, const int* __restrict__ pidx,
                        float* __restrict__ qt, float* __restrict__ kt,
                        float* __restrict__ vt)
{
    const long gid = (long)blockIdx.x * blockDim.x + threadIdx.x;
    const long total = (long)M_ * H_ * (D_/2);
    if (gid >= total) return;
    const int  i  = (int)(gid & 63);
    const int  h  = (int)((gid >> 6) & (H_-1));
    const long bs = gid >> 10;
    const int  s  = (int)(bs & (S_-1));
    const int  b  = (int)(bs >> 10);

    const long in_off  = bs*HID_ + h*D_ + 2*i;
    const long out_off = (((long)(b*H_ + h))*S_ + s)*D_ + 2*i;

    float2 qq = *(const float2*)(q + in_off);
    float2 kk = *(const float2*)(k + in_off);
    float2 vv = *(const float2*)(v + in_off);

    const float seq = (float)(pidx[0] + s - (S_/2)) * (1.0f/512.0f);
    const float df  = 2.0f * (float)(i + 1);
    const float theta = expf(-(df * (1.0f/(float)D_)) * 9.210340371976184f);
    float sn, c;
    sincosf(seq * theta, &sn, &c);
    const float zeta = (df*(1.0f/64.0f) + 51.2f) * (1.0f/52.2f);
    const float t  = powf(zeta, seq);
    const float it = 1.0f / t;

    float2 ko, vo;
    ko.x = (kk.x*c - kk.y*sn)*t;   ko.y = (kk.y*c + kk.x*sn)*t;
    vo.x = (vv.x*c - vv.y*sn)*it;  vo.y = (vv.y*c + vv.x*sn)*it;

    *(float2*)(qt + out_off) = qq;
    *(float2*)(kt + out_off) = ko;
    *(float2*)(vt + out_off) = vo;
}

// ---------------- causal flash attention (fp32, BM=BN=64, D=128) -----------
#define ATTN_SMEM_FLOATS (128*65 + 128*65 + 64*65 + 64*128)
__global__ void __launch_bounds__(256) hx_attn(
    const float* __restrict__ qt, const float* __restrict__ kt,
    const float* __restrict__ vt,
    __nv_bfloat16* __restrict__ ctxh, __nv_bfloat16* __restrict__ ctxl)
{
    extern __shared__ float smf[];
    float* Qst = smf;
    float* Kst = Qst + 128*65;
    float* Pst = Kst + 128*65;
    float* Vs  = Pst + 64*65;

    const int qtile = blockIdx.x;
    const int bh    = blockIdx.y;
    const int b = bh >> 4, h = bh & 15;
    const float* Qg = qt + ((long)bh*S_ + qtile*64)*D_;
    const float* Kg = kt + (long)bh*S_*D_;
    const float* Vg = vt + (long)bh*S_*D_;

    const int tid = threadIdx.x;
    const int d4 = tid & 31, mr = tid >> 5;
    const int tx = tid & 15, ty = tid >> 4;

#pragma unroll
    for (int p = 0; p < 8; p++) {
        const int m = mr + p*8;
        float4 qv = *(const float4*)(Qg + m*D_ + d4*4);
        Qst[(d4*4+0)*65 + m] = qv.x;
        Qst[(d4*4+1)*65 + m] = qv.y;
        Qst[(d4*4+2)*65 + m] = qv.z;
        Qst[(d4*4+3)*65 + m] = qv.w;
    }

    float mi[4], li[4], o[4][8];
#pragma unroll
    for (int i = 0; i < 4; i++) {
        mi[i] = -INFINITY; li[i] = 0.f;
#pragma unroll
        for (int c = 0; c < 8; c++) o[i][c] = 0.f;
    }
    const float scale = 0.088388347648318447f;

    for (int j = 0; j <= qtile; j++) {
        __syncthreads();
#pragma unroll
        for (int p = 0; p < 8; p++) {
            const int n = mr + p*8;
            float4 kv = *(const float4*)(Kg + (long)(j*64 + n)*D_ + d4*4);
            Kst[(d4*4+0)*65 + n] = kv.x;
            Kst[(d4*4+1)*65 + n] = kv.y;
            Kst[(d4*4+2)*65 + n] = kv.z;
            Kst[(d4*4+3)*65 + n] = kv.w;
            float4 vv = *(const float4*)(Vg + (long)(j*64 + n)*D_ + d4*4);
            *(float4*)&Vs[n*128 + d4*4] = vv;
        }
        __syncthreads();

        float sacc[4][4];
#pragma unroll
        for (int i = 0; i < 4; i++)
#pragma unroll
            for (int jj = 0; jj < 4; jj++) sacc[i][jj] = 0.f;
        for (int d = 0; d < 128; d++) {
            float qr[4], kr[4];
#pragma unroll
            for (int i = 0; i < 4; i++)  qr[i]  = Qst[d*65 + ty*4 + i];
#pragma unroll
            for (int jj = 0; jj < 4; jj++) kr[jj] = Kst[d*65 + tx*4 + jj];
#pragma unroll
            for (int i = 0; i < 4; i++)
#pragma unroll
                for (int jj = 0; jj < 4; jj++)
                    sacc[i][jj] = fmaf(qr[i], kr[jj], sacc[i][jj]);
        }

#pragma unroll
        for (int i = 0; i < 4; i++) {
            const int mg = qtile*64 + ty*4 + i;
            float rmax = -INFINITY;
#pragma unroll
            for (int jj = 0; jj < 4; jj++) {
                const int ng = j*64 + tx*4 + jj;
                float sv = sacc[i][jj] * scale;
                sv = (ng <= mg) ? sv : -INFINITY;
                sacc[i][jj] = sv;
                rmax = fmaxf(rmax, sv);
            }
#pragma unroll
            for (int off = 8; off; off >>= 1)
                rmax = fmaxf(rmax, __shfl_xor_sync(0xffffffffu, rmax, off));
            const float mnew  = fmaxf(mi[i], rmax);
            const float alpha = expf(mi[i] - mnew);
            float rsum = 0.f;
#pragma unroll
            for (int jj = 0; jj < 4; jj++) {
                const float pv = expf(sacc[i][jj] - mnew);
                sacc[i][jj] = pv;
                rsum += pv;
            }
#pragma unroll
            for (int off = 8; off; off >>= 1)
                rsum += __shfl_xor_sync(0xffffffffu, rsum, off);
            li[i] = li[i]*alpha + rsum;
            mi[i] = mnew;
#pragma unroll
            for (int c = 0; c < 8; c++) o[i][c] *= alpha;
#pragma unroll
            for (int jj = 0; jj < 4; jj++)
                Pst[(tx*4 + jj)*65 + ty*4 + i] = sacc[i][jj];
        }
        __syncthreads();

#pragma unroll 4
        for (int n = 0; n < 64; n++) {
            float pr[4], vr[8];
#pragma unroll
            for (int i = 0; i < 4; i++) pr[i] = Pst[n*65 + ty*4 + i];
#pragma unroll
            for (int c = 0; c < 8; c++) vr[c] = Vs[n*128 + tx*8 + c];
#pragma unroll
            for (int i = 0; i < 4; i++)
#pragma unroll
                for (int c = 0; c < 8; c++)
                    o[i][c] = fmaf(pr[i], vr[c], o[i][c]);
        }
    }

#pragma unroll
    for (int i = 0; i < 4; i++) {
        const float inv = 1.0f / li[i];
        const int sq = qtile*64 + ty*4 + i;
        const long off = ((long)(b*S_ + sq))*HID_ + h*D_ + tx*8;
        float4 v0 = { o[i][0]*inv, o[i][1]*inv, o[i][2]*inv, o[i][3]*inv };
        float4 v1 = { o[i][4]*inv, o[i][5]*inv, o[i][6]*inv, o[i][7]*inv };
        uint2 h0, l0, h1, l1;
        hx_split4(v0, h0, l0);
        hx_split4(v1, h1, l1);
        uint4 hv; hv.x = h0.x; hv.y = h0.y; hv.z = h1.x; hv.w = h1.y;
        uint4 lv; lv.x = l0.x; lv.y = l0.y; lv.z = l1.x; lv.w = l1.y;
        *(uint4*)(ctxh + off) = hv;
        *(uint4*)(ctxl + off) = lv;
    }
}

// ---------------- launch ----------------------------------------------------
extern "C" void kernel_launch(void* const* d_in, const int* in_sizes, int n_in,
                              void* d_out, int out_size)
{
    const float* acts_in = (const float*)d_in[0];
    const float* ln1_w   = (const float*)d_in[4];
    const float* ln2_w   = (const float*)d_in[5];
    const float* q_w     = (const float*)d_in[6];
    const float* k_w     = (const float*)d_in[7];
    const float* v_w     = (const float*)d_in[8];
    const float* o_w     = (const float*)d_in[9];
    const float* w1      = (const float*)d_in[10];
    const float* w2      = (const float*)d_in[11];
    const int*   p_index = (const int*)d_in[3];
    float* out = (float*)d_out;

    float *p_q, *p_k, *p_v, *p_qt, *p_kt, *p_vt, *p_acts;
    __nv_bfloat16 *p_wh, *p_wl, *p_xnh, *p_xnl, *p_ctxh, *p_ctxl, *p_hh, *p_hl;
    cudaGetSymbolAddress((void**)&p_q,    g_q);
    cudaGetSymbolAddress((void**)&p_k,    g_k);
    cudaGetSymbolAddress((void**)&p_v,    g_v);
    cudaGetSymbolAddress((void**)&p_qt,   g_qt);
    cudaGetSymbolAddress((void**)&p_kt,   g_kt);
    cudaGetSymbolAddress((void**)&p_vt,   g_vt);
    cudaGetSymbolAddress((void**)&p_acts, g_acts);
    cudaGetSymbolAddress((void**)&p_wh,   g_wh);
    cudaGetSymbolAddress((void**)&p_wl,   g_wl);
    cudaGetSymbolAddress((void**)&p_xnh,  g_xnh);
    cudaGetSymbolAddress((void**)&p_xnl,  g_xnl);
    cudaGetSymbolAddress((void**)&p_ctxh, g_ctxh);
    cudaGetSymbolAddress((void**)&p_ctxl, g_ctxl);
    cudaGetSymbolAddress((void**)&p_hh,   g_hh);
    cudaGetSymbolAddress((void**)&p_hl,   g_hl);

    cudaFuncSetAttribute(mm3<0,true>,  cudaFuncAttributeMaxDynamicSharedMemorySize, MM3_SMEM);
    cudaFuncSetAttribute(mm3<1,false>, cudaFuncAttributeMaxDynamicSharedMemorySize, MM3_SMEM);
    cudaFuncSetAttribute(mm3<2,false>, cudaFuncAttributeMaxDynamicSharedMemorySize, MM3_SMEM);

    // 0) weight pre-split (independent of LN)
    hx_wsplit<<<4096, 256>>>(q_w, k_w, v_w, o_w, w1, w2, p_wh, p_wl);

    // 1) LN1 -> xn hi/lo planes
    hx_ln<<<M_, 256>>>(acts_in, ln1_w, p_xnh, p_xnl);

    // 2) fused QKV projection: 24 n-tiles of 256 (8 per output)
    mm3<0,true><<<64*24, 256, MM3_SMEM>>>(M_, HID_, HID_,
        p_xnh, p_xnl, p_wh, p_wl, nullptr, p_q, p_k, p_v, nullptr, nullptr, 24);

    // 3) xPos rotary (K,V) + transpose
    const long nrope = (long)M_*H_*(D_/2);
    hx_rope<<<(unsigned)((nrope + 255)/256), 256>>>(p_q, p_k, p_v, p_index,
                                                    p_qt, p_kt, p_vt);

    // 4) causal flash attention -> ctx hi/lo planes
    const int attn_smem = ATTN_SMEM_FLOATS * (int)sizeof(float);
    cudaFuncSetAttribute(hx_attn, cudaFuncAttributeMaxDynamicSharedMemorySize, attn_smem);
    hx_attn<<<dim3(S_/64, B_*H_), 256, attn_smem>>>(p_qt, p_kt, p_vt, p_ctxh, p_ctxl);

    // 5) O projection + residual -> acts fp32
    mm3<1,false><<<64*8, 256, MM3_SMEM>>>(M_, HID_, HID_,
        p_ctxh, p_ctxl, p_wh + OFF_O, p_wl + OFF_O, acts_in,
        p_acts, nullptr, nullptr, nullptr, nullptr, 8);

    // 6) LN2 -> xn hi/lo planes (reuse)
    hx_ln<<<M_, 256>>>(p_acts, ln2_w, p_xnh, p_xnl);

    // 7) FFN up + exact GELU -> h hi/lo planes (N=8192, 32 n-tiles)
    mm3<2,false><<<64*32, 256, MM3_SMEM>>>(M_, FF_, HID_,
        p_xnh, p_xnl, p_wh + OFF_W1, p_wl + OFF_W1, nullptr,
        nullptr, nullptr, nullptr, p_hh, p_hl, 32);

    // 8) FFN down + residual -> output acts (K=8192)
    mm3<1,false><<<64*8, 256, MM3_SMEM>>>(M_, HID_, FF_,
        p_hh, p_hl, p_wh + OFF_W2, p_wl + OFF_W2, p_acts,
        out, nullptr, nullptr, nullptr, nullptr, 8);

    // 9) pass-through caches
    const long actN = (long)M_*HID_;
    if (n_in > 2 && (long)out_size >= actN + (long)in_sizes[1] + (long)in_sizes[2]) {
        cudaMemcpyAsync(out + actN, d_in[1],
                        (size_t)in_sizes[1]*sizeof(float),
                        cudaMemcpyDeviceToDevice);
        cudaMemcpyAsync(out + actN + in_sizes[1], d_in[2],
                        (size_t)in_sizes[2]*sizeof(float),
                        cudaMemcpyDeviceToDevice);
    }
}

// round 7
// speedup vs baseline: 1.0142x; 1.0142x over previous
#include <cuda_runtime.h>
#include <cuda_bf16.h>
#include <cstdint>
#include <math.h>

// ---------------- problem constants ----------------
#define B_    8
#define S_    1024
#define HID_  2048
#define H_    16
#define D_    128
#define M_    (B_*S_)      // 8192 token rows
#define FF_   (4*HID_)     // 8192

// weight plane offsets (elements)
#define OFF_Q   0L
#define OFF_K   4194304L
#define OFF_V   8388608L
#define OFF_O   12582912L
#define OFF_W1  16777216L
#define OFF_W2  33554432L
#define W_TOTAL 50331648L

// ---------------- scratch (device globals; no allocations allowed) --------
__device__ float g_q   [(size_t)M_*HID_];
__device__ float g_k   [(size_t)M_*HID_];
__device__ float g_v   [(size_t)M_*HID_];
__device__ float g_qt  [(size_t)M_*HID_];
__device__ float g_kt  [(size_t)M_*HID_];
__device__ float g_vt  [(size_t)M_*HID_];
__device__ float g_acts[(size_t)M_*HID_];
__device__ __nv_bfloat16 g_wh  [W_TOTAL];
__device__ __nv_bfloat16 g_wl  [W_TOTAL];
__device__ __nv_bfloat16 g_xnh [(size_t)M_*HID_];
__device__ __nv_bfloat16 g_xnl [(size_t)M_*HID_];
__device__ __nv_bfloat16 g_ctxh[(size_t)M_*HID_];
__device__ __nv_bfloat16 g_ctxl[(size_t)M_*HID_];
__device__ __nv_bfloat16 g_hh  [(size_t)M_*FF_];
__device__ __nv_bfloat16 g_hl  [(size_t)M_*FF_];

// ---------------- helpers ---------------------------------------------------
__device__ __forceinline__ uint32_t hx_smem_u32(const void* p) {
    uint32_t a;
    asm("{ .reg .u64 t; cvta.to.shared.u64 t, %1; cvt.u32.u64 %0, t; }" : "=r"(a) : "l"(p));
    return a;
}
#define HX_LDSM4(r, addr) \
    asm volatile("ldmatrix.sync.aligned.m8n8.x4.shared.b16 {%0,%1,%2,%3}, [%4];" \
        : "=r"((r)[0]), "=r"((r)[1]), "=r"((r)[2]), "=r"((r)[3]) : "r"(addr))

#define HX_MMA(d, a, b0, b1) \
    asm volatile("mma.sync.aligned.m16n8k16.row.col.f32.bf16.bf16.f32 " \
        "{%0,%1,%2,%3}, {%4,%5,%6,%7}, {%8,%9}, {%0,%1,%2,%3};" \
        : "+f"((d)[0]), "+f"((d)[1]), "+f"((d)[2]), "+f"((d)[3]) \
        : "r"((a)[0]), "r"((a)[1]), "r"((a)[2]), "r"((a)[3]), "r"(b0), "r"(b1))

#define HX_CPASYNC16(dst, src) \
    asm volatile("cp.async.cg.shared.global [%0], [%1], 16;" :: "r"(dst), "l"(src) : "memory")
#define HX_CPCOMMIT() asm volatile("cp.async.commit_group;" ::: "memory")

__device__ __forceinline__ uint32_t hx_pk2(float a, float b) {
    __nv_bfloat162 t; t.x = __float2bfloat16(a); t.y = __float2bfloat16(b);
    return *(uint32_t*)&t;
}
// split float4 -> hi uint2, lo uint2 (4 bf16 each)
__device__ __forceinline__ void hx_split4(float4 v, uint2& h, uint2& l) {
    __nv_bfloat16 h0 = __float2bfloat16(v.x), h1 = __float2bfloat16(v.y);
    __nv_bfloat16 h2 = __float2bfloat16(v.z), h3 = __float2bfloat16(v.w);
    __nv_bfloat162 p0; p0.x = h0; p0.y = h1;
    __nv_bfloat162 p1; p1.x = h2; p1.y = h3;
    h.x = *(uint32_t*)&p0; h.y = *(uint32_t*)&p1;
    l.x = hx_pk2(v.x - __bfloat162float(h0), v.y - __bfloat162float(h1));
    l.y = hx_pk2(v.z - __bfloat162float(h2), v.w - __bfloat162float(h3));
}

// ---------------- weight pre-split ------------------------------------------
__global__ void __launch_bounds__(256) hx_wsplit(
    const float* __restrict__ qw, const float* __restrict__ kw,
    const float* __restrict__ vw, const float* __restrict__ ow,
    const float* __restrict__ w1, const float* __restrict__ w2,
    __nv_bfloat16* __restrict__ wh, __nv_bfloat16* __restrict__ wl)
{
    const long stride = (long)gridDim.x * blockDim.x;
    for (long i = (long)blockIdx.x * blockDim.x + threadIdx.x;
         i * 4 < W_TOTAL; i += stride) {
        const long e = i * 4;
        const float* src; long off;
        if (e < OFF_W1) {
            const int m = (int)(e >> 22);
            src = (m == 0) ? qw : (m == 1) ? kw : (m == 2) ? vw : ow;
            off = e & 4194303L;
        } else if (e < OFF_W2) { src = w1; off = e - OFF_W1; }
        else                   { src = w2; off = e - OFF_W2; }
        float4 v = *(const float4*)(src + off);
        uint2 h, l;
        hx_split4(v, h, l);
        *(uint2*)(wh + e) = h;
        *(uint2*)(wl + e) = l;
    }
}

// ---------------- split-bf16 tensor-core GEMM v2b (cp.async pipeline) -------
// C[M,N] = A[M,K] @ B[N,K]^T. Operands pre-split hi/lo bf16 planes, K-major.
// CTA 128x128, K-chunk 64, 3 stages, 8 warps (2m x 4n), warp tile 64x32.
// Stage: Ah/Al/Bh/Bl planes, 128 rows x 144B (128B data + 16B pad).
// MMA ordering: product-outermost (16-MMA RAW reuse distance per accumulator).
// EPI: 0 = none (fp32 C), 1 = +Res (fp32 C), 2 = exact gelu -> bf16 hi/lo planes
#define MM2_PLANE   18432
#define MM2_STAGE   (4*MM2_PLANE)     // 73728
#define MM2_SMEM    (3*MM2_STAGE)     // 221184

template<int EPI, bool QKV>
__global__ void __launch_bounds__(256, 1) mm2(
    int M, int N, int K,
    const __nv_bfloat16* __restrict__ Ah, const __nv_bfloat16* __restrict__ Al,
    const __nv_bfloat16* __restrict__ Bh, const __nv_bfloat16* __restrict__ Bl,
    const float* __restrict__ Res,
    float* __restrict__ C0, float* __restrict__ C1, float* __restrict__ C2,
    __nv_bfloat16* __restrict__ Chh, __nv_bfloat16* __restrict__ Chl,
    int tiles_n)
{
    extern __shared__ char smc[];
    const uint32_t smb = hx_smem_u32(smc);
    const int tid  = threadIdx.x;
    const int lane = tid & 31;
    const int warp = tid >> 5;
    const int wm = warp & 1;
    const int wn = warp >> 1;

    // supertile raster: 16 m-tiles per band
    const int SUPER = 16;
    const int per  = SUPER * tiles_n;
    const int band = blockIdx.x / per;
    const int rem  = blockIdx.x % per;
    const int mt  = band * SUPER + (rem % SUPER);
    int ntg = rem / SUPER;

    int sel = 0;
    if (QKV) { sel = ntg >> 4; ntg &= 15; }
    const int nt = ntg;

    const long boff = QKV ? (long)sel * 4194304L : 0L;
    const __nv_bfloat16* pAh = Ah + (long)mt * 128 * K;
    const __nv_bfloat16* pAl = Al + (long)mt * 128 * K;
    const __nv_bfloat16* pBh = Bh + boff + (long)nt * 128 * K;
    const __nv_bfloat16* pBl = Bl + boff + (long)nt * 128 * K;
    float* Cw = QKV ? (sel == 0 ? C0 : sel == 1 ? C1 : C2) : C0;

    float acc[4][4][4];
#pragma unroll
    for (int i = 0; i < 4; i++)
#pragma unroll
        for (int j = 0; j < 4; j++)
#pragma unroll
            for (int r = 0; r < 4; r++) acc[i][j][r] = 0.f;

    const __nv_bfloat16* plp[4] = { pAh, pAl, pBh, pBl };

    auto issue_chunk = [&](int c, int st) {
        const uint32_t sb = smb + st * MM2_STAGE;
#pragma unroll
        for (int pl = 0; pl < 4; pl++) {
#pragma unroll
            for (int q = 0; q < 4; q++) {
                const int op = tid + q * 256;        // 0..1023
                const int r = op >> 3;               // 0..127
                const int s = op & 7;                // 16B segment
                const __nv_bfloat16* src = plp[pl] + (long)r * K + c * 64 + s * 8;
                const uint32_t dst = sb + pl * MM2_PLANE + r * 144 + s * 16;
                HX_CPASYNC16(dst, src);
            }
        }
        HX_CPCOMMIT();
    };

    const int nch = K / 64;
    issue_chunk(0, 0);
    issue_chunk(1, 1);

    for (int c = 0; c < nch; c++) {
        const int st = c % 3;
        if (c + 1 < nch) { asm volatile("cp.async.wait_group 1;" ::: "memory"); }
        else             { asm volatile("cp.async.wait_group 0;" ::: "memory"); }
        __syncthreads();
        if (c + 2 < nch) issue_chunk(c + 2, (c + 2) % 3);

        const uint32_t stb = smb + st * MM2_STAGE;
#pragma unroll
        for (int ks = 0; ks < 4; ks++) {
            const uint32_t colb = ks * 32 + (lane >> 4) * 16;
            uint32_t ah[4][4], al[4][4], bh[2][4], bl[2][4];
#pragma unroll
            for (int im = 0; im < 4; im++) {
                const uint32_t row = wm * 64 + im * 16 + (lane & 15);
                const uint32_t ad = stb + row * 144 + colb;
                HX_LDSM4(ah[im], ad);
                HX_LDSM4(al[im], ad + MM2_PLANE);
            }
#pragma unroll
            for (int ib = 0; ib < 2; ib++) {
                const uint32_t row = wn * 32 + ib * 16 + (lane & 15);
                const uint32_t bd = stb + 2 * MM2_PLANE + row * 144 + colb;
                HX_LDSM4(bh[ib], bd);
                HX_LDSM4(bl[ib], bd + MM2_PLANE);
            }
            // product-outermost passes: per-acc RAW reuse distance = 16 MMAs.
            // (Per-accumulator addition order unchanged: hh, hl, lh per ks.)
#pragma unroll
            for (int im = 0; im < 4; im++)
#pragma unroll
                for (int j = 0; j < 4; j++)
                    HX_MMA(acc[im][j], ah[im], bh[j>>1][j&1], bh[j>>1][(j&1)+2]); // hh
#pragma unroll
            for (int im = 0; im < 4; im++)
#pragma unroll
                for (int j = 0; j < 4; j++)
                    HX_MMA(acc[im][j], ah[im], bl[j>>1][j&1], bl[j>>1][(j&1)+2]); // hl
#pragma unroll
            for (int im = 0; im < 4; im++)
#pragma unroll
                for (int j = 0; j < 4; j++)
                    HX_MMA(acc[im][j], al[im], bh[j>>1][j&1], bh[j>>1][(j&1)+2]); // lh
        }
    }

    // ---- epilogue ----
#pragma unroll
    for (int im = 0; im < 4; im++)
#pragma unroll
        for (int j = 0; j < 4; j++) {
            const long row0 = (long)mt * 128 + wm * 64 + im * 16 + (lane >> 2);
            const long col  = (long)nt * 128 + wn * 32 + j * 8 + (lane & 3) * 2;
            const long o0 = row0 * N + col;
            const long o1 = (row0 + 8) * N + col;
            float2 v0 = { acc[im][j][0], acc[im][j][1] };
            float2 v1 = { acc[im][j][2], acc[im][j][3] };
            if (EPI == 2) {
                v0.x = 0.5f*v0.x*(1.0f + erff(v0.x*0.70710678118654752f));
                v0.y = 0.5f*v0.y*(1.0f + erff(v0.y*0.70710678118654752f));
                v1.x = 0.5f*v1.x*(1.0f + erff(v1.x*0.70710678118654752f));
                v1.y = 0.5f*v1.y*(1.0f + erff(v1.y*0.70710678118654752f));
                __nv_bfloat16 h0 = __float2bfloat16(v0.x), h1 = __float2bfloat16(v0.y);
                __nv_bfloat16 h2 = __float2bfloat16(v1.x), h3 = __float2bfloat16(v1.y);
                __nv_bfloat162 ph0; ph0.x = h0; ph0.y = h1;
                __nv_bfloat162 ph1; ph1.x = h2; ph1.y = h3;
                *(__nv_bfloat162*)(Chh + o0) = ph0;
                *(__nv_bfloat162*)(Chh + o1) = ph1;
                __nv_bfloat162 pl0, pl1;
                pl0.x = __float2bfloat16(v0.x - __bfloat162float(h0));
                pl0.y = __float2bfloat16(v0.y - __bfloat162float(h1));
                pl1.x = __float2bfloat16(v1.x - __bfloat162float(h2));
                pl1.y = __float2bfloat16(v1.y - __bfloat162float(h3));
                *(__nv_bfloat162*)(Chl + o0) = pl0;
                *(__nv_bfloat162*)(Chl + o1) = pl1;
            } else {
                if (EPI == 1) {
                    const float2 r0 = *(const float2*)(Res + o0);
                    const float2 r1 = *(const float2*)(Res + o1);
                    v0.x += r0.x; v0.y += r0.y; v1.x += r1.x; v1.y += r1.y;
                }
                *(float2*)(Cw + o0) = v0;
                *(float2*)(Cw + o1) = v1;
            }
        }
}

// ---------------- LayerNorm -> hi/lo bf16 planes ----------------------------
__global__ void __launch_bounds__(256) hx_ln(const float* __restrict__ x,
                                             const float* __restrict__ w,
                                             __nv_bfloat16* __restrict__ outh,
                                             __nv_bfloat16* __restrict__ outl)
{
    const int row = blockIdx.x;
    const int tid = threadIdx.x;
    const float4* xr = (const float4*)(x + (long)row*HID_);
    float4 a = xr[tid];
    float4 b = xr[tid + 256];
    float s  = a.x+a.y+a.z+a.w + b.x+b.y+b.z+b.w;
    float s2 = a.x*a.x+a.y*a.y+a.z*a.z+a.w*a.w
             + b.x*b.x+b.y*b.y+b.z*b.z+b.w*b.w;
#pragma unroll
    for (int o = 16; o; o >>= 1) {
        s  += __shfl_xor_sync(0xffffffffu, s,  o);
        s2 += __shfl_xor_sync(0xffffffffu, s2, o);
    }
    __shared__ float sh[16];
    if ((tid & 31) == 0) { sh[tid >> 5] = s; sh[(tid >> 5) + 8] = s2; }
    __syncthreads();
    float ts = 0.f, ts2 = 0.f;
#pragma unroll
    for (int i = 0; i < 8; i++) { ts += sh[i]; ts2 += sh[i + 8]; }
    const float mean = ts * (1.0f/HID_);
    const float var  = ts2 * (1.0f/HID_) - mean*mean;
    const float rstd = rsqrtf(var + 1e-5f);

    const float4* wr = (const float4*)w;
    float4 w0 = wr[tid], w1v = wr[tid + 256];
    float4 o0, o1;
    o0.x = (a.x-mean)*rstd*w0.x;  o0.y = (a.y-mean)*rstd*w0.y;
    o0.z = (a.z-mean)*rstd*w0.z;  o0.w = (a.w-mean)*rstd*w0.w;
    o1.x = (b.x-mean)*rstd*w1v.x; o1.y = (b.y-mean)*rstd*w1v.y;
    o1.z = (b.z-mean)*rstd*w1v.z; o1.w = (b.w-mean)*rstd*w1v.w;

    uint2 h, l;
    hx_split4(o0, h, l);
    *(uint2*)(outh + (long)row*HID_ + tid*4) = h;
    *(uint2*)(outl + (long)row*HID_ + tid*4) = l;
    hx_split4(o1, h, l);
    *(uint2*)(outh + (long)row*HID_ + (tid+256)*4) = h;
    *(uint2*)(outl + (long)row*HID_ + (tid+256)*4) = l;
}

// ---------------- xPos rotary on K,V + transpose Q/K/V to [B*H,S,D] --------
__global__ void hx_rope(const float* __restrict__ q, const float* __restrict__ k,
                        const float* __restrict__ v, const int* __restrict__ pidx,
                        float* __restrict__ qt, float* __restrict__ kt,
                        float* __restrict__ vt)
{
    const long gid = (long)blockIdx.x * blockDim.x + threadIdx.x;
    const long total = (long)M_ * H_ * (D_/2);
    if (gid >= total) return;
    const int  i  = (int)(gid & 63);
    const int  h  = (int)((gid >> 6) & (H_-1));
    const long bs = gid >> 10;
    const int  s  = (int)(bs & (S_-1));
    const int  b  = (int)(bs >> 10);

    const long in_off  = bs*HID_ + h*D_ + 2*i;
    const long out_off = (((long)(b*H_ + h))*S_ + s)*D_ + 2*i;

    float2 qq = *(const float2*)(q + in_off);
    float2 kk = *(const float2*)(k + in_off);
    float2 vv = *(const float2*)(v + in_off);

    const float seq = (float)(pidx[0] + s - (S_/2)) * (1.0f/512.0f);
    const float df  = 2.0f * (float)(i + 1);
    const float theta = expf(-(df * (1.0f/(float)D_)) * 9.210340371976184f);
    float sn, c;
    sincosf(seq * theta, &sn, &c);
    const float zeta = (df*(1.0f/64.0f) + 51.2f) * (1.0f/52.2f);
    const float t  = powf(zeta, seq);
    const float it = 1.0f / t;

    float2 ko, vo;
    ko.x = (kk.x*c - kk.y*sn)*t;   ko.y = (kk.y*c + kk.x*sn)*t;
    vo.x = (vv.x*c - vv.y*sn)*it;  vo.y = (vv.y*c + vv.x*sn)*it;

    *(float2*)(qt + out_off) = qq;
    *(float2*)(kt + out_off) = ko;
    *(float2*)(vt + out_off) = vo;
}

// ---------------- causal flash attention (fp32, BM=BN=64, D=128) -----------
#define ATTN_SMEM_FLOATS (128*65 + 128*65 + 64*65 + 64*128)
__global__ void __launch_bounds__(256) hx_attn(
    const float* __restrict__ qt, const float* __restrict__ kt,
    const float* __restrict__ vt,
    __nv_bfloat16* __restrict__ ctxh, __nv_bfloat16* __restrict__ ctxl)
{
    extern __shared__ float smf[];
    float* Qst = smf;
    float* Kst = Qst + 128*65;
    float* Pst = Kst + 128*65;
    float* Vs  = Pst + 64*65;

    const int qtile = blockIdx.x;
    const int bh    = blockIdx.y;
    const int b = bh >> 4, h = bh & 15;
    const float* Qg = qt + ((long)bh*S_ + qtile*64)*D_;
    const float* Kg = kt + (long)bh*S_*D_;
    const float* Vg = vt + (long)bh*S_*D_;

    const int tid = threadIdx.x;
    const int d4 = tid & 31, mr = tid >> 5;
    const int tx = tid & 15, ty = tid >> 4;

#pragma unroll
    for (int p = 0; p < 8; p++) {
        const int m = mr + p*8;
        float4 qv = *(const float4*)(Qg + m*D_ + d4*4);
        Qst[(d4*4+0)*65 + m] = qv.x;
        Qst[(d4*4+1)*65 + m] = qv.y;
        Qst[(d4*4+2)*65 + m] = qv.z;
        Qst[(d4*4+3)*65 + m] = qv.w;
    }

    float mi[4], li[4], o[4][8];
#pragma unroll
    for (int i = 0; i < 4; i++) {
        mi[i] = -INFINITY; li[i] = 0.f;
#pragma unroll
        for (int c = 0; c < 8; c++) o[i][c] = 0.f;
    }
    const float scale = 0.088388347648318447f;

    for (int j = 0; j <= qtile; j++) {
        __syncthreads();
#pragma unroll
        for (int p = 0; p < 8; p++) {
            const int n = mr + p*8;
            float4 kv = *(const float4*)(Kg + (long)(j*64 + n)*D_ + d4*4);
            Kst[(d4*4+0)*65 + n] = kv.x;
            Kst[(d4*4+1)*65 + n] = kv.y;
            Kst[(d4*4+2)*65 + n] = kv.z;
            Kst[(d4*4+3)*65 + n] = kv.w;
            float4 vv = *(const float4*)(Vg + (long)(j*64 + n)*D_ + d4*4);
            *(float4*)&Vs[n*128 + d4*4] = vv;
        }
        __syncthreads();

        float sacc[4][4];
#pragma unroll
        for (int i = 0; i < 4; i++)
#pragma unroll
            for (int jj = 0; jj < 4; jj++) sacc[i][jj] = 0.f;
        for (int d = 0; d < 128; d++) {
            float qr[4], kr[4];
#pragma unroll
            for (int i = 0; i < 4; i++)  qr[i]  = Qst[d*65 + ty*4 + i];
#pragma unroll
            for (int jj = 0; jj < 4; jj++) kr[jj] = Kst[d*65 + tx*4 + jj];
#pragma unroll
            for (int i = 0; i < 4; i++)
#pragma unroll
                for (int jj = 0; jj < 4; jj++)
                    sacc[i][jj] = fmaf(qr[i], kr[jj], sacc[i][jj]);
        }

#pragma unroll
        for (int i = 0; i < 4; i++) {
            const int mg = qtile*64 + ty*4 + i;
            float rmax = -INFINITY;
#pragma unroll
            for (int jj = 0; jj < 4; jj++) {
                const int ng = j*64 + tx*4 + jj;
                float sv = sacc[i][jj] * scale;
                sv = (ng <= mg) ? sv : -INFINITY;
                sacc[i][jj] = sv;
                rmax = fmaxf(rmax, sv);
            }
#pragma unroll
            for (int off = 8; off; off >>= 1)
                rmax = fmaxf(rmax, __shfl_xor_sync(0xffffffffu, rmax, off));
            const float mnew  = fmaxf(mi[i], rmax);
            const float alpha = expf(mi[i] - mnew);
            float rsum = 0.f;
#pragma unroll
            for (int jj = 0; jj < 4; jj++) {
                const float pv = expf(sacc[i][jj] - mnew);
                sacc[i][jj] = pv;
                rsum += pv;
            }
#pragma unroll
            for (int off = 8; off; off >>= 1)
                rsum += __shfl_xor_sync(0xffffffffu, rsum, off);
            li[i] = li[i]*alpha + rsum;
            mi[i] = mnew;
#pragma unroll
            for (int c = 0; c < 8; c++) o[i][c] *= alpha;
#pragma unroll
            for (int jj = 0; jj < 4; jj++)
                Pst[(tx*4 + jj)*65 + ty*4 + i] = sacc[i][jj];
        }
        __syncthreads();

#pragma unroll 4
        for (int n = 0; n < 64; n++) {
            float pr[4], vr[8];
#pragma unroll
            for (int i = 0; i < 4; i++) pr[i] = Pst[n*65 + ty*4 + i];
#pragma unroll
            for (int c = 0; c < 8; c++) vr[c] = Vs[n*128 + tx*8 + c];
#pragma unroll
            for (int i = 0; i < 4; i++)
#pragma unroll
                for (int c = 0; c < 8; c++)
                    o[i][c] = fmaf(pr[i], vr[c], o[i][c]);
        }
    }

#pragma unroll
    for (int i = 0; i < 4; i++) {
        const float inv = 1.0f / li[i];
        const int sq = qtile*64 + ty*4 + i;
        const long off = ((long)(b*S_ + sq))*HID_ + h*D_ + tx*8;
        float4 v0 = { o[i][0]*inv, o[i][1]*inv, o[i][2]*inv, o[i][3]*inv };
        float4 v1 = { o[i][4]*inv, o[i][5]*inv, o[i][6]*inv, o[i][7]*inv };
        uint2 h0, l0, h1, l1;
        hx_split4(v0, h0, l0);
        hx_split4(v1, h1, l1);
        uint4 hv; hv.x = h0.x; hv.y = h0.y; hv.z = h1.x; hv.w = h1.y;
        uint4 lv; lv.x = l0.x; lv.y = l0.y; lv.z = l1.x; lv.w = l1.y;
        *(uint4*)(ctxh + off) = hv;
        *(uint4*)(ctxl + off) = lv;
    }
}

// ---------------- launch ----------------------------------------------------
extern "C" void kernel_launch(void* const* d_in, const int* in_sizes, int n_in,
                              void* d_out, int out_size)
{
    const float* acts_in = (const float*)d_in[0];
    const float* ln1_w   = (const float*)d_in[4];
    const float* ln2_w   = (const float*)d_in[5];
    const float* q_w     = (const float*)d_in[6];
    const float* k_w     = (const float*)d_in[7];
    const float* v_w     = (const float*)d_in[8];
    const float* o_w     = (const float*)d_in[9];
    const float* w1      = (const float*)d_in[10];
    const float* w2      = (const float*)d_in[11];
    const int*   p_index = (const int*)d_in[3];
    float* out = (float*)d_out;

    float *p_q, *p_k, *p_v, *p_qt, *p_kt, *p_vt, *p_acts;
    __nv_bfloat16 *p_wh, *p_wl, *p_xnh, *p_xnl, *p_ctxh, *p_ctxl, *p_hh, *p_hl;
    cudaGetSymbolAddress((void**)&p_q,    g_q);
    cudaGetSymbolAddress((void**)&p_k,    g_k);
    cudaGetSymbolAddress((void**)&p_v,    g_v);
    cudaGetSymbolAddress((void**)&p_qt,   g_qt);
    cudaGetSymbolAddress((void**)&p_kt,   g_kt);
    cudaGetSymbolAddress((void**)&p_vt,   g_vt);
    cudaGetSymbolAddress((void**)&p_acts, g_acts);
    cudaGetSymbolAddress((void**)&p_wh,   g_wh);
    cudaGetSymbolAddress((void**)&p_wl,   g_wl);
    cudaGetSymbolAddress((void**)&p_xnh,  g_xnh);
    cudaGetSymbolAddress((void**)&p_xnl,  g_xnl);
    cudaGetSymbolAddress((void**)&p_ctxh, g_ctxh);
    cudaGetSymbolAddress((void**)&p_ctxl, g_ctxl);
    cudaGetSymbolAddress((void**)&p_hh,   g_hh);
    cudaGetSymbolAddress((void**)&p_hl,   g_hl);

    cudaFuncSetAttribute(mm2<0,true>,  cudaFuncAttributeMaxDynamicSharedMemorySize, MM2_SMEM);
    cudaFuncSetAttribute(mm2<1,false>, cudaFuncAttributeMaxDynamicSharedMemorySize, MM2_SMEM);
    cudaFuncSetAttribute(mm2<2,false>, cudaFuncAttributeMaxDynamicSharedMemorySize, MM2_SMEM);

    // 0) weight pre-split (independent of LN)
    hx_wsplit<<<4096, 256>>>(q_w, k_w, v_w, o_w, w1, w2, p_wh, p_wl);

    // 1) LN1 -> xn hi/lo planes
    hx_ln<<<M_, 256>>>(acts_in, ln1_w, p_xnh, p_xnl);

    // 2) fused QKV projection (48 n-tiles)
    mm2<0,true><<<64*48, 256, MM2_SMEM>>>(M_, HID_, HID_,
        p_xnh, p_xnl, p_wh, p_wl, nullptr, p_q, p_k, p_v, nullptr, nullptr, 48);

    // 3) xPos rotary (K,V) + transpose
    const long nrope = (long)M_*H_*(D_/2);
    hx_rope<<<(unsigned)((nrope + 255)/256), 256>>>(p_q, p_k, p_v, p_index,
                                                    p_qt, p_kt, p_vt);

    // 4) causal flash attention -> ctx hi/lo planes
    const int attn_smem = ATTN_SMEM_FLOATS * (int)sizeof(float);
    cudaFuncSetAttribute(hx_attn, cudaFuncAttributeMaxDynamicSharedMemorySize, attn_smem);
    hx_attn<<<dim3(S_/64, B_*H_), 256, attn_smem>>>(p_qt, p_kt, p_vt, p_ctxh, p_ctxl);

    // 5) O projection + residual -> acts fp32
    mm2<1,false><<<64*16, 256, MM2_SMEM>>>(M_, HID_, HID_,
        p_ctxh, p_ctxl, p_wh + OFF_O, p_wl + OFF_O, acts_in,
        p_acts, nullptr, nullptr, nullptr, nullptr, 16);

    // 6) LN2 -> xn hi/lo planes (reuse)
    hx_ln<<<M_, 256>>>(p_acts, ln2_w, p_xnh, p_xnl);

    // 7) FFN up + exact GELU -> h hi/lo planes
    mm2<2,false><<<64*64, 256, MM2_SMEM>>>(M_, FF_, HID_,
        p_xnh, p_xnl, p_wh + OFF_W1, p_wl + OFF_W1, nullptr,
        nullptr, nullptr, nullptr, p_hh, p_hl, 64);

    // 8) FFN down + residual -> output acts
    mm2<1,false><<<64*16, 256, MM2_SMEM>>>(M_, HID_, FF_,
        p_hh, p_hl, p_wh + OFF_W2, p_wl + OFF_W2, p_acts,
        out, nullptr, nullptr, nullptr, nullptr, 16);

    // 9) pass-through caches
    const long actN = (long)M_*HID_;
    if (n_in > 2 && (long)out_size >= actN + (long)in_sizes[1] + (long)in_sizes[2]) {
        cudaMemcpyAsync(out + actN, d_in[1],
                        (size_t)in_sizes[1]*sizeof(float),
                        cudaMemcpyDeviceToDevice);
        cudaMemcpyAsync(out + actN + in_sizes[1], d_in[2],
                        (size_t)in_sizes[2]*sizeof(float),
                        cudaMemcpyDeviceToDevice);
    }
}

// round 8
// speedup vs baseline: 1.0744x; 1.0594x over previous
#include <cuda_runtime.h>
#include <cuda_bf16.h>
#include <cstdint>
#include <math.h>

// ---------------- problem constants ----------------
#define B_    8
#define S_    1024
#define HID_  2048
#define H_    16
#define D_    128
#define M_    (B_*S_)      // 8192 token rows
#define FF_   (4*HID_)     // 8192

// weight plane offsets (elements)
#define OFF_Q   0L
#define OFF_K   4194304L
#define OFF_V   8388608L
#define OFF_O   12582912L
#define OFF_W1  16777216L
#define OFF_W2  33554432L
#define W_TOTAL 50331648L

// ---------------- scratch (device globals; no allocations allowed) --------
__device__ float g_q   [(size_t)M_*HID_];
__device__ float g_k   [(size_t)M_*HID_];
__device__ float g_v   [(size_t)M_*HID_];
__device__ float g_qt  [(size_t)M_*HID_];
__device__ float g_kt  [(size_t)M_*HID_];
__device__ float g_vt  [(size_t)M_*HID_];
__device__ float g_acts[(size_t)M_*HID_];
__device__ __nv_bfloat16 g_wh  [W_TOTAL];
__device__ __nv_bfloat16 g_wl  [W_TOTAL];
__device__ __nv_bfloat16 g_xnh [(size_t)M_*HID_];
__device__ __nv_bfloat16 g_xnl [(size_t)M_*HID_];
__device__ __nv_bfloat16 g_ctxh[(size_t)M_*HID_];
__device__ __nv_bfloat16 g_ctxl[(size_t)M_*HID_];
__device__ __nv_bfloat16 g_hh  [(size_t)M_*FF_];
__device__ __nv_bfloat16 g_hl  [(size_t)M_*FF_];

// ---------------- helpers ---------------------------------------------------
__device__ __forceinline__ uint32_t hx_smem_u32(const void* p) {
    uint32_t a;
    asm("{ .reg .u64 t; cvta.to.shared.u64 t, %1; cvt.u32.u64 %0, t; }" : "=r"(a) : "l"(p));
    return a;
}
#define HX_LDSM4(r, addr) \
    asm volatile("ldmatrix.sync.aligned.m8n8.x4.shared.b16 {%0,%1,%2,%3}, [%4];" \
        : "=r"((r)[0]), "=r"((r)[1]), "=r"((r)[2]), "=r"((r)[3]) : "r"(addr))

#define HX_MMA(d, a, b0, b1) \
    asm volatile("mma.sync.aligned.m16n8k16.row.col.f32.bf16.bf16.f32 " \
        "{%0,%1,%2,%3}, {%4,%5,%6,%7}, {%8,%9}, {%0,%1,%2,%3};" \
        : "+f"((d)[0]), "+f"((d)[1]), "+f"((d)[2]), "+f"((d)[3]) \
        : "r"((a)[0]), "r"((a)[1]), "r"((a)[2]), "r"((a)[3]), "r"(b0), "r"(b1))

#define HX_CPASYNC16(dst, src) \
    asm volatile("cp.async.cg.shared.global [%0], [%1], 16;" :: "r"(dst), "l"(src) : "memory")
#define HX_CPCOMMIT() asm volatile("cp.async.commit_group;" ::: "memory")

__device__ __forceinline__ uint32_t hx_pk2(float a, float b) {
    __nv_bfloat162 t; t.x = __float2bfloat16(a); t.y = __float2bfloat16(b);
    return *(uint32_t*)&t;
}
// split float4 -> hi uint2, lo uint2 (4 bf16 each)
__device__ __forceinline__ void hx_split4(float4 v, uint2& h, uint2& l) {
    __nv_bfloat16 h0 = __float2bfloat16(v.x), h1 = __float2bfloat16(v.y);
    __nv_bfloat16 h2 = __float2bfloat16(v.z), h3 = __float2bfloat16(v.w);
    __nv_bfloat162 p0; p0.x = h0; p0.y = h1;
    __nv_bfloat162 p1; p1.x = h2; p1.y = h3;
    h.x = *(uint32_t*)&p0; h.y = *(uint32_t*)&p1;
    l.x = hx_pk2(v.x - __bfloat162float(h0), v.y - __bfloat162float(h1));
    l.y = hx_pk2(v.z - __bfloat162float(h2), v.w - __bfloat162float(h3));
}

// ---------------- weight pre-split ------------------------------------------
__global__ void __launch_bounds__(256) hx_wsplit(
    const float* __restrict__ qw, const float* __restrict__ kw,
    const float* __restrict__ vw, const float* __restrict__ ow,
    const float* __restrict__ w1, const float* __restrict__ w2,
    __nv_bfloat16* __restrict__ wh, __nv_bfloat16* __restrict__ wl)
{
    const long stride = (long)gridDim.x * blockDim.x;
    for (long i = (long)blockIdx.x * blockDim.x + threadIdx.x;
         i * 4 < W_TOTAL; i += stride) {
        const long e = i * 4;
        const float* src; long off;
        if (e < OFF_W1) {
            const int m = (int)(e >> 22);
            src = (m == 0) ? qw : (m == 1) ? kw : (m == 2) ? vw : ow;
            off = e & 4194303L;
        } else if (e < OFF_W2) { src = w1; off = e - OFF_W1; }
        else                   { src = w2; off = e - OFF_W2; }
        float4 v = *(const float4*)(src + off);
        uint2 h, l;
        hx_split4(v, h, l);
        *(uint2*)(wh + e) = h;
        *(uint2*)(wl + e) = l;
    }
}

// ---------------- split-bf16 tensor-core GEMM v4 (512 threads) --------------
// C[M,N] = A[M,K] @ B[N,K]^T. Operands pre-split hi/lo bf16 planes, K-major.
// CTA 128x128, K-chunk 64, 3 stages, 16 warps (4m x 4n), warp tile 32x32.
// Stage: Ah/Al/Bh/Bl planes, 128 rows x 144B (128B data + 16B pad).
// EPI: 0 = none (fp32 C), 1 = +Res (fp32 C), 2 = exact gelu -> bf16 hi/lo planes
#define MM2_PLANE   18432
#define MM2_STAGE   (4*MM2_PLANE)     // 73728
#define MM2_SMEM    (3*MM2_STAGE)     // 221184

template<int EPI, bool QKV>
__global__ void __launch_bounds__(512, 1) mm2(
    int M, int N, int K,
    const __nv_bfloat16* __restrict__ Ah, const __nv_bfloat16* __restrict__ Al,
    const __nv_bfloat16* __restrict__ Bh, const __nv_bfloat16* __restrict__ Bl,
    const float* __restrict__ Res,
    float* __restrict__ C0, float* __restrict__ C1, float* __restrict__ C2,
    __nv_bfloat16* __restrict__ Chh, __nv_bfloat16* __restrict__ Chl,
    int tiles_n)
{
    extern __shared__ char smc[];
    const uint32_t smb = hx_smem_u32(smc);
    const int tid  = threadIdx.x;
    const int lane = tid & 31;
    const int warp = tid >> 5;     // 0..15
    const int wm = warp & 3;       // m offset wm*32
    const int wn = warp >> 2;      // n offset wn*32

    // supertile raster: 16 m-tiles per band
    const int SUPER = 16;
    const int per  = SUPER * tiles_n;
    const int band = blockIdx.x / per;
    const int rem  = blockIdx.x % per;
    const int mt  = band * SUPER + (rem % SUPER);
    int ntg = rem / SUPER;

    int sel = 0;
    if (QKV) { sel = ntg >> 4; ntg &= 15; }
    const int nt = ntg;

    const long boff = QKV ? (long)sel * 4194304L : 0L;
    const __nv_bfloat16* pAh = Ah + (long)mt * 128 * K;
    const __nv_bfloat16* pAl = Al + (long)mt * 128 * K;
    const __nv_bfloat16* pBh = Bh + boff + (long)nt * 128 * K;
    const __nv_bfloat16* pBl = Bl + boff + (long)nt * 128 * K;
    float* Cw = QKV ? (sel == 0 ? C0 : sel == 1 ? C1 : C2) : C0;

    float acc[2][4][4];
#pragma unroll
    for (int i = 0; i < 2; i++)
#pragma unroll
        for (int j = 0; j < 4; j++)
#pragma unroll
            for (int r = 0; r < 4; r++) acc[i][j][r] = 0.f;

    const __nv_bfloat16* plp[4] = { pAh, pAl, pBh, pBl };

    auto issue_chunk = [&](int c, int st) {
        const uint32_t sb = smb + st * MM2_STAGE;
        // 4096 ops total (4 planes x 128 rows x 8 segs), 8 per thread
#pragma unroll
        for (int q = 0; q < 8; q++) {
            const int op = tid + q * 512;        // 0..4095
            const int pl = op >> 10;             // plane 0..3
            const int rm = op & 1023;
            const int r  = rm >> 3;              // 0..127
            const int s  = rm & 7;               // 16B segment
            const __nv_bfloat16* src = plp[pl] + (long)r * K + c * 64 + s * 8;
            const uint32_t dst = sb + pl * MM2_PLANE + r * 144 + s * 16;
            HX_CPASYNC16(dst, src);
        }
        HX_CPCOMMIT();
    };

    const int nch = K / 64;
    issue_chunk(0, 0);
    issue_chunk(1, 1);

    for (int c = 0; c < nch; c++) {
        const int st = c % 3;
        if (c + 1 < nch) { asm volatile("cp.async.wait_group 1;" ::: "memory"); }
        else             { asm volatile("cp.async.wait_group 0;" ::: "memory"); }
        __syncthreads();
        if (c + 2 < nch) issue_chunk(c + 2, (c + 2) % 3);

        const uint32_t stb = smb + st * MM2_STAGE;
#pragma unroll
        for (int ks = 0; ks < 4; ks++) {
            const uint32_t colb = ks * 32 + (lane >> 4) * 16;
            uint32_t ah[2][4], al[2][4], bh[2][4], bl[2][4];
#pragma unroll
            for (int im = 0; im < 2; im++) {
                const uint32_t row = wm * 32 + im * 16 + (lane & 15);
                const uint32_t ad = stb + row * 144 + colb;
                HX_LDSM4(ah[im], ad);
                HX_LDSM4(al[im], ad + MM2_PLANE);
            }
#pragma unroll
            for (int ib = 0; ib < 2; ib++) {
                const uint32_t row = wn * 32 + ib * 16 + (lane & 15);
                const uint32_t bd = stb + 2 * MM2_PLANE + row * 144 + colb;
                HX_LDSM4(bh[ib], bd);
                HX_LDSM4(bl[ib], bd + MM2_PLANE);
            }
            // per-accumulator addition order: hh, hl, lh (per ks) — unchanged
#pragma unroll
            for (int im = 0; im < 2; im++)
#pragma unroll
                for (int j = 0; j < 4; j++)
                    HX_MMA(acc[im][j], ah[im], bh[j>>1][j&1], bh[j>>1][(j&1)+2]); // hh
#pragma unroll
            for (int im = 0; im < 2; im++)
#pragma unroll
                for (int j = 0; j < 4; j++)
                    HX_MMA(acc[im][j], ah[im], bl[j>>1][j&1], bl[j>>1][(j&1)+2]); // hl
#pragma unroll
            for (int im = 0; im < 2; im++)
#pragma unroll
                for (int j = 0; j < 4; j++)
                    HX_MMA(acc[im][j], al[im], bh[j>>1][j&1], bh[j>>1][(j&1)+2]); // lh
        }
    }

    // ---- epilogue ----
#pragma unroll
    for (int im = 0; im < 2; im++)
#pragma unroll
        for (int j = 0; j < 4; j++) {
            const long row0 = (long)mt * 128 + wm * 32 + im * 16 + (lane >> 2);
            const long col  = (long)nt * 128 + wn * 32 + j * 8 + (lane & 3) * 2;
            const long o0 = row0 * N + col;
            const long o1 = (row0 + 8) * N + col;
            float2 v0 = { acc[im][j][0], acc[im][j][1] };
            float2 v1 = { acc[im][j][2], acc[im][j][3] };
            if (EPI == 2) {
                v0.x = 0.5f*v0.x*(1.0f + erff(v0.x*0.70710678118654752f));
                v0.y = 0.5f*v0.y*(1.0f + erff(v0.y*0.70710678118654752f));
                v1.x = 0.5f*v1.x*(1.0f + erff(v1.x*0.70710678118654752f));
                v1.y = 0.5f*v1.y*(1.0f + erff(v1.y*0.70710678118654752f));
                __nv_bfloat16 h0 = __float2bfloat16(v0.x), h1 = __float2bfloat16(v0.y);
                __nv_bfloat16 h2 = __float2bfloat16(v1.x), h3 = __float2bfloat16(v1.y);
                __nv_bfloat162 ph0; ph0.x = h0; ph0.y = h1;
                __nv_bfloat162 ph1; ph1.x = h2; ph1.y = h3;
                *(__nv_bfloat162*)(Chh + o0) = ph0;
                *(__nv_bfloat162*)(Chh + o1) = ph1;
                __nv_bfloat162 pl0, pl1;
                pl0.x = __float2bfloat16(v0.x - __bfloat162float(h0));
                pl0.y = __float2bfloat16(v0.y - __bfloat162float(h1));
                pl1.x = __float2bfloat16(v1.x - __bfloat162float(h2));
                pl1.y = __float2bfloat16(v1.y - __bfloat162float(h3));
                *(__nv_bfloat162*)(Chl + o0) = pl0;
                *(__nv_bfloat162*)(Chl + o1) = pl1;
            } else {
                if (EPI == 1) {
                    const float2 r0 = *(const float2*)(Res + o0);
                    const float2 r1 = *(const float2*)(Res + o1);
                    v0.x += r0.x; v0.y += r0.y; v1.x += r1.x; v1.y += r1.y;
                }
                *(float2*)(Cw + o0) = v0;
                *(float2*)(Cw + o1) = v1;
            }
        }
}

// ---------------- LayerNorm -> hi/lo bf16 planes ----------------------------
__global__ void __launch_bounds__(256) hx_ln(const float* __restrict__ x,
                                             const float* __restrict__ w,
                                             __nv_bfloat16* __restrict__ outh,
                                             __nv_bfloat16* __restrict__ outl)
{
    const int row = blockIdx.x;
    const int tid = threadIdx.x;
    const float4* xr = (const float4*)(x + (long)row*HID_);
    float4 a = xr[tid];
    float4 b = xr[tid + 256];
    float s  = a.x+a.y+a.z+a.w + b.x+b.y+b.z+b.w;
    float s2 = a.x*a.x+a.y*a.y+a.z*a.z+a.w*a.w
             + b.x*b.x+b.y*b.y+b.z*b.z+b.w*b.w;
#pragma unroll
    for (int o = 16; o; o >>= 1) {
        s  += __shfl_xor_sync(0xffffffffu, s,  o);
        s2 += __shfl_xor_sync(0xffffffffu, s2, o);
    }
    __shared__ float sh[16];
    if ((tid & 31) == 0) { sh[tid >> 5] = s; sh[(tid >> 5) + 8] = s2; }
    __syncthreads();
    float ts = 0.f, ts2 = 0.f;
#pragma unroll
    for (int i = 0; i < 8; i++) { ts += sh[i]; ts2 += sh[i + 8]; }
    const float mean = ts * (1.0f/HID_);
    const float var  = ts2 * (1.0f/HID_) - mean*mean;
    const float rstd = rsqrtf(var + 1e-5f);

    const float4* wr = (const float4*)w;
    float4 w0 = wr[tid], w1v = wr[tid + 256];
    float4 o0, o1;
    o0.x = (a.x-mean)*rstd*w0.x;  o0.y = (a.y-mean)*rstd*w0.y;
    o0.z = (a.z-mean)*rstd*w0.z;  o0.w = (a.w-mean)*rstd*w0.w;
    o1.x = (b.x-mean)*rstd*w1v.x; o1.y = (b.y-mean)*rstd*w1v.y;
    o1.z = (b.z-mean)*rstd*w1v.z; o1.w = (b.w-mean)*rstd*w1v.w;

    uint2 h, l;
    hx_split4(o0, h, l);
    *(uint2*)(outh + (long)row*HID_ + tid*4) = h;
    *(uint2*)(outl + (long)row*HID_ + tid*4) = l;
    hx_split4(o1, h, l);
    *(uint2*)(outh + (long)row*HID_ + (tid+256)*4) = h;
    *(uint2*)(outl + (long)row*HID_ + (tid+256)*4) = l;
}

// ---------------- xPos rotary on K,V + transpose Q/K/V to [B*H,S,D] --------
__global__ void hx_rope(const float* __restrict__ q, const float* __restrict__ k,
                        const float* __restrict__ v, const int* __restrict__ pidx,
                        float* __restrict__ qt, float* __restrict__ kt,
                        float* __restrict__ vt)
{
    const long gid = (long)blockIdx.x * blockDim.x + threadIdx.x;
    const long total = (long)M_ * H_ * (D_/2);
    if (gid >= total) return;
    const int  i  = (int)(gid & 63);
    const int  h  = (int)((gid >> 6) & (H_-1));
    const long bs = gid >> 10;
    const int  s  = (int)(bs & (S_-1));
    const int  b  = (int)(bs >> 10);

    const long in_off  = bs*HID_ + h*D_ + 2*i;
    const long out_off = (((long)(b*H_ + h))*S_ + s)*D_ + 2*i;

    float2 qq = *(const float2*)(q + in_off);
    float2 kk = *(const float2*)(k + in_off);
    float2 vv = *(const float2*)(v + in_off);

    const float seq = (float)(pidx[0] + s - (S_/2)) * (1.0f/512.0f);
    const float df  = 2.0f * (float)(i + 1);
    const float theta = expf(-(df * (1.0f/(float)D_)) * 9.210340371976184f);
    float sn, c;
    sincosf(seq * theta, &sn, &c);
    const float zeta = (df*(1.0f/64.0f) + 51.2f) * (1.0f/52.2f);
    const float t  = powf(zeta, seq);
    const float it = 1.0f / t;

    float2 ko, vo;
    ko.x = (kk.x*c - kk.y*sn)*t;   ko.y = (kk.y*c + kk.x*sn)*t;
    vo.x = (vv.x*c - vv.y*sn)*it;  vo.y = (vv.y*c + vv.x*sn)*it;

    *(float2*)(qt + out_off) = qq;
    *(float2*)(kt + out_off) = ko;
    *(float2*)(vt + out_off) = vo;
}

// ---------------- causal flash attention (fp32, BM=BN=64, D=128) -----------
#define ATTN_SMEM_FLOATS (128*65 + 128*65 + 64*65 + 64*128)
__global__ void __launch_bounds__(256) hx_attn(
    const float* __restrict__ qt, const float* __restrict__ kt,
    const float* __restrict__ vt,
    __nv_bfloat16* __restrict__ ctxh, __nv_bfloat16* __restrict__ ctxl)
{
    extern __shared__ float smf[];
    float* Qst = smf;
    float* Kst = Qst + 128*65;
    float* Pst = Kst + 128*65;
    float* Vs  = Pst + 64*65;

    const int qtile = blockIdx.x;
    const int bh    = blockIdx.y;
    const int b = bh >> 4, h = bh & 15;
    const float* Qg = qt + ((long)bh*S_ + qtile*64)*D_;
    const float* Kg = kt + (long)bh*S_*D_;
    const float* Vg = vt + (long)bh*S_*D_;

    const int tid = threadIdx.x;
    const int d4 = tid & 31, mr = tid >> 5;
    const int tx = tid & 15, ty = tid >> 4;

#pragma unroll
    for (int p = 0; p < 8; p++) {
        const int m = mr + p*8;
        float4 qv = *(const float4*)(Qg + m*D_ + d4*4);
        Qst[(d4*4+0)*65 + m] = qv.x;
        Qst[(d4*4+1)*65 + m] = qv.y;
        Qst[(d4*4+2)*65 + m] = qv.z;
        Qst[(d4*4+3)*65 + m] = qv.w;
    }

    float mi[4], li[4], o[4][8];
#pragma unroll
    for (int i = 0; i < 4; i++) {
        mi[i] = -INFINITY; li[i] = 0.f;
#pragma unroll
        for (int c = 0; c < 8; c++) o[i][c] = 0.f;
    }
    const float scale = 0.088388347648318447f;

    for (int j = 0; j <= qtile; j++) {
        __syncthreads();
#pragma unroll
        for (int p = 0; p < 8; p++) {
            const int n = mr + p*8;
            float4 kv = *(const float4*)(Kg + (long)(j*64 + n)*D_ + d4*4);
            Kst[(d4*4+0)*65 + n] = kv.x;
            Kst[(d4*4+1)*65 + n] = kv.y;
            Kst[(d4*4+2)*65 + n] = kv.z;
            Kst[(d4*4+3)*65 + n] = kv.w;
            float4 vv = *(const float4*)(Vg + (long)(j*64 + n)*D_ + d4*4);
            *(float4*)&Vs[n*128 + d4*4] = vv;
        }
        __syncthreads();

        float sacc[4][4];
#pragma unroll
        for (int i = 0; i < 4; i++)
#pragma unroll
            for (int jj = 0; jj < 4; jj++) sacc[i][jj] = 0.f;
        for (int d = 0; d < 128; d++) {
            float qr[4], kr[4];
#pragma unroll
            for (int i = 0; i < 4; i++)  qr[i]  = Qst[d*65 + ty*4 + i];
#pragma unroll
            for (int jj = 0; jj < 4; jj++) kr[jj] = Kst[d*65 + tx*4 + jj];
#pragma unroll
            for (int i = 0; i < 4; i++)
#pragma unroll
                for (int jj = 0; jj < 4; jj++)
                    sacc[i][jj] = fmaf(qr[i], kr[jj], sacc[i][jj]);
        }

#pragma unroll
        for (int i = 0; i < 4; i++) {
            const int mg = qtile*64 + ty*4 + i;
            float rmax = -INFINITY;
#pragma unroll
            for (int jj = 0; jj < 4; jj++) {
                const int ng = j*64 + tx*4 + jj;
                float sv = sacc[i][jj] * scale;
                sv = (ng <= mg) ? sv : -INFINITY;
                sacc[i][jj] = sv;
                rmax = fmaxf(rmax, sv);
            }
#pragma unroll
            for (int off = 8; off; off >>= 1)
                rmax = fmaxf(rmax, __shfl_xor_sync(0xffffffffu, rmax, off));
            const float mnew  = fmaxf(mi[i], rmax);
            const float alpha = expf(mi[i] - mnew);
            float rsum = 0.f;
#pragma unroll
            for (int jj = 0; jj < 4; jj++) {
                const float pv = expf(sacc[i][jj] - mnew);
                sacc[i][jj] = pv;
                rsum += pv;
            }
#pragma unroll
            for (int off = 8; off; off >>= 1)
                rsum += __shfl_xor_sync(0xffffffffu, rsum, off);
            li[i] = li[i]*alpha + rsum;
            mi[i] = mnew;
#pragma unroll
            for (int c = 0; c < 8; c++) o[i][c] *= alpha;
#pragma unroll
            for (int jj = 0; jj < 4; jj++)
                Pst[(tx*4 + jj)*65 + ty*4 + i] = sacc[i][jj];
        }
        __syncthreads();

#pragma unroll 4
        for (int n = 0; n < 64; n++) {
            float pr[4], vr[8];
#pragma unroll
            for (int i = 0; i < 4; i++) pr[i] = Pst[n*65 + ty*4 + i];
#pragma unroll
            for (int c = 0; c < 8; c++) vr[c] = Vs[n*128 + tx*8 + c];
#pragma unroll
            for (int i = 0; i < 4; i++)
#pragma unroll
                for (int c = 0; c < 8; c++)
                    o[i][c] = fmaf(pr[i], vr[c], o[i][c]);
        }
    }

#pragma unroll
    for (int i = 0; i < 4; i++) {
        const float inv = 1.0f / li[i];
        const int sq = qtile*64 + ty*4 + i;
        const long off = ((long)(b*S_ + sq))*HID_ + h*D_ + tx*8;
        float4 v0 = { o[i][0]*inv, o[i][1]*inv, o[i][2]*inv, o[i][3]*inv };
        float4 v1 = { o[i][4]*inv, o[i][5]*inv, o[i][6]*inv, o[i][7]*inv };
        uint2 h0, l0, h1, l1;
        hx_split4(v0, h0, l0);
        hx_split4(v1, h1, l1);
        uint4 hv; hv.x = h0.x; hv.y = h0.y; hv.z = h1.x; hv.w = h1.y;
        uint4 lv; lv.x = l0.x; lv.y = l0.y; lv.z = l1.x; lv.w = l1.y;
        *(uint4*)(ctxh + off) = hv;
        *(uint4*)(ctxl + off) = lv;
    }
}

// ---------------- launch ----------------------------------------------------
extern "C" void kernel_launch(void* const* d_in, const int* in_sizes, int n_in,
                              void* d_out, int out_size)
{
    const float* acts_in = (const float*)d_in[0];
    const float* ln1_w   = (const float*)d_in[4];
    const float* ln2_w   = (const float*)d_in[5];
    const float* q_w     = (const float*)d_in[6];
    const float* k_w     = (const float*)d_in[7];
    const float* v_w     = (const float*)d_in[8];
    const float* o_w     = (const float*)d_in[9];
    const float* w1      = (const float*)d_in[10];
    const float* w2      = (const float*)d_in[11];
    const int*   p_index = (const int*)d_in[3];
    float* out = (float*)d_out;

    float *p_q, *p_k, *p_v, *p_qt, *p_kt, *p_vt, *p_acts;
    __nv_bfloat16 *p_wh, *p_wl, *p_xnh, *p_xnl, *p_ctxh, *p_ctxl, *p_hh, *p_hl;
    cudaGetSymbolAddress((void**)&p_q,    g_q);
    cudaGetSymbolAddress((void**)&p_k,    g_k);
    cudaGetSymbolAddress((void**)&p_v,    g_v);
    cudaGetSymbolAddress((void**)&p_qt,   g_qt);
    cudaGetSymbolAddress((void**)&p_kt,   g_kt);
    cudaGetSymbolAddress((void**)&p_vt,   g_vt);
    cudaGetSymbolAddress((void**)&p_acts, g_acts);
    cudaGetSymbolAddress((void**)&p_wh,   g_wh);
    cudaGetSymbolAddress((void**)&p_wl,   g_wl);
    cudaGetSymbolAddress((void**)&p_xnh,  g_xnh);
    cudaGetSymbolAddress((void**)&p_xnl,  g_xnl);
    cudaGetSymbolAddress((void**)&p_ctxh, g_ctxh);
    cudaGetSymbolAddress((void**)&p_ctxl, g_ctxl);
    cudaGetSymbolAddress((void**)&p_hh,   g_hh);
    cudaGetSymbolAddress((void**)&p_hl,   g_hl);

    cudaFuncSetAttribute(mm2<0,true>,  cudaFuncAttributeMaxDynamicSharedMemorySize, MM2_SMEM);
    cudaFuncSetAttribute(mm2<1,false>, cudaFuncAttributeMaxDynamicSharedMemorySize, MM2_SMEM);
    cudaFuncSetAttribute(mm2<2,false>, cudaFuncAttributeMaxDynamicSharedMemorySize, MM2_SMEM);

    // 0) weight pre-split (independent of LN)
    hx_wsplit<<<4096, 256>>>(q_w, k_w, v_w, o_w, w1, w2, p_wh, p_wl);

    // 1) LN1 -> xn hi/lo planes
    hx_ln<<<M_, 256>>>(acts_in, ln1_w, p_xnh, p_xnl);

    // 2) fused QKV projection (48 n-tiles)
    mm2<0,true><<<64*48, 512, MM2_SMEM>>>(M_, HID_, HID_,
        p_xnh, p_xnl, p_wh, p_wl, nullptr, p_q, p_k, p_v, nullptr, nullptr, 48);

    // 3) xPos rotary (K,V) + transpose
    const long nrope = (long)M_*H_*(D_/2);
    hx_rope<<<(unsigned)((nrope + 255)/256), 256>>>(p_q, p_k, p_v, p_index,
                                                    p_qt, p_kt, p_vt);

    // 4) causal flash attention -> ctx hi/lo planes
    const int attn_smem = ATTN_SMEM_FLOATS * (int)sizeof(float);
    cudaFuncSetAttribute(hx_attn, cudaFuncAttributeMaxDynamicSharedMemorySize, attn_smem);
    hx_attn<<<dim3(S_/64, B_*H_), 256, attn_smem>>>(p_qt, p_kt, p_vt, p_ctxh, p_ctxl);

    // 5) O projection + residual -> acts fp32
    mm2<1,false><<<64*16, 512, MM2_SMEM>>>(M_, HID_, HID_,
        p_ctxh, p_ctxl, p_wh + OFF_O, p_wl + OFF_O, acts_in,
        p_acts, nullptr, nullptr, nullptr, nullptr, 16);

    // 6) LN2 -> xn hi/lo planes (reuse)
    hx_ln<<<M_, 256>>>(p_acts, ln2_w, p_xnh, p_xnl);

    // 7) FFN up + exact GELU -> h hi/lo planes
    mm2<2,false><<<64*64, 512, MM2_SMEM>>>(M_, FF_, HID_,
        p_xnh, p_xnl, p_wh + OFF_W1, p_wl + OFF_W1, nullptr,
        nullptr, nullptr, nullptr, p_hh, p_hl, 64);

    // 8) FFN down + residual -> output acts
    mm2<1,false><<<64*16, 512, MM2_SMEM>>>(M_, HID_, FF_,
        p_hh, p_hl, p_wh + OFF_W2, p_wl + OFF_W2, p_acts,
        out, nullptr, nullptr, nullptr, nullptr, 16);

    // 9) pass-through caches
    const long actN = (long)M_*HID_;
    if (n_in > 2 && (long)out_size >= actN + (long)in_sizes[1] + (long)in_sizes[2]) {
        cudaMemcpyAsync(out + actN, d_in[1],
                        (size_t)in_sizes[1]*sizeof(float),
                        cudaMemcpyDeviceToDevice);
        cudaMemcpyAsync(out + actN + in_sizes[1], d_in[2],
                        (size_t)in_sizes[2]*sizeof(float),
                        cudaMemcpyDeviceToDevice);
    }
}

// round 9
// speedup vs baseline: 1.3768x; 1.2814x over previous
#include <cuda_runtime.h>
#include <cuda_fp16.h>
#include <cstdint>
#include <math.h>

// ---------------- problem constants ----------------
#define B_    8
#define S_    1024
#define HID_  2048
#define H_    16
#define D_    128
#define M_    (B_*S_)      // 8192 token rows
#define FF_   (4*HID_)     // 8192

// weight plane offsets (elements)
#define OFF_Q   0L
#define OFF_K   4194304L
#define OFF_V   8388608L
#define OFF_O   12582912L
#define OFF_W1  16777216L
#define OFF_W2  33554432L
#define W_TOTAL 50331648L

// ---------------- scratch (device globals; no allocations allowed) --------
__device__ float g_q   [(size_t)M_*HID_];
__device__ float g_k   [(size_t)M_*HID_];
__device__ float g_v   [(size_t)M_*HID_];
__device__ float g_qt  [(size_t)M_*HID_];
__device__ float g_kt  [(size_t)M_*HID_];
__device__ float g_vt  [(size_t)M_*HID_];
__device__ float g_acts[(size_t)M_*HID_];
__device__ __half g_wh  [W_TOTAL];          // fp16 weights (single plane)
__device__ __half g_xnh [(size_t)M_*HID_];
__device__ __half g_xnl [(size_t)M_*HID_];
__device__ __half g_ctxh[(size_t)M_*HID_];
__device__ __half g_ctxl[(size_t)M_*HID_];
__device__ __half g_hh  [(size_t)M_*FF_];
__device__ __half g_hl  [(size_t)M_*FF_];

// ---------------- helpers ---------------------------------------------------
__device__ __forceinline__ uint32_t hx_smem_u32(const void* p) {
    uint32_t a;
    asm("{ .reg .u64 t; cvta.to.shared.u64 t, %1; cvt.u32.u64 %0, t; }" : "=r"(a) : "l"(p));
    return a;
}
#define HX_LDSM4(r, addr) \
    asm volatile("ldmatrix.sync.aligned.m8n8.x4.shared.b16 {%0,%1,%2,%3}, [%4];" \
        : "=r"((r)[0]), "=r"((r)[1]), "=r"((r)[2]), "=r"((r)[3]) : "r"(addr))

#define HX_MMA(d, a, b0, b1) \
    asm volatile("mma.sync.aligned.m16n8k16.row.col.f32.f16.f16.f32 " \
        "{%0,%1,%2,%3}, {%4,%5,%6,%7}, {%8,%9}, {%0,%1,%2,%3};" \
        : "+f"((d)[0]), "+f"((d)[1]), "+f"((d)[2]), "+f"((d)[3]) \
        : "r"((a)[0]), "r"((a)[1]), "r"((a)[2]), "r"((a)[3]), "r"(b0), "r"(b1))

#define HX_CPASYNC16(dst, src) \
    asm volatile("cp.async.cg.shared.global [%0], [%1], 16;" :: "r"(dst), "l"(src) : "memory")
#define HX_CPCOMMIT() asm volatile("cp.async.commit_group;" ::: "memory")

__device__ __forceinline__ uint32_t hx_pkh(__half a, __half b) {
    __half2 t; t.x = a; t.y = b;
    return *(uint32_t*)&t;
}
// split float4 -> hi uint2, lo uint2 (4 fp16 each); hi+lo ≈ exact fp32
__device__ __forceinline__ void hx_split4h(float4 v, uint2& h, uint2& l) {
    __half h0 = __float2half_rn(v.x), h1 = __float2half_rn(v.y);
    __half h2 = __float2half_rn(v.z), h3 = __float2half_rn(v.w);
    h.x = hx_pkh(h0, h1); h.y = hx_pkh(h2, h3);
    l.x = hx_pkh(__float2half_rn(v.x - __half2float(h0)),
                 __float2half_rn(v.y - __half2float(h1)));
    l.y = hx_pkh(__float2half_rn(v.z - __half2float(h2)),
                 __float2half_rn(v.w - __half2float(h3)));
}

// ---------------- weight fp16 conversion (single plane) ---------------------
__global__ void __launch_bounds__(256) hx_wsplit(
    const float* __restrict__ qw, const float* __restrict__ kw,
    const float* __restrict__ vw, const float* __restrict__ ow,
    const float* __restrict__ w1, const float* __restrict__ w2,
    __half* __restrict__ wh)
{
    const long stride = (long)gridDim.x * blockDim.x;
    for (long i = (long)blockIdx.x * blockDim.x + threadIdx.x;
         i * 4 < W_TOTAL; i += stride) {
        const long e = i * 4;
        const float* src; long off;
        if (e < OFF_W1) {
            const int m = (int)(e >> 22);
            src = (m == 0) ? qw : (m == 1) ? kw : (m == 2) ? vw : ow;
            off = e & 4194303L;
        } else if (e < OFF_W2) { src = w1; off = e - OFF_W1; }
        else                   { src = w2; off = e - OFF_W2; }
        float4 v = *(const float4*)(src + off);
        uint2 h;
        h.x = hx_pkh(__float2half_rn(v.x), __float2half_rn(v.y));
        h.y = hx_pkh(__float2half_rn(v.z), __float2half_rn(v.w));
        *(uint2*)(wh + e) = h;
    }
}

// ---------------- split-fp16 tensor-core GEMM v5 (512 threads, 2 products) --
// C[M,N] = A[M,K] @ B[N,K]^T.  A = exact (hi+lo fp16 planes), B = fp16 plane.
// D = Ah*Bh + Al*Bh  ==  (exact A) x fp16(B).
// CTA 128x128, K-chunk 64, 3 stages, 16 warps (4m x 4n), warp tile 32x32.
// Stage: Ah/Al/Bh planes, 128 rows x 144B (128B data + 16B pad).
// EPI: 0 = none (fp32 C), 1 = +Res (fp32 C), 2 = exact gelu -> fp16 hi/lo planes
#define MM2_PLANE   18432
#define MM2_STAGE   (3*MM2_PLANE)     // 55296
#define MM2_SMEM    (3*MM2_STAGE)     // 165888

template<int EPI, bool QKV>
__global__ void __launch_bounds__(512, 1) mm2(
    int M, int N, int K,
    const __half* __restrict__ Ah, const __half* __restrict__ Al,
    const __half* __restrict__ Bh,
    const float* __restrict__ Res,
    float* __restrict__ C0, float* __restrict__ C1, float* __restrict__ C2,
    __half* __restrict__ Chh, __half* __restrict__ Chl,
    int tiles_n)
{
    extern __shared__ char smc[];
    const uint32_t smb = hx_smem_u32(smc);
    const int tid  = threadIdx.x;
    const int lane = tid & 31;
    const int warp = tid >> 5;     // 0..15
    const int wm = warp & 3;       // m offset wm*32
    const int wn = warp >> 2;      // n offset wn*32

    // supertile raster: 16 m-tiles per band
    const int SUPER = 16;
    const int per  = SUPER * tiles_n;
    const int band = blockIdx.x / per;
    const int rem  = blockIdx.x % per;
    const int mt  = band * SUPER + (rem % SUPER);
    int ntg = rem / SUPER;

    int sel = 0;
    if (QKV) { sel = ntg >> 4; ntg &= 15; }
    const int nt = ntg;

    const long boff = QKV ? (long)sel * 4194304L : 0L;
    const __half* pAh = Ah + (long)mt * 128 * K;
    const __half* pAl = Al + (long)mt * 128 * K;
    const __half* pBh = Bh + boff + (long)nt * 128 * K;
    float* Cw = QKV ? (sel == 0 ? C0 : sel == 1 ? C1 : C2) : C0;

    float acc[2][4][4];
#pragma unroll
    for (int i = 0; i < 2; i++)
#pragma unroll
        for (int j = 0; j < 4; j++)
#pragma unroll
            for (int r = 0; r < 4; r++) acc[i][j][r] = 0.f;

    const __half* plp[3] = { pAh, pAl, pBh };

    auto issue_chunk = [&](int c, int st) {
        const uint32_t sb = smb + st * MM2_STAGE;
        // 3072 ops total (3 planes x 128 rows x 8 segs), 6 per thread
#pragma unroll
        for (int q = 0; q < 6; q++) {
            const int op = tid + q * 512;        // 0..3071
            const int pl = op >> 10;             // plane 0..2
            const int rm = op & 1023;
            const int r  = rm >> 3;              // 0..127
            const int s  = rm & 7;               // 16B segment
            const __half* src = plp[pl] + (long)r * K + c * 64 + s * 8;
            const uint32_t dst = sb + pl * MM2_PLANE + r * 144 + s * 16;
            HX_CPASYNC16(dst, src);
        }
        HX_CPCOMMIT();
    };

    const int nch = K / 64;
    issue_chunk(0, 0);
    issue_chunk(1, 1);

    for (int c = 0; c < nch; c++) {
        const int st = c % 3;
        if (c + 1 < nch) { asm volatile("cp.async.wait_group 1;" ::: "memory"); }
        else             { asm volatile("cp.async.wait_group 0;" ::: "memory"); }
        __syncthreads();
        if (c + 2 < nch) issue_chunk(c + 2, (c + 2) % 3);

        const uint32_t stb = smb + st * MM2_STAGE;
#pragma unroll
        for (int ks = 0; ks < 4; ks++) {
            const uint32_t colb = ks * 32 + (lane >> 4) * 16;
            uint32_t ah[2][4], al[2][4], bh[2][4];
#pragma unroll
            for (int im = 0; im < 2; im++) {
                const uint32_t row = wm * 32 + im * 16 + (lane & 15);
                const uint32_t ad = stb + row * 144 + colb;
                HX_LDSM4(ah[im], ad);
                HX_LDSM4(al[im], ad + MM2_PLANE);
            }
#pragma unroll
            for (int ib = 0; ib < 2; ib++) {
                const uint32_t row = wn * 32 + ib * 16 + (lane & 15);
                const uint32_t bd = stb + 2 * MM2_PLANE + row * 144 + colb;
                HX_LDSM4(bh[ib], bd);
            }
            // per-accumulator addition order: hh then lh (per ks)
#pragma unroll
            for (int im = 0; im < 2; im++)
#pragma unroll
                for (int j = 0; j < 4; j++)
                    HX_MMA(acc[im][j], ah[im], bh[j>>1][j&1], bh[j>>1][(j&1)+2]); // hh
#pragma unroll
            for (int im = 0; im < 2; im++)
#pragma unroll
                for (int j = 0; j < 4; j++)
                    HX_MMA(acc[im][j], al[im], bh[j>>1][j&1], bh[j>>1][(j&1)+2]); // lh
        }
    }

    // ---- epilogue ----
#pragma unroll
    for (int im = 0; im < 2; im++)
#pragma unroll
        for (int j = 0; j < 4; j++) {
            const long row0 = (long)mt * 128 + wm * 32 + im * 16 + (lane >> 2);
            const long col  = (long)nt * 128 + wn * 32 + j * 8 + (lane & 3) * 2;
            const long o0 = row0 * N + col;
            const long o1 = (row0 + 8) * N + col;
            float2 v0 = { acc[im][j][0], acc[im][j][1] };
            float2 v1 = { acc[im][j][2], acc[im][j][3] };
            if (EPI == 2) {
                v0.x = 0.5f*v0.x*(1.0f + erff(v0.x*0.70710678118654752f));
                v0.y = 0.5f*v0.y*(1.0f + erff(v0.y*0.70710678118654752f));
                v1.x = 0.5f*v1.x*(1.0f + erff(v1.x*0.70710678118654752f));
                v1.y = 0.5f*v1.y*(1.0f + erff(v1.y*0.70710678118654752f));
                __half h0 = __float2half_rn(v0.x), h1 = __float2half_rn(v0.y);
                __half h2 = __float2half_rn(v1.x), h3 = __float2half_rn(v1.y);
                *(uint32_t*)(Chh + o0) = hx_pkh(h0, h1);
                *(uint32_t*)(Chh + o1) = hx_pkh(h2, h3);
                *(uint32_t*)(Chl + o0) = hx_pkh(__float2half_rn(v0.x - __half2float(h0)),
                                                __float2half_rn(v0.y - __half2float(h1)));
                *(uint32_t*)(Chl + o1) = hx_pkh(__float2half_rn(v1.x - __half2float(h2)),
                                                __float2half_rn(v1.y - __half2float(h3)));
            } else {
                if (EPI == 1) {
                    const float2 r0 = *(const float2*)(Res + o0);
                    const float2 r1 = *(const float2*)(Res + o1);
                    v0.x += r0.x; v0.y += r0.y; v1.x += r1.x; v1.y += r1.y;
                }
                *(float2*)(Cw + o0) = v0;
                *(float2*)(Cw + o1) = v1;
            }
        }
}

// ---------------- LayerNorm -> hi/lo fp16 planes ----------------------------
__global__ void __launch_bounds__(256) hx_ln(const float* __restrict__ x,
                                             const float* __restrict__ w,
                                             __half* __restrict__ outh,
                                             __half* __restrict__ outl)
{
    const int row = blockIdx.x;
    const int tid = threadIdx.x;
    const float4* xr = (const float4*)(x + (long)row*HID_);
    float4 a = xr[tid];
    float4 b = xr[tid + 256];
    float s  = a.x+a.y+a.z+a.w + b.x+b.y+b.z+b.w;
    float s2 = a.x*a.x+a.y*a.y+a.z*a.z+a.w*a.w
             + b.x*b.x+b.y*b.y+b.z*b.z+b.w*b.w;
#pragma unroll
    for (int o = 16; o; o >>= 1) {
        s  += __shfl_xor_sync(0xffffffffu, s,  o);
        s2 += __shfl_xor_sync(0xffffffffu, s2, o);
    }
    __shared__ float sh[16];
    if ((tid & 31) == 0) { sh[tid >> 5] = s; sh[(tid >> 5) + 8] = s2; }
    __syncthreads();
    float ts = 0.f, ts2 = 0.f;
#pragma unroll
    for (int i = 0; i < 8; i++) { ts += sh[i]; ts2 += sh[i + 8]; }
    const float mean = ts * (1.0f/HID_);
    const float var  = ts2 * (1.0f/HID_) - mean*mean;
    const float rstd = rsqrtf(var + 1e-5f);

    const float4* wr = (const float4*)w;
    float4 w0 = wr[tid], w1v = wr[tid + 256];
    float4 o0, o1;
    o0.x = (a.x-mean)*rstd*w0.x;  o0.y = (a.y-mean)*rstd*w0.y;
    o0.z = (a.z-mean)*rstd*w0.z;  o0.w = (a.w-mean)*rstd*w0.w;
    o1.x = (b.x-mean)*rstd*w1v.x; o1.y = (b.y-mean)*rstd*w1v.y;
    o1.z = (b.z-mean)*rstd*w1v.z; o1.w = (b.w-mean)*rstd*w1v.w;

    uint2 h, l;
    hx_split4h(o0, h, l);
    *(uint2*)(outh + (long)row*HID_ + tid*4) = h;
    *(uint2*)(outl + (long)row*HID_ + tid*4) = l;
    hx_split4h(o1, h, l);
    *(uint2*)(outh + (long)row*HID_ + (tid+256)*4) = h;
    *(uint2*)(outl + (long)row*HID_ + (tid+256)*4) = l;
}

// ---------------- xPos rotary on K,V + transpose Q/K/V to [B*H,S,D] --------
__global__ void hx_rope(const float* __restrict__ q, const float* __restrict__ k,
                        const float* __restrict__ v, const int* __restrict__ pidx,
                        float* __restrict__ qt, float* __restrict__ kt,
                        float* __restrict__ vt)
{
    const long gid = (long)blockIdx.x * blockDim.x + threadIdx.x;
    const long total = (long)M_ * H_ * (D_/2);
    if (gid >= total) return;
    const int  i  = (int)(gid & 63);
    const int  h  = (int)((gid >> 6) & (H_-1));
    const long bs = gid >> 10;
    const int  s  = (int)(bs & (S_-1));
    const int  b  = (int)(bs >> 10);

    const long in_off  = bs*HID_ + h*D_ + 2*i;
    const long out_off = (((long)(b*H_ + h))*S_ + s)*D_ + 2*i;

    float2 qq = *(const float2*)(q + in_off);
    float2 kk = *(const float2*)(k + in_off);
    float2 vv = *(const float2*)(v + in_off);

    const float seq = (float)(pidx[0] + s - (S_/2)) * (1.0f/512.0f);
    const float df  = 2.0f * (float)(i + 1);
    const float theta = expf(-(df * (1.0f/(float)D_)) * 9.210340371976184f);
    float sn, c;
    sincosf(seq * theta, &sn, &c);
    const float zeta = (df*(1.0f/64.0f) + 51.2f) * (1.0f/52.2f);
    const float t  = powf(zeta, seq);
    const float it = 1.0f / t;

    float2 ko, vo;
    ko.x = (kk.x*c - kk.y*sn)*t;   ko.y = (kk.y*c + kk.x*sn)*t;
    vo.x = (vv.x*c - vv.y*sn)*it;  vo.y = (vv.y*c + vv.x*sn)*it;

    *(float2*)(qt + out_off) = qq;
    *(float2*)(kt + out_off) = ko;
    *(float2*)(vt + out_off) = vo;
}

// ---------------- causal flash attention (fp32, BM=BN=64, D=128) -----------
#define ATTN_SMEM_FLOATS (128*65 + 128*65 + 64*65 + 64*128)
__global__ void __launch_bounds__(256) hx_attn(
    const float* __restrict__ qt, const float* __restrict__ kt,
    const float* __restrict__ vt,
    __half* __restrict__ ctxh, __half* __restrict__ ctxl)
{
    extern __shared__ float smf[];
    float* Qst = smf;
    float* Kst = Qst + 128*65;
    float* Pst = Kst + 128*65;
    float* Vs  = Pst + 64*65;

    const int qtile = blockIdx.x;
    const int bh    = blockIdx.y;
    const int b = bh >> 4, h = bh & 15;
    const float* Qg = qt + ((long)bh*S_ + qtile*64)*D_;
    const float* Kg = kt + (long)bh*S_*D_;
    const float* Vg = vt + (long)bh*S_*D_;

    const int tid = threadIdx.x;
    const int d4 = tid & 31, mr = tid >> 5;
    const int tx = tid & 15, ty = tid >> 4;

#pragma unroll
    for (int p = 0; p < 8; p++) {
        const int m = mr + p*8;
        float4 qv = *(const float4*)(Qg + m*D_ + d4*4);
        Qst[(d4*4+0)*65 + m] = qv.x;
        Qst[(d4*4+1)*65 + m] = qv.y;
        Qst[(d4*4+2)*65 + m] = qv.z;
        Qst[(d4*4+3)*65 + m] = qv.w;
    }

    float mi[4], li[4], o[4][8];
#pragma unroll
    for (int i = 0; i < 4; i++) {
        mi[i] = -INFINITY; li[i] = 0.f;
#pragma unroll
        for (int c = 0; c < 8; c++) o[i][c] = 0.f;
    }
    const float scale = 0.088388347648318447f;

    for (int j = 0; j <= qtile; j++) {
        __syncthreads();
#pragma unroll
        for (int p = 0; p < 8; p++) {
            const int n = mr + p*8;
            float4 kv = *(const float4*)(Kg + (long)(j*64 + n)*D_ + d4*4);
            Kst[(d4*4+0)*65 + n] = kv.x;
            Kst[(d4*4+1)*65 + n] = kv.y;
            Kst[(d4*4+2)*65 + n] = kv.z;
            Kst[(d4*4+3)*65 + n] = kv.w;
            float4 vv = *(const float4*)(Vg + (long)(j*64 + n)*D_ + d4*4);
            *(float4*)&Vs[n*128 + d4*4] = vv;
        }
        __syncthreads();

        float sacc[4][4];
#pragma unroll
        for (int i = 0; i < 4; i++)
#pragma unroll
            for (int jj = 0; jj < 4; jj++) sacc[i][jj] = 0.f;
        for (int d = 0; d < 128; d++) {
            float qr[4], kr[4];
#pragma unroll
            for (int i = 0; i < 4; i++)  qr[i]  = Qst[d*65 + ty*4 + i];
#pragma unroll
            for (int jj = 0; jj < 4; jj++) kr[jj] = Kst[d*65 + tx*4 + jj];
#pragma unroll
            for (int i = 0; i < 4; i++)
#pragma unroll
                for (int jj = 0; jj < 4; jj++)
                    sacc[i][jj] = fmaf(qr[i], kr[jj], sacc[i][jj]);
        }

#pragma unroll
        for (int i = 0; i < 4; i++) {
            const int mg = qtile*64 + ty*4 + i;
            float rmax = -INFINITY;
#pragma unroll
            for (int jj = 0; jj < 4; jj++) {
                const int ng = j*64 + tx*4 + jj;
                float sv = sacc[i][jj] * scale;
                sv = (ng <= mg) ? sv : -INFINITY;
                sacc[i][jj] = sv;
                rmax = fmaxf(rmax, sv);
            }
#pragma unroll
            for (int off = 8; off; off >>= 1)
                rmax = fmaxf(rmax, __shfl_xor_sync(0xffffffffu, rmax, off));
            const float mnew  = fmaxf(mi[i], rmax);
            const float alpha = expf(mi[i] - mnew);
            float rsum = 0.f;
#pragma unroll
            for (int jj = 0; jj < 4; jj++) {
                const float pv = expf(sacc[i][jj] - mnew);
                sacc[i][jj] = pv;
                rsum += pv;
            }
#pragma unroll
            for (int off = 8; off; off >>= 1)
                rsum += __shfl_xor_sync(0xffffffffu, rsum, off);
            li[i] = li[i]*alpha + rsum;
            mi[i] = mnew;
#pragma unroll
            for (int c = 0; c < 8; c++) o[i][c] *= alpha;
#pragma unroll
            for (int jj = 0; jj < 4; jj++)
                Pst[(tx*4 + jj)*65 + ty*4 + i] = sacc[i][jj];
        }
        __syncthreads();

#pragma unroll 4
        for (int n = 0; n < 64; n++) {
            float pr[4], vr[8];
#pragma unroll
            for (int i = 0; i < 4; i++) pr[i] = Pst[n*65 + ty*4 + i];
#pragma unroll
            for (int c = 0; c < 8; c++) vr[c] = Vs[n*128 + tx*8 + c];
#pragma unroll
            for (int i = 0; i < 4; i++)
#pragma unroll
                for (int c = 0; c < 8; c++)
                    o[i][c] = fmaf(pr[i], vr[c], o[i][c]);
        }
    }

#pragma unroll
    for (int i = 0; i < 4; i++) {
        const float inv = 1.0f / li[i];
        const int sq = qtile*64 + ty*4 + i;
        const long off = ((long)(b*S_ + sq))*HID_ + h*D_ + tx*8;
        float4 v0 = { o[i][0]*inv, o[i][1]*inv, o[i][2]*inv, o[i][3]*inv };
        float4 v1 = { o[i][4]*inv, o[i][5]*inv, o[i][6]*inv, o[i][7]*inv };
        uint2 h0, l0, h1, l1;
        hx_split4h(v0, h0, l0);
        hx_split4h(v1, h1, l1);
        uint4 hv; hv.x = h0.x; hv.y = h0.y; hv.z = h1.x; hv.w = h1.y;
        uint4 lv; lv.x = l0.x; lv.y = l0.y; lv.z = l1.x; lv.w = l1.y;
        *(uint4*)(ctxh + off) = hv;
        *(uint4*)(ctxl + off) = lv;
    }
}

// ---------------- launch ----------------------------------------------------
extern "C" void kernel_launch(void* const* d_in, const int* in_sizes, int n_in,
                              void* d_out, int out_size)
{
    const float* acts_in = (const float*)d_in[0];
    const float* ln1_w   = (const float*)d_in[4];
    const float* ln2_w   = (const float*)d_in[5];
    const float* q_w     = (const float*)d_in[6];
    const float* k_w     = (const float*)d_in[7];
    const float* v_w     = (const float*)d_in[8];
    const float* o_w     = (const float*)d_in[9];
    const float* w1      = (const float*)d_in[10];
    const float* w2      = (const float*)d_in[11];
    const int*   p_index = (const int*)d_in[3];
    float* out = (float*)d_out;

    float *p_q, *p_k, *p_v, *p_qt, *p_kt, *p_vt, *p_acts;
    __half *p_wh, *p_xnh, *p_xnl, *p_ctxh, *p_ctxl, *p_hh, *p_hl;
    cudaGetSymbolAddress((void**)&p_q,    g_q);
    cudaGetSymbolAddress((void**)&p_k,    g_k);
    cudaGetSymbolAddress((void**)&p_v,    g_v);
    cudaGetSymbolAddress((void**)&p_qt,   g_qt);
    cudaGetSymbolAddress((void**)&p_kt,   g_kt);
    cudaGetSymbolAddress((void**)&p_vt,   g_vt);
    cudaGetSymbolAddress((void**)&p_acts, g_acts);
    cudaGetSymbolAddress((void**)&p_wh,   g_wh);
    cudaGetSymbolAddress((void**)&p_xnh,  g_xnh);
    cudaGetSymbolAddress((void**)&p_xnl,  g_xnl);
    cudaGetSymbolAddress((void**)&p_ctxh, g_ctxh);
    cudaGetSymbolAddress((void**)&p_ctxl, g_ctxl);
    cudaGetSymbolAddress((void**)&p_hh,   g_hh);
    cudaGetSymbolAddress((void**)&p_hl,   g_hl);

    cudaFuncSetAttribute(mm2<0,true>,  cudaFuncAttributeMaxDynamicSharedMemorySize, MM2_SMEM);
    cudaFuncSetAttribute(mm2<1,false>, cudaFuncAttributeMaxDynamicSharedMemorySize, MM2_SMEM);
    cudaFuncSetAttribute(mm2<2,false>, cudaFuncAttributeMaxDynamicSharedMemorySize, MM2_SMEM);

    // 0) weight fp16 conversion (independent of LN)
    hx_wsplit<<<4096, 256>>>(q_w, k_w, v_w, o_w, w1, w2, p_wh);

    // 1) LN1 -> xn hi/lo planes
    hx_ln<<<M_, 256>>>(acts_in, ln1_w, p_xnh, p_xnl);

    // 2) fused QKV projection (48 n-tiles)
    mm2<0,true><<<64*48, 512, MM2_SMEM>>>(M_, HID_, HID_,
        p_xnh, p_xnl, p_wh, nullptr, p_q, p_k, p_v, nullptr, nullptr, 48);

    // 3) xPos rotary (K,V) + transpose
    const long nrope = (long)M_*H_*(D_/2);
    hx_rope<<<(unsigned)((nrope + 255)/256), 256>>>(p_q, p_k, p_v, p_index,
                                                    p_qt, p_kt, p_vt);

    // 4) causal flash attention -> ctx hi/lo planes
    const int attn_smem = ATTN_SMEM_FLOATS * (int)sizeof(float);
    cudaFuncSetAttribute(hx_attn, cudaFuncAttributeMaxDynamicSharedMemorySize, attn_smem);
    hx_attn<<<dim3(S_/64, B_*H_), 256, attn_smem>>>(p_qt, p_kt, p_vt, p_ctxh, p_ctxl);

    // 5) O projection + residual -> acts fp32
    mm2<1,false><<<64*16, 512, MM2_SMEM>>>(M_, HID_, HID_,
        p_ctxh, p_ctxl, p_wh + OFF_O, acts_in,
        p_acts, nullptr, nullptr, nullptr, nullptr, 16);

    // 6) LN2 -> xn hi/lo planes (reuse)
    hx_ln<<<M_, 256>>>(p_acts, ln2_w, p_xnh, p_xnl);

    // 7) FFN up + exact GELU -> h hi/lo planes
    mm2<2,false><<<64*64, 512, MM2_SMEM>>>(M_, FF_, HID_,
        p_xnh, p_xnl, p_wh + OFF_W1, nullptr,
        nullptr, nullptr, nullptr, p_hh, p_hl, 64);

    // 8) FFN down + residual -> output acts
    mm2<1,false><<<64*16, 512, MM2_SMEM>>>(M_, HID_, FF_,
        p_hh, p_hl, p_wh + OFF_W2, p_acts,
        out, nullptr, nullptr, nullptr, nullptr, 16);

    // 9) pass-through caches
    const long actN = (long)M_*HID_;
    if (n_in > 2 && (long)out_size >= actN + (long)in_sizes[1] + (long)in_sizes[2]) {
        cudaMemcpyAsync(out + actN, d_in[1],
                        (size_t)in_sizes[1]*sizeof(float),
                        cudaMemcpyDeviceToDevice);
        cudaMemcpyAsync(out + actN + in_sizes[1], d_in[2],
                        (size_t)in_sizes[2]*sizeof(float),
                        cudaMemcpyDeviceToDevice);
    }
}

// round 10
// speedup vs baseline: 2.0596x; 1.4960x over previous
#include <cuda_runtime.h>
#include <cuda_fp16.h>
#include <cstdint>
#include <math.h>

// ---------------- problem constants ----------------
#define B_    8
#define S_    1024
#define HID_  2048
#define H_    16
#define D_    128
#define M_    (B_*S_)      // 8192 token rows
#define FF_   (4*HID_)     // 8192

// weight plane offsets (elements)
#define OFF_Q   0L
#define OFF_K   4194304L
#define OFF_V   8388608L
#define OFF_O   12582912L
#define OFF_W1  16777216L
#define OFF_W2  33554432L
#define W_TOTAL 50331648L

// ---------------- scratch (device globals; no allocations allowed) --------
__device__ float g_q   [(size_t)M_*HID_];
__device__ float g_k   [(size_t)M_*HID_];
__device__ float g_v   [(size_t)M_*HID_];
__device__ float g_qt  [(size_t)M_*HID_];
__device__ float g_kt  [(size_t)M_*HID_];
__device__ float g_vt  [(size_t)M_*HID_];
__device__ float g_acts[(size_t)M_*HID_];
__device__ __half g_wh  [W_TOTAL];          // fp16 weights
__device__ __half g_xnh [(size_t)M_*HID_];  // fp16 activations
__device__ __half g_ctxh[(size_t)M_*HID_];
__device__ __half g_hh  [(size_t)M_*FF_];

// ---------------- helpers ---------------------------------------------------
__device__ __forceinline__ uint32_t hx_smem_u32(const void* p) {
    uint32_t a;
    asm("{ .reg .u64 t; cvta.to.shared.u64 t, %1; cvt.u32.u64 %0, t; }" : "=r"(a) : "l"(p));
    return a;
}
#define HX_LDSM4(r, addr) \
    asm volatile("ldmatrix.sync.aligned.m8n8.x4.shared.b16 {%0,%1,%2,%3}, [%4];" \
        : "=r"((r)[0]), "=r"((r)[1]), "=r"((r)[2]), "=r"((r)[3]) : "r"(addr))

#define HX_MMA(d, a, b0, b1) \
    asm volatile("mma.sync.aligned.m16n8k16.row.col.f32.f16.f16.f32 " \
        "{%0,%1,%2,%3}, {%4,%5,%6,%7}, {%8,%9}, {%0,%1,%2,%3};" \
        : "+f"((d)[0]), "+f"((d)[1]), "+f"((d)[2]), "+f"((d)[3]) \
        : "r"((a)[0]), "r"((a)[1]), "r"((a)[2]), "r"((a)[3]), "r"(b0), "r"(b1))

#define HX_CPASYNC16(dst, src) \
    asm volatile("cp.async.cg.shared.global [%0], [%1], 16;" :: "r"(dst), "l"(src) : "memory")
#define HX_CPCOMMIT() asm volatile("cp.async.commit_group;" ::: "memory")

__device__ __forceinline__ uint32_t hx_pkh(__half a, __half b) {
    __half2 t; t.x = a; t.y = b;
    return *(uint32_t*)&t;
}
// float4 -> 4 packed fp16
__device__ __forceinline__ uint2 hx_cvt4h(float4 v) {
    uint2 h;
    h.x = hx_pkh(__float2half_rn(v.x), __float2half_rn(v.y));
    h.y = hx_pkh(__float2half_rn(v.z), __float2half_rn(v.w));
    return h;
}

// ---------------- weight fp16 conversion ------------------------------------
__global__ void __launch_bounds__(256) hx_wsplit(
    const float* __restrict__ qw, const float* __restrict__ kw,
    const float* __restrict__ vw, const float* __restrict__ ow,
    const float* __restrict__ w1, const float* __restrict__ w2,
    __half* __restrict__ wh)
{
    const long stride = (long)gridDim.x * blockDim.x;
    for (long i = (long)blockIdx.x * blockDim.x + threadIdx.x;
         i * 4 < W_TOTAL; i += stride) {
        const long e = i * 4;
        const float* src; long off;
        if (e < OFF_W1) {
            const int m = (int)(e >> 22);
            src = (m == 0) ? qw : (m == 1) ? kw : (m == 2) ? vw : ow;
            off = e & 4194303L;
        } else if (e < OFF_W2) { src = w1; off = e - OFF_W1; }
        else                   { src = w2; off = e - OFF_W2; }
        float4 v = *(const float4*)(src + off);
        *(uint2*)(wh + e) = hx_cvt4h(v);
    }
}

// ---------------- fp16 tensor-core GEMM v6 (512 threads, 1 product) ---------
// C[M,N] = fp16(A)[M,K] @ fp16(B)[N,K]^T, fp32 accumulate.
// CTA 128x128, K-chunk 64, 3 stages, 16 warps (4m x 4n), warp tile 32x32.
// Stage: A/B planes, 128 rows x 144B (128B data + 16B pad).
// EPI: 0 = none (fp32 C), 1 = +Res (fp32 C), 2 = exact gelu -> fp16 plane
#define MM2_PLANE   18432
#define MM2_STAGE   (2*MM2_PLANE)     // 36864
#define MM2_SMEM    (3*MM2_STAGE)     // 110592

template<int EPI, bool QKV>
__global__ void __launch_bounds__(512, 1) mm2(
    int M, int N, int K,
    const __half* __restrict__ Ah,
    const __half* __restrict__ Bh,
    const float* __restrict__ Res,
    float* __restrict__ C0, float* __restrict__ C1, float* __restrict__ C2,
    __half* __restrict__ Chh,
    int tiles_n)
{
    extern __shared__ char smc[];
    const uint32_t smb = hx_smem_u32(smc);
    const int tid  = threadIdx.x;
    const int lane = tid & 31;
    const int warp = tid >> 5;     // 0..15
    const int wm = warp & 3;       // m offset wm*32
    const int wn = warp >> 2;      // n offset wn*32

    // supertile raster: 16 m-tiles per band
    const int SUPER = 16;
    const int per  = SUPER * tiles_n;
    const int band = blockIdx.x / per;
    const int rem  = blockIdx.x % per;
    const int mt  = band * SUPER + (rem % SUPER);
    int ntg = rem / SUPER;

    int sel = 0;
    if (QKV) { sel = ntg >> 4; ntg &= 15; }
    const int nt = ntg;

    const long boff = QKV ? (long)sel * 4194304L : 0L;
    const __half* pAh = Ah + (long)mt * 128 * K;
    const __half* pBh = Bh + boff + (long)nt * 128 * K;
    float* Cw = QKV ? (sel == 0 ? C0 : sel == 1 ? C1 : C2) : C0;

    float acc[2][4][4];
#pragma unroll
    for (int i = 0; i < 2; i++)
#pragma unroll
        for (int j = 0; j < 4; j++)
#pragma unroll
            for (int r = 0; r < 4; r++) acc[i][j][r] = 0.f;

    const __half* plp[2] = { pAh, pBh };

    auto issue_chunk = [&](int c, int st) {
        const uint32_t sb = smb + st * MM2_STAGE;
        // 2048 ops total (2 planes x 128 rows x 8 segs), 4 per thread
#pragma unroll
        for (int q = 0; q < 4; q++) {
            const int op = tid + q * 512;        // 0..2047
            const int pl = op >> 10;             // plane 0..1
            const int rm = op & 1023;
            const int r  = rm >> 3;              // 0..127
            const int s  = rm & 7;               // 16B segment
            const __half* src = plp[pl] + (long)r * K + c * 64 + s * 8;
            const uint32_t dst = sb + pl * MM2_PLANE + r * 144 + s * 16;
            HX_CPASYNC16(dst, src);
        }
        HX_CPCOMMIT();
    };

    const int nch = K / 64;
    issue_chunk(0, 0);
    issue_chunk(1, 1);

    for (int c = 0; c < nch; c++) {
        const int st = c % 3;
        if (c + 1 < nch) { asm volatile("cp.async.wait_group 1;" ::: "memory"); }
        else             { asm volatile("cp.async.wait_group 0;" ::: "memory"); }
        __syncthreads();
        if (c + 2 < nch) issue_chunk(c + 2, (c + 2) % 3);

        const uint32_t stb = smb + st * MM2_STAGE;
#pragma unroll
        for (int ks = 0; ks < 4; ks++) {
            const uint32_t colb = ks * 32 + (lane >> 4) * 16;
            uint32_t ah[2][4], bh[2][4];
#pragma unroll
            for (int im = 0; im < 2; im++) {
                const uint32_t row = wm * 32 + im * 16 + (lane & 15);
                HX_LDSM4(ah[im], stb + row * 144 + colb);
            }
#pragma unroll
            for (int ib = 0; ib < 2; ib++) {
                const uint32_t row = wn * 32 + ib * 16 + (lane & 15);
                HX_LDSM4(bh[ib], stb + MM2_PLANE + row * 144 + colb);
            }
#pragma unroll
            for (int im = 0; im < 2; im++)
#pragma unroll
                for (int j = 0; j < 4; j++)
                    HX_MMA(acc[im][j], ah[im], bh[j>>1][j&1], bh[j>>1][(j&1)+2]);
        }
    }

    // ---- epilogue ----
#pragma unroll
    for (int im = 0; im < 2; im++)
#pragma unroll
        for (int j = 0; j < 4; j++) {
            const long row0 = (long)mt * 128 + wm * 32 + im * 16 + (lane >> 2);
            const long col  = (long)nt * 128 + wn * 32 + j * 8 + (lane & 3) * 2;
            const long o0 = row0 * N + col;
            const long o1 = (row0 + 8) * N + col;
            float2 v0 = { acc[im][j][0], acc[im][j][1] };
            float2 v1 = { acc[im][j][2], acc[im][j][3] };
            if (EPI == 2) {
                v0.x = 0.5f*v0.x*(1.0f + erff(v0.x*0.70710678118654752f));
                v0.y = 0.5f*v0.y*(1.0f + erff(v0.y*0.70710678118654752f));
                v1.x = 0.5f*v1.x*(1.0f + erff(v1.x*0.70710678118654752f));
                v1.y = 0.5f*v1.y*(1.0f + erff(v1.y*0.70710678118654752f));
                *(uint32_t*)(Chh + o0) = hx_pkh(__float2half_rn(v0.x), __float2half_rn(v0.y));
                *(uint32_t*)(Chh + o1) = hx_pkh(__float2half_rn(v1.x), __float2half_rn(v1.y));
            } else {
                if (EPI == 1) {
                    const float2 r0 = *(const float2*)(Res + o0);
                    const float2 r1 = *(const float2*)(Res + o1);
                    v0.x += r0.x; v0.y += r0.y; v1.x += r1.x; v1.y += r1.y;
                }
                *(float2*)(Cw + o0) = v0;
                *(float2*)(Cw + o1) = v1;
            }
        }
}

// ---------------- LayerNorm -> fp16 plane -----------------------------------
__global__ void __launch_bounds__(256) hx_ln(const float* __restrict__ x,
                                             const float* __restrict__ w,
                                             __half* __restrict__ outh)
{
    const int row = blockIdx.x;
    const int tid = threadIdx.x;
    const float4* xr = (const float4*)(x + (long)row*HID_);
    float4 a = xr[tid];
    float4 b = xr[tid + 256];
    float s  = a.x+a.y+a.z+a.w + b.x+b.y+b.z+b.w;
    float s2 = a.x*a.x+a.y*a.y+a.z*a.z+a.w*a.w
             + b.x*b.x+b.y*b.y+b.z*b.z+b.w*b.w;
#pragma unroll
    for (int o = 16; o; o >>= 1) {
        s  += __shfl_xor_sync(0xffffffffu, s,  o);
        s2 += __shfl_xor_sync(0xffffffffu, s2, o);
    }
    __shared__ float sh[16];
    if ((tid & 31) == 0) { sh[tid >> 5] = s; sh[(tid >> 5) + 8] = s2; }
    __syncthreads();
    float ts = 0.f, ts2 = 0.f;
#pragma unroll
    for (int i = 0; i < 8; i++) { ts += sh[i]; ts2 += sh[i + 8]; }
    const float mean = ts * (1.0f/HID_);
    const float var  = ts2 * (1.0f/HID_) - mean*mean;
    const float rstd = rsqrtf(var + 1e-5f);

    const float4* wr = (const float4*)w;
    float4 w0 = wr[tid], w1v = wr[tid + 256];
    float4 o0, o1;
    o0.x = (a.x-mean)*rstd*w0.x;  o0.y = (a.y-mean)*rstd*w0.y;
    o0.z = (a.z-mean)*rstd*w0.z;  o0.w = (a.w-mean)*rstd*w0.w;
    o1.x = (b.x-mean)*rstd*w1v.x; o1.y = (b.y-mean)*rstd*w1v.y;
    o1.z = (b.z-mean)*rstd*w1v.z; o1.w = (b.w-mean)*rstd*w1v.w;

    *(uint2*)(outh + (long)row*HID_ + tid*4)       = hx_cvt4h(o0);
    *(uint2*)(outh + (long)row*HID_ + (tid+256)*4) = hx_cvt4h(o1);
}

// ---------------- xPos rotary on K,V + transpose Q/K/V to [B*H,S,D] --------
__global__ void hx_rope(const float* __restrict__ q, const float* __restrict__ k,
                        const float* __restrict__ v, const int* __restrict__ pidx,
                        float* __restrict__ qt, float* __restrict__ kt,
                        float* __restrict__ vt)
{
    const long gid = (long)blockIdx.x * blockDim.x + threadIdx.x;
    const long total = (long)M_ * H_ * (D_/2);
    if (gid >= total) return;
    const int  i  = (int)(gid & 63);
    const int  h  = (int)((gid >> 6) & (H_-1));
    const long bs = gid >> 10;
    const int  s  = (int)(bs & (S_-1));
    const int  b  = (int)(bs >> 10);

    const long in_off  = bs*HID_ + h*D_ + 2*i;
    const long out_off = (((long)(b*H_ + h))*S_ + s)*D_ + 2*i;

    float2 qq = *(const float2*)(q + in_off);
    float2 kk = *(const float2*)(k + in_off);
    float2 vv = *(const float2*)(v + in_off);

    const float seq = (float)(pidx[0] + s - (S_/2)) * (1.0f/512.0f);
    const float df  = 2.0f * (float)(i + 1);
    const float theta = expf(-(df * (1.0f/(float)D_)) * 9.210340371976184f);
    float sn, c;
    sincosf(seq * theta, &sn, &c);
    const float zeta = (df*(1.0f/64.0f) + 51.2f) * (1.0f/52.2f);
    const float t  = powf(zeta, seq);
    const float it = 1.0f / t;

    float2 ko, vo;
    ko.x = (kk.x*c - kk.y*sn)*t;   ko.y = (kk.y*c + kk.x*sn)*t;
    vo.x = (vv.x*c - vv.y*sn)*it;  vo.y = (vv.y*c + vv.x*sn)*it;

    *(float2*)(qt + out_off) = qq;
    *(float2*)(kt + out_off) = ko;
    *(float2*)(vt + out_off) = vo;
}

// ---------------- causal flash attention (fp32, BM=BN=64, D=128) -----------
#define ATTN_SMEM_FLOATS (128*65 + 128*65 + 64*65 + 64*128)
__global__ void __launch_bounds__(256) hx_attn(
    const float* __restrict__ qt, const float* __restrict__ kt,
    const float* __restrict__ vt,
    __half* __restrict__ ctxh)
{
    extern __shared__ float smf[];
    float* Qst = smf;
    float* Kst = Qst + 128*65;
    float* Pst = Kst + 128*65;
    float* Vs  = Pst + 64*65;

    const int qtile = blockIdx.x;
    const int bh    = blockIdx.y;
    const int b = bh >> 4, h = bh & 15;
    const float* Qg = qt + ((long)bh*S_ + qtile*64)*D_;
    const float* Kg = kt + (long)bh*S_*D_;
    const float* Vg = vt + (long)bh*S_*D_;

    const int tid = threadIdx.x;
    const int d4 = tid & 31, mr = tid >> 5;
    const int tx = tid & 15, ty = tid >> 4;

#pragma unroll
    for (int p = 0; p < 8; p++) {
        const int m = mr + p*8;
        float4 qv = *(const float4*)(Qg + m*D_ + d4*4);
        Qst[(d4*4+0)*65 + m] = qv.x;
        Qst[(d4*4+1)*65 + m] = qv.y;
        Qst[(d4*4+2)*65 + m] = qv.z;
        Qst[(d4*4+3)*65 + m] = qv.w;
    }

    float mi[4], li[4], o[4][8];
#pragma unroll
    for (int i = 0; i < 4; i++) {
        mi[i] = -INFINITY; li[i] = 0.f;
#pragma unroll
        for (int c = 0; c < 8; c++) o[i][c] = 0.f;
    }
    const float scale = 0.088388347648318447f;

    for (int j = 0; j <= qtile; j++) {
        __syncthreads();
#pragma unroll
        for (int p = 0; p < 8; p++) {
            const int n = mr + p*8;
            float4 kv = *(const float4*)(Kg + (long)(j*64 + n)*D_ + d4*4);
            Kst[(d4*4+0)*65 + n] = kv.x;
            Kst[(d4*4+1)*65 + n] = kv.y;
            Kst[(d4*4+2)*65 + n] = kv.z;
            Kst[(d4*4+3)*65 + n] = kv.w;
            float4 vv = *(const float4*)(Vg + (long)(j*64 + n)*D_ + d4*4);
            *(float4*)&Vs[n*128 + d4*4] = vv;
        }
        __syncthreads();

        float sacc[4][4];
#pragma unroll
        for (int i = 0; i < 4; i++)
#pragma unroll
            for (int jj = 0; jj < 4; jj++) sacc[i][jj] = 0.f;
        for (int d = 0; d < 128; d++) {
            float qr[4], kr[4];
#pragma unroll
            for (int i = 0; i < 4; i++)  qr[i]  = Qst[d*65 + ty*4 + i];
#pragma unroll
            for (int jj = 0; jj < 4; jj++) kr[jj] = Kst[d*65 + tx*4 + jj];
#pragma unroll
            for (int i = 0; i < 4; i++)
#pragma unroll
                for (int jj = 0; jj < 4; jj++)
                    sacc[i][jj] = fmaf(qr[i], kr[jj], sacc[i][jj]);
        }

#pragma unroll
        for (int i = 0; i < 4; i++) {
            const int mg = qtile*64 + ty*4 + i;
            float rmax = -INFINITY;
#pragma unroll
            for (int jj = 0; jj < 4; jj++) {
                const int ng = j*64 + tx*4 + jj;
                float sv = sacc[i][jj] * scale;
                sv = (ng <= mg) ? sv : -INFINITY;
                sacc[i][jj] = sv;
                rmax = fmaxf(rmax, sv);
            }
#pragma unroll
            for (int off = 8; off; off >>= 1)
                rmax = fmaxf(rmax, __shfl_xor_sync(0xffffffffu, rmax, off));
            const float mnew  = fmaxf(mi[i], rmax);
            const float alpha = expf(mi[i] - mnew);
            float rsum = 0.f;
#pragma unroll
            for (int jj = 0; jj < 4; jj++) {
                const float pv = expf(sacc[i][jj] - mnew);
                sacc[i][jj] = pv;
                rsum += pv;
            }
#pragma unroll
            for (int off = 8; off; off >>= 1)
                rsum += __shfl_xor_sync(0xffffffffu, rsum, off);
            li[i] = li[i]*alpha + rsum;
            mi[i] = mnew;
#pragma unroll
            for (int c = 0; c < 8; c++) o[i][c] *= alpha;
#pragma unroll
            for (int jj = 0; jj < 4; jj++)
                Pst[(tx*4 + jj)*65 + ty*4 + i] = sacc[i][jj];
        }
        __syncthreads();

#pragma unroll 4
        for (int n = 0; n < 64; n++) {
            float pr[4], vr[8];
#pragma unroll
            for (int i = 0; i < 4; i++) pr[i] = Pst[n*65 + ty*4 + i];
#pragma unroll
            for (int c = 0; c < 8; c++) vr[c] = Vs[n*128 + tx*8 + c];
#pragma unroll
            for (int i = 0; i < 4; i++)
#pragma unroll
                for (int c = 0; c < 8; c++)
                    o[i][c] = fmaf(pr[i], vr[c], o[i][c]);
        }
    }

#pragma unroll
    for (int i = 0; i < 4; i++) {
        const float inv = 1.0f / li[i];
        const int sq = qtile*64 + ty*4 + i;
        const long off = ((long)(b*S_ + sq))*HID_ + h*D_ + tx*8;
        float4 v0 = { o[i][0]*inv, o[i][1]*inv, o[i][2]*inv, o[i][3]*inv };
        float4 v1 = { o[i][4]*inv, o[i][5]*inv, o[i][6]*inv, o[i][7]*inv };
        uint2 h0 = hx_cvt4h(v0);
        uint2 h1 = hx_cvt4h(v1);
        uint4 hv; hv.x = h0.x; hv.y = h0.y; hv.z = h1.x; hv.w = h1.y;
        *(uint4*)(ctxh + off) = hv;
    }
}

// ---------------- launch ----------------------------------------------------
extern "C" void kernel_launch(void* const* d_in, const int* in_sizes, int n_in,
                              void* d_out, int out_size)
{
    const float* acts_in = (const float*)d_in[0];
    const float* ln1_w   = (const float*)d_in[4];
    const float* ln2_w   = (const float*)d_in[5];
    const float* q_w     = (const float*)d_in[6];
    const float* k_w     = (const float*)d_in[7];
    const float* v_w     = (const float*)d_in[8];
    const float* o_w     = (const float*)d_in[9];
    const float* w1      = (const float*)d_in[10];
    const float* w2      = (const float*)d_in[11];
    const int*   p_index = (const int*)d_in[3];
    float* out = (float*)d_out;

    float *p_q, *p_k, *p_v, *p_qt, *p_kt, *p_vt, *p_acts;
    __half *p_wh, *p_xnh, *p_ctxh, *p_hh;
    cudaGetSymbolAddress((void**)&p_q,    g_q);
    cudaGetSymbolAddress((void**)&p_k,    g_k);
    cudaGetSymbolAddress((void**)&p_v,    g_v);
    cudaGetSymbolAddress((void**)&p_qt,   g_qt);
    cudaGetSymbolAddress((void**)&p_kt,   g_kt);
    cudaGetSymbolAddress((void**)&p_vt,   g_vt);
    cudaGetSymbolAddress((void**)&p_acts, g_acts);
    cudaGetSymbolAddress((void**)&p_wh,   g_wh);
    cudaGetSymbolAddress((void**)&p_xnh,  g_xnh);
    cudaGetSymbolAddress((void**)&p_ctxh, g_ctxh);
    cudaGetSymbolAddress((void**)&p_hh,   g_hh);

    cudaFuncSetAttribute(mm2<0,true>,  cudaFuncAttributeMaxDynamicSharedMemorySize, MM2_SMEM);
    cudaFuncSetAttribute(mm2<1,false>, cudaFuncAttributeMaxDynamicSharedMemorySize, MM2_SMEM);
    cudaFuncSetAttribute(mm2<2,false>, cudaFuncAttributeMaxDynamicSharedMemorySize, MM2_SMEM);

    // 0) weight fp16 conversion (independent of LN)
    hx_wsplit<<<4096, 256>>>(q_w, k_w, v_w, o_w, w1, w2, p_wh);

    // 1) LN1 -> xn fp16
    hx_ln<<<M_, 256>>>(acts_in, ln1_w, p_xnh);

    // 2) fused QKV projection (48 n-tiles)
    mm2<0,true><<<64*48, 512, MM2_SMEM>>>(M_, HID_, HID_,
        p_xnh, p_wh, nullptr, p_q, p_k, p_v, nullptr, 48);

    // 3) xPos rotary (K,V) + transpose
    const long nrope = (long)M_*H_*(D_/2);
    hx_rope<<<(unsigned)((nrope + 255)/256), 256>>>(p_q, p_k, p_v, p_index,
                                                    p_qt, p_kt, p_vt);

    // 4) causal flash attention -> ctx fp16
    const int attn_smem = ATTN_SMEM_FLOATS * (int)sizeof(float);
    cudaFuncSetAttribute(hx_attn, cudaFuncAttributeMaxDynamicSharedMemorySize, attn_smem);
    hx_attn<<<dim3(S_/64, B_*H_), 256, attn_smem>>>(p_qt, p_kt, p_vt, p_ctxh);

    // 5) O projection + residual -> acts fp32
    mm2<1,false><<<64*16, 512, MM2_SMEM>>>(M_, HID_, HID_,
        p_ctxh, p_wh + OFF_O, acts_in,
        p_acts, nullptr, nullptr, nullptr, 16);

    // 6) LN2 -> xn fp16 (reuse)
    hx_ln<<<M_, 256>>>(p_acts, ln2_w, p_xnh);

    // 7) FFN up + exact GELU -> h fp16
    mm2<2,false><<<64*64, 512, MM2_SMEM>>>(M_, FF_, HID_,
        p_xnh, p_wh + OFF_W1, nullptr,
        nullptr, nullptr, nullptr, p_hh, 64);

    // 8) FFN down + residual -> output acts
    mm2<1,false><<<64*16, 512, MM2_SMEM>>>(M_, HID_, FF_,
        p_hh, p_wh + OFF_W2, p_acts,
        out, nullptr, nullptr, nullptr, 16);

    // 9) pass-through caches
    const long actN = (long)M_*HID_;
    if (n_in > 2 && (long)out_size >= actN + (long)in_sizes[1] + (long)in_sizes[2]) {
        cudaMemcpyAsync(out + actN, d_in[1],
                        (size_t)in_sizes[1]*sizeof(float),
                        cudaMemcpyDeviceToDevice);
        cudaMemcpyAsync(out + actN + in_sizes[1], d_in[2],
                        (size_t)in_sizes[2]*sizeof(float),
                        cudaMemcpyDeviceToDevice);
    }
}

// round 11
// speedup vs baseline: 2.9991x; 1.4561x over previous
#include <cuda_runtime.h>
#include <cuda_fp16.h>
#include <cstdint>
#include <math.h>

// ---------------- problem constants ----------------
#define B_    8
#define S_    1024
#define HID_  2048
#define H_    16
#define D_    128
#define M_    (B_*S_)      // 8192 token rows
#define FF_   (4*HID_)     // 8192

// weight plane offsets (elements)
#define OFF_Q   0L
#define OFF_K   4194304L
#define OFF_V   8388608L
#define OFF_O   12582912L
#define OFF_W1  16777216L
#define OFF_W2  33554432L
#define W_TOTAL 50331648L

// ---------------- scratch (device globals; no allocations allowed) --------
__device__ float g_q   [(size_t)M_*HID_];
__device__ float g_k   [(size_t)M_*HID_];
__device__ float g_v   [(size_t)M_*HID_];
__device__ float g_acts[(size_t)M_*HID_];
__device__ __half g_qt  [(size_t)M_*HID_];  // [B*H][S][D] fp16
__device__ __half g_kt  [(size_t)M_*HID_];
__device__ __half g_vt  [(size_t)M_*HID_];
__device__ __half g_wh  [W_TOTAL];          // fp16 weights
__device__ __half g_xnh [(size_t)M_*HID_];  // fp16 activations
__device__ __half g_ctxh[(size_t)M_*HID_];
__device__ __half g_hh  [(size_t)M_*FF_];

// ---------------- helpers ---------------------------------------------------
__device__ __forceinline__ uint32_t hx_smem_u32(const void* p) {
    uint32_t a;
    asm("{ .reg .u64 t; cvta.to.shared.u64 t, %1; cvt.u32.u64 %0, t; }" : "=r"(a) : "l"(p));
    return a;
}
#define HX_LDSM4(r, addr) \
    asm volatile("ldmatrix.sync.aligned.m8n8.x4.shared.b16 {%0,%1,%2,%3}, [%4];" \
        : "=r"((r)[0]), "=r"((r)[1]), "=r"((r)[2]), "=r"((r)[3]) : "r"(addr))
#define HX_LDSM4T(r, addr) \
    asm volatile("ldmatrix.sync.aligned.m8n8.x4.trans.shared.b16 {%0,%1,%2,%3}, [%4];" \
        : "=r"((r)[0]), "=r"((r)[1]), "=r"((r)[2]), "=r"((r)[3]) : "r"(addr))

#define HX_MMA(d, a, b0, b1) \
    asm volatile("mma.sync.aligned.m16n8k16.row.col.f32.f16.f16.f32 " \
        "{%0,%1,%2,%3}, {%4,%5,%6,%7}, {%8,%9}, {%0,%1,%2,%3};" \
        : "+f"((d)[0]), "+f"((d)[1]), "+f"((d)[2]), "+f"((d)[3]) \
        : "r"((a)[0]), "r"((a)[1]), "r"((a)[2]), "r"((a)[3]), "r"(b0), "r"(b1))

#define HX_CPASYNC16(dst, src) \
    asm volatile("cp.async.cg.shared.global [%0], [%1], 16;" :: "r"(dst), "l"(src) : "memory")
#define HX_CPCOMMIT() asm volatile("cp.async.commit_group;" ::: "memory")

__device__ __forceinline__ uint32_t hx_pkh(__half a, __half b) {
    __half2 t; t.x = a; t.y = b;
    return *(uint32_t*)&t;
}
__device__ __forceinline__ uint32_t hx_pkf(float a, float b) {
    return hx_pkh(__float2half_rn(a), __float2half_rn(b));
}
// float4 -> 4 packed fp16
__device__ __forceinline__ uint2 hx_cvt4h(float4 v) {
    uint2 h;
    h.x = hx_pkf(v.x, v.y);
    h.y = hx_pkf(v.z, v.w);
    return h;
}

// ---------------- weight fp16 conversion ------------------------------------
__global__ void __launch_bounds__(256) hx_wsplit(
    const float* __restrict__ qw, const float* __restrict__ kw,
    const float* __restrict__ vw, const float* __restrict__ ow,
    const float* __restrict__ w1, const float* __restrict__ w2,
    __half* __restrict__ wh)
{
    const long stride = (long)gridDim.x * blockDim.x;
    for (long i = (long)blockIdx.x * blockDim.x + threadIdx.x;
         i * 4 < W_TOTAL; i += stride) {
        const long e = i * 4;
        const float* src; long off;
        if (e < OFF_W1) {
            const int m = (int)(e >> 22);
            src = (m == 0) ? qw : (m == 1) ? kw : (m == 2) ? vw : ow;
            off = e & 4194303L;
        } else if (e < OFF_W2) { src = w1; off = e - OFF_W1; }
        else                   { src = w2; off = e - OFF_W2; }
        float4 v = *(const float4*)(src + off);
        *(uint2*)(wh + e) = hx_cvt4h(v);
    }
}

// ---------------- fp16 tensor-core GEMM v6 (512 threads) --------------------
#define MM2_PLANE   18432
#define MM2_STAGE   (2*MM2_PLANE)     // 36864
#define MM2_SMEM    (3*MM2_STAGE)     // 110592

template<int EPI, bool QKV>
__global__ void __launch_bounds__(512, 1) mm2(
    int M, int N, int K,
    const __half* __restrict__ Ah,
    const __half* __restrict__ Bh,
    const float* __restrict__ Res,
    float* __restrict__ C0, float* __restrict__ C1, float* __restrict__ C2,
    __half* __restrict__ Chh,
    int tiles_n)
{
    extern __shared__ char smc[];
    const uint32_t smb = hx_smem_u32(smc);
    const int tid  = threadIdx.x;
    const int lane = tid & 31;
    const int warp = tid >> 5;     // 0..15
    const int wm = warp & 3;       // m offset wm*32
    const int wn = warp >> 2;      // n offset wn*32

    const int SUPER = 16;
    const int per  = SUPER * tiles_n;
    const int band = blockIdx.x / per;
    const int rem  = blockIdx.x % per;
    const int mt  = band * SUPER + (rem % SUPER);
    int ntg = rem / SUPER;

    int sel = 0;
    if (QKV) { sel = ntg >> 4; ntg &= 15; }
    const int nt = ntg;

    const long boff = QKV ? (long)sel * 4194304L : 0L;
    const __half* pAh = Ah + (long)mt * 128 * K;
    const __half* pBh = Bh + boff + (long)nt * 128 * K;
    float* Cw = QKV ? (sel == 0 ? C0 : sel == 1 ? C1 : C2) : C0;

    float acc[2][4][4];
#pragma unroll
    for (int i = 0; i < 2; i++)
#pragma unroll
        for (int j = 0; j < 4; j++)
#pragma unroll
            for (int r = 0; r < 4; r++) acc[i][j][r] = 0.f;

    const __half* plp[2] = { pAh, pBh };

    auto issue_chunk = [&](int c, int st) {
        const uint32_t sb = smb + st * MM2_STAGE;
#pragma unroll
        for (int q = 0; q < 4; q++) {
            const int op = tid + q * 512;
            const int pl = op >> 10;
            const int rm = op & 1023;
            const int r  = rm >> 3;
            const int s  = rm & 7;
            const __half* src = plp[pl] + (long)r * K + c * 64 + s * 8;
            const uint32_t dst = sb + pl * MM2_PLANE + r * 144 + s * 16;
            HX_CPASYNC16(dst, src);
        }
        HX_CPCOMMIT();
    };

    const int nch = K / 64;
    issue_chunk(0, 0);
    issue_chunk(1, 1);

    for (int c = 0; c < nch; c++) {
        const int st = c % 3;
        if (c + 1 < nch) { asm volatile("cp.async.wait_group 1;" ::: "memory"); }
        else             { asm volatile("cp.async.wait_group 0;" ::: "memory"); }
        __syncthreads();
        if (c + 2 < nch) issue_chunk(c + 2, (c + 2) % 3);

        const uint32_t stb = smb + st * MM2_STAGE;
#pragma unroll
        for (int ks = 0; ks < 4; ks++) {
            const uint32_t colb = ks * 32 + (lane >> 4) * 16;
            uint32_t ah[2][4], bh[2][4];
#pragma unroll
            for (int im = 0; im < 2; im++) {
                const uint32_t row = wm * 32 + im * 16 + (lane & 15);
                HX_LDSM4(ah[im], stb + row * 144 + colb);
            }
#pragma unroll
            for (int ib = 0; ib < 2; ib++) {
                const uint32_t row = wn * 32 + ib * 16 + (lane & 15);
                HX_LDSM4(bh[ib], stb + MM2_PLANE + row * 144 + colb);
            }
#pragma unroll
            for (int im = 0; im < 2; im++)
#pragma unroll
                for (int j = 0; j < 4; j++)
                    HX_MMA(acc[im][j], ah[im], bh[j>>1][j&1], bh[j>>1][(j&1)+2]);
        }
    }

    // ---- epilogue ----
#pragma unroll
    for (int im = 0; im < 2; im++)
#pragma unroll
        for (int j = 0; j < 4; j++) {
            const long row0 = (long)mt * 128 + wm * 32 + im * 16 + (lane >> 2);
            const long col  = (long)nt * 128 + wn * 32 + j * 8 + (lane & 3) * 2;
            const long o0 = row0 * N + col;
            const long o1 = (row0 + 8) * N + col;
            float2 v0 = { acc[im][j][0], acc[im][j][1] };
            float2 v1 = { acc[im][j][2], acc[im][j][3] };
            if (EPI == 2) {
                v0.x = 0.5f*v0.x*(1.0f + erff(v0.x*0.70710678118654752f));
                v0.y = 0.5f*v0.y*(1.0f + erff(v0.y*0.70710678118654752f));
                v1.x = 0.5f*v1.x*(1.0f + erff(v1.x*0.70710678118654752f));
                v1.y = 0.5f*v1.y*(1.0f + erff(v1.y*0.70710678118654752f));
                *(uint32_t*)(Chh + o0) = hx_pkf(v0.x, v0.y);
                *(uint32_t*)(Chh + o1) = hx_pkf(v1.x, v1.y);
            } else {
                if (EPI == 1) {
                    const float2 r0 = *(const float2*)(Res + o0);
                    const float2 r1 = *(const float2*)(Res + o1);
                    v0.x += r0.x; v0.y += r0.y; v1.x += r1.x; v1.y += r1.y;
                }
                *(float2*)(Cw + o0) = v0;
                *(float2*)(Cw + o1) = v1;
            }
        }
}

// ---------------- LayerNorm -> fp16 plane -----------------------------------
__global__ void __launch_bounds__(256) hx_ln(const float* __restrict__ x,
                                             const float* __restrict__ w,
                                             __half* __restrict__ outh)
{
    const int row = blockIdx.x;
    const int tid = threadIdx.x;
    const float4* xr = (const float4*)(x + (long)row*HID_);
    float4 a = xr[tid];
    float4 b = xr[tid + 256];
    float s  = a.x+a.y+a.z+a.w + b.x+b.y+b.z+b.w;
    float s2 = a.x*a.x+a.y*a.y+a.z*a.z+a.w*a.w
             + b.x*b.x+b.y*b.y+b.z*b.z+b.w*b.w;
#pragma unroll
    for (int o = 16; o; o >>= 1) {
        s  += __shfl_xor_sync(0xffffffffu, s,  o);
        s2 += __shfl_xor_sync(0xffffffffu, s2, o);
    }
    __shared__ float sh[16];
    if ((tid & 31) == 0) { sh[tid >> 5] = s; sh[(tid >> 5) + 8] = s2; }
    __syncthreads();
    float ts = 0.f, ts2 = 0.f;
#pragma unroll
    for (int i = 0; i < 8; i++) { ts += sh[i]; ts2 += sh[i + 8]; }
    const float mean = ts * (1.0f/HID_);
    const float var  = ts2 * (1.0f/HID_) - mean*mean;
    const float rstd = rsqrtf(var + 1e-5f);

    const float4* wr = (const float4*)w;
    float4 w0 = wr[tid], w1v = wr[tid + 256];
    float4 o0, o1;
    o0.x = (a.x-mean)*rstd*w0.x;  o0.y = (a.y-mean)*rstd*w0.y;
    o0.z = (a.z-mean)*rstd*w0.z;  o0.w = (a.w-mean)*rstd*w0.w;
    o1.x = (b.x-mean)*rstd*w1v.x; o1.y = (b.y-mean)*rstd*w1v.y;
    o1.z = (b.z-mean)*rstd*w1v.z; o1.w = (b.w-mean)*rstd*w1v.w;

    *(uint2*)(outh + (long)row*HID_ + tid*4)       = hx_cvt4h(o0);
    *(uint2*)(outh + (long)row*HID_ + (tid+256)*4) = hx_cvt4h(o1);
}

// ---------------- xPos rotary -> fp16 qt/kt/vt [B*H, S, D] ------------------
__global__ void hx_rope(const float* __restrict__ q, const float* __restrict__ k,
                        const float* __restrict__ v, const int* __restrict__ pidx,
                        __half* __restrict__ qt, __half* __restrict__ kt,
                        __half* __restrict__ vt)
{
    const long gid = (long)blockIdx.x * blockDim.x + threadIdx.x;
    const long total = (long)M_ * H_ * (D_/2);
    if (gid >= total) return;
    const int  i  = (int)(gid & 63);
    const int  h  = (int)((gid >> 6) & (H_-1));
    const long bs = gid >> 10;
    const int  s  = (int)(bs & (S_-1));
    const int  b  = (int)(bs >> 10);

    const long in_off  = bs*HID_ + h*D_ + 2*i;
    const long out_off = (((long)(b*H_ + h))*S_ + s)*D_ + 2*i;

    float2 qq = *(const float2*)(q + in_off);
    float2 kk = *(const float2*)(k + in_off);
    float2 vv = *(const float2*)(v + in_off);

    const float seq = (float)(pidx[0] + s - (S_/2)) * (1.0f/512.0f);
    const float df  = 2.0f * (float)(i + 1);
    const float theta = expf(-(df * (1.0f/(float)D_)) * 9.210340371976184f);
    float sn, c;
    sincosf(seq * theta, &sn, &c);
    const float zeta = (df*(1.0f/64.0f) + 51.2f) * (1.0f/52.2f);
    const float t  = powf(zeta, seq);
    const float it = 1.0f / t;

    float2 ko, vo;
    ko.x = (kk.x*c - kk.y*sn)*t;   ko.y = (kk.y*c + kk.x*sn)*t;
    vo.x = (vv.x*c - vv.y*sn)*it;  vo.y = (vv.y*c + vv.x*sn)*it;

    *(uint32_t*)(qt + out_off) = hx_pkf(qq.x, qq.y);
    *(uint32_t*)(kt + out_off) = hx_pkf(ko.x, ko.y);
    *(uint32_t*)(vt + out_off) = hx_pkf(vo.x, vo.y);
}

// ---------------- fp16 tensor-core causal flash attention -------------------
// CTA: 128 q-rows, 8 warps (16 rows each), KV tiles of 64, D=128.
// Q tile fp16 in smem (272B rows), K/V tiles double-buffered via cp.async.
// S = Q K^T (mma), softmax in registers, O += P V (V frags via ldmatrix.trans).
#define AT_ROW    272
#define AT_Q      0
#define AT_QBYTES (128*AT_ROW)        // 34816
#define AT_KB     17408               // 64*272
#define AT_STAGE  (2*AT_KB)           // 34816
#define AT_SMEM   (AT_QBYTES + 2*AT_STAGE)  // 104448

__global__ void __launch_bounds__(256, 1) hx_attn16(
    const __half* __restrict__ qt, const __half* __restrict__ kt,
    const __half* __restrict__ vt, __half* __restrict__ ctxh)
{
    extern __shared__ char smc[];
    const uint32_t smb = hx_smem_u32(smc);
    const int tid = threadIdx.x, lane = tid & 31, warp = tid >> 5;
    const int qb = blockIdx.x;           // q block of 128 rows
    const int bh = blockIdx.y;
    const int b = bh >> 4, h = bh & 15;
    const int wrow = warp * 16;

    const __half* Qg = qt + ((long)bh*S_ + qb*128)*D_;
    const __half* Kg = kt + (long)bh*S_*D_;
    const __half* Vg = vt + (long)bh*S_*D_;

    // Q: 128 rows x 16 segs = 2048 ops (8/thread)
#pragma unroll
    for (int p = 0; p < 8; p++) {
        const int op = tid + p*256;
        const int r = op >> 4, s = op & 15;
        HX_CPASYNC16(smb + AT_Q + r*AT_ROW + s*16, Qg + (long)r*D_ + s*8);
    }
    auto issue_kv = [&](int j, int st) {
        const uint32_t sb = smb + AT_QBYTES + st*AT_STAGE;
#pragma unroll
        for (int p = 0; p < 8; p++) {
            const int op = tid + p*256;        // 0..2047
            const int kv = op >> 10;           // 0=K, 1=V
            const int rm = op & 1023;
            const int r = rm >> 4, s = rm & 15;
            const __half* src = (kv ? Vg : Kg) + (long)(j*64 + r)*D_ + s*8;
            HX_CPASYNC16(sb + kv*AT_KB + r*AT_ROW + s*16, src);
        }
        HX_CPCOMMIT();
    };

    const int njt = 2*qb + 2;
    issue_kv(0, 0);     // commits Q + KV0 together
    issue_kv(1, 1);
    asm volatile("cp.async.wait_group 1;" ::: "memory");
    __syncthreads();

    // Q fragments (register-resident)
    uint32_t qf[8][4];
#pragma unroll
    for (int kb = 0; kb < 8; kb++)
        HX_LDSM4(qf[kb], smb + AT_Q + (wrow + (lane & 15))*AT_ROW + kb*32 + (lane >> 4)*16);

    float o[16][4];
#pragma unroll
    for (int nd = 0; nd < 16; nd++)
#pragma unroll
        for (int r = 0; r < 4; r++) o[nd][r] = 0.f;
    float mi0 = -INFINITY, mi1 = -INFINITY, li0 = 0.f, li1 = 0.f;

    const float scale = 0.088388347648318447f;
    const int r0g = qb*128 + wrow + (lane >> 2);
    const int c0l = (lane & 3)*2;

    for (int j = 0; j < njt; j++) {
        const int st = j & 1;
        if (j > 0) {
            if (j + 1 < njt) { asm volatile("cp.async.wait_group 1;" ::: "memory"); }
            else             { asm volatile("cp.async.wait_group 0;" ::: "memory"); }
            __syncthreads();
        }
        const uint32_t kb_ = smb + AT_QBYTES + st*AT_STAGE;
        const uint32_t vb_ = kb_ + AT_KB;

        // S = Q K^T
        float sacc[8][4];
#pragma unroll
        for (int nb = 0; nb < 8; nb++)
#pragma unroll
            for (int r = 0; r < 4; r++) sacc[nb][r] = 0.f;
#pragma unroll
        for (int ng = 0; ng < 4; ng++) {
#pragma unroll
            for (int kb = 0; kb < 8; kb++) {
                uint32_t kf[4];
                HX_LDSM4(kf, kb_ + (ng*16 + (lane & 15))*AT_ROW + kb*32 + (lane >> 4)*16);
                HX_MMA(sacc[ng*2+0], qf[kb], kf[0], kf[2]);
                HX_MMA(sacc[ng*2+1], qf[kb], kf[1], kf[3]);
            }
        }

        // masked scale + row max
        float rmax0 = -INFINITY, rmax1 = -INFINITY;
#pragma unroll
        for (int nb = 0; nb < 8; nb++) {
            const int cg = j*64 + nb*8 + c0l;
            float v0 = sacc[nb][0]*scale; if (cg     > r0g)     v0 = -INFINITY;
            float v1 = sacc[nb][1]*scale; if (cg + 1 > r0g)     v1 = -INFINITY;
            float v2 = sacc[nb][2]*scale; if (cg     > r0g + 8) v2 = -INFINITY;
            float v3 = sacc[nb][3]*scale; if (cg + 1 > r0g + 8) v3 = -INFINITY;
            sacc[nb][0] = v0; sacc[nb][1] = v1; sacc[nb][2] = v2; sacc[nb][3] = v3;
            rmax0 = fmaxf(rmax0, fmaxf(v0, v1));
            rmax1 = fmaxf(rmax1, fmaxf(v2, v3));
        }
        rmax0 = fmaxf(rmax0, __shfl_xor_sync(0xffffffffu, rmax0, 1));
        rmax0 = fmaxf(rmax0, __shfl_xor_sync(0xffffffffu, rmax0, 2));
        rmax1 = fmaxf(rmax1, __shfl_xor_sync(0xffffffffu, rmax1, 1));
        rmax1 = fmaxf(rmax1, __shfl_xor_sync(0xffffffffu, rmax1, 2));
        const float mn0 = fmaxf(mi0, rmax0), mn1 = fmaxf(mi1, rmax1);
        const float a0 = expf(mi0 - mn0), a1 = expf(mi1 - mn1);
        float rs0 = 0.f, rs1 = 0.f;
#pragma unroll
        for (int nb = 0; nb < 8; nb++) {
            const float p0 = expf(sacc[nb][0] - mn0);
            const float p1 = expf(sacc[nb][1] - mn0);
            const float p2 = expf(sacc[nb][2] - mn1);
            const float p3 = expf(sacc[nb][3] - mn1);
            sacc[nb][0] = p0; sacc[nb][1] = p1; sacc[nb][2] = p2; sacc[nb][3] = p3;
            rs0 += p0 + p1; rs1 += p2 + p3;
        }
        rs0 += __shfl_xor_sync(0xffffffffu, rs0, 1);
        rs0 += __shfl_xor_sync(0xffffffffu, rs0, 2);
        rs1 += __shfl_xor_sync(0xffffffffu, rs1, 1);
        rs1 += __shfl_xor_sync(0xffffffffu, rs1, 2);
        li0 = li0*a0 + rs0; li1 = li1*a1 + rs1;
        mi0 = mn0; mi1 = mn1;
#pragma unroll
        for (int nd = 0; nd < 16; nd++) {
            o[nd][0] *= a0; o[nd][1] *= a0; o[nd][2] *= a1; o[nd][3] *= a1;
        }

        // P fragments (fp16) from S accumulators
        uint32_t pa[4][4];
#pragma unroll
        for (int kk = 0; kk < 4; kk++) {
            pa[kk][0] = hx_pkf(sacc[2*kk][0],   sacc[2*kk][1]);
            pa[kk][1] = hx_pkf(sacc[2*kk][2],   sacc[2*kk][3]);
            pa[kk][2] = hx_pkf(sacc[2*kk+1][0], sacc[2*kk+1][1]);
            pa[kk][3] = hx_pkf(sacc[2*kk+1][2], sacc[2*kk+1][3]);
        }

        // O += P V  (V frags via ldmatrix.trans on [kv][d] tile)
#pragma unroll
        for (int ndg = 0; ndg < 8; ndg++) {
#pragma unroll
            for (int kk = 0; kk < 4; kk++) {
                uint32_t vf[4];
                HX_LDSM4T(vf, vb_ + (kk*16 + (lane & 15))*AT_ROW + ndg*32 + (lane >> 4)*16);
                HX_MMA(o[ndg*2+0], pa[kk], vf[0], vf[1]);
                HX_MMA(o[ndg*2+1], pa[kk], vf[2], vf[3]);
            }
        }
        __syncthreads();
        if (j + 2 < njt) issue_kv(j + 2, st);
    }

    // normalize + write ctx [B,S,HID] fp16
    const float i0 = 1.f/li0, i1 = 1.f/li1;
    const long s0 = (long)(b*S_) + qb*128 + wrow + (lane >> 2);
    const long base0 = s0*HID_ + h*128 + c0l;
    const long base1 = (s0 + 8)*HID_ + h*128 + c0l;
#pragma unroll
    for (int nd = 0; nd < 16; nd++) {
        *(uint32_t*)(ctxh + base0 + nd*8) = hx_pkf(o[nd][0]*i0, o[nd][1]*i0);
        *(uint32_t*)(ctxh + base1 + nd*8) = hx_pkf(o[nd][2]*i1, o[nd][3]*i1);
    }
}

// ---------------- launch ----------------------------------------------------
extern "C" void kernel_launch(void* const* d_in, const int* in_sizes, int n_in,
                              void* d_out, int out_size)
{
    const float* acts_in = (const float*)d_in[0];
    const float* ln1_w   = (const float*)d_in[4];
    const float* ln2_w   = (const float*)d_in[5];
    const float* q_w     = (const float*)d_in[6];
    const float* k_w     = (const float*)d_in[7];
    const float* v_w     = (const float*)d_in[8];
    const float* o_w     = (const float*)d_in[9];
    const float* w1      = (const float*)d_in[10];
    const float* w2      = (const float*)d_in[11];
    const int*   p_index = (const int*)d_in[3];
    float* out = (float*)d_out;

    float *p_q, *p_k, *p_v, *p_acts;
    __half *p_qt, *p_kt, *p_vt, *p_wh, *p_xnh, *p_ctxh, *p_hh;
    cudaGetSymbolAddress((void**)&p_q,    g_q);
    cudaGetSymbolAddress((void**)&p_k,    g_k);
    cudaGetSymbolAddress((void**)&p_v,    g_v);
    cudaGetSymbolAddress((void**)&p_qt,   g_qt);
    cudaGetSymbolAddress((void**)&p_kt,   g_kt);
    cudaGetSymbolAddress((void**)&p_vt,   g_vt);
    cudaGetSymbolAddress((void**)&p_acts, g_acts);
    cudaGetSymbolAddress((void**)&p_wh,   g_wh);
    cudaGetSymbolAddress((void**)&p_xnh,  g_xnh);
    cudaGetSymbolAddress((void**)&p_ctxh, g_ctxh);
    cudaGetSymbolAddress((void**)&p_hh,   g_hh);

    cudaFuncSetAttribute(mm2<0,true>,  cudaFuncAttributeMaxDynamicSharedMemorySize, MM2_SMEM);
    cudaFuncSetAttribute(mm2<1,false>, cudaFuncAttributeMaxDynamicSharedMemorySize, MM2_SMEM);
    cudaFuncSetAttribute(mm2<2,false>, cudaFuncAttributeMaxDynamicSharedMemorySize, MM2_SMEM);
    cudaFuncSetAttribute(hx_attn16,    cudaFuncAttributeMaxDynamicSharedMemorySize, AT_SMEM);

    // 0) weight fp16 conversion
    hx_wsplit<<<4096, 256>>>(q_w, k_w, v_w, o_w, w1, w2, p_wh);

    // 1) LN1 -> xn fp16
    hx_ln<<<M_, 256>>>(acts_in, ln1_w, p_xnh);

    // 2) fused QKV projection (48 n-tiles)
    mm2<0,true><<<64*48, 512, MM2_SMEM>>>(M_, HID_, HID_,
        p_xnh, p_wh, nullptr, p_q, p_k, p_v, nullptr, 48);

    // 3) xPos rotary (K,V) + transpose -> fp16 [B*H,S,D]
    const long nrope = (long)M_*H_*(D_/2);
    hx_rope<<<(unsigned)((nrope + 255)/256), 256>>>(p_q, p_k, p_v, p_index,
                                                    p_qt, p_kt, p_vt);

    // 4) fp16 tensor-core causal flash attention -> ctx fp16
    hx_attn16<<<dim3(S_/128, B_*H_), 256, AT_SMEM>>>(p_qt, p_kt, p_vt, p_ctxh);

    // 5) O projection + residual -> acts fp32
    mm2<1,false><<<64*16, 512, MM2_SMEM>>>(M_, HID_, HID_,
        p_ctxh, p_wh + OFF_O, acts_in,
        p_acts, nullptr, nullptr, nullptr, 16);

    // 6) LN2 -> xn fp16 (reuse)
    hx_ln<<<M_, 256>>>(p_acts, ln2_w, p_xnh);

    // 7) FFN up + exact GELU -> h fp16
    mm2<2,false><<<64*64, 512, MM2_SMEM>>>(M_, FF_, HID_,
        p_xnh, p_wh + OFF_W1, nullptr,
        nullptr, nullptr, nullptr, p_hh, 64);

    // 8) FFN down + residual -> output acts
    mm2<1,false><<<64*16, 512, MM2_SMEM>>>(M_, HID_, FF_,
        p_hh, p_wh + OFF_W2, p_acts,
        out, nullptr, nullptr, nullptr, 16);

    // 9) pass-through caches
    const long actN = (long)M_*HID_;
    if (n_in > 2 && (long)out_size >= actN + (long)in_sizes[1] + (long)in_sizes[2]) {
        cudaMemcpyAsync(out + actN, d_in[1],
                        (size_t)in_sizes[1]*sizeof(float),
                        cudaMemcpyDeviceToDevice);
        cudaMemcpyAsync(out + actN + in_sizes[1], d_in[2],
                        (size_t)in_sizes[2]*sizeof(float),
                        cudaMemcpyDeviceToDevice);
    }
}

// round 12
// speedup vs baseline: 3.0420x; 1.0143x over previous
#include <cuda_runtime.h>
#include <cuda_fp16.h>
#include <cstdint>
#include <math.h>

// ---------------- problem constants ----------------
#define B_    8
#define S_    1024
#define HID_  2048
#define H_    16
#define D_    128
#define M_    (B_*S_)      // 8192 token rows
#define FF_   (4*HID_)     // 8192

// weight plane offsets (elements)
#define OFF_Q   0L
#define OFF_K   4194304L
#define OFF_V   8388608L
#define OFF_O   12582912L
#define OFF_W1  16777216L
#define OFF_W2  33554432L
#define W_TOTAL 50331648L

// ---------------- scratch (device globals; no allocations allowed) --------
__device__ float g_acts[(size_t)M_*HID_];
__device__ __half g_qt  [(size_t)M_*HID_];  // [B*H][S][D] fp16
__device__ __half g_kt  [(size_t)M_*HID_];
__device__ __half g_vt  [(size_t)M_*HID_];
__device__ __half g_wh  [W_TOTAL];          // fp16 weights
__device__ __half g_xnh [(size_t)M_*HID_];  // fp16 activations
__device__ __half g_ctxh[(size_t)M_*HID_];
__device__ __half g_hh  [(size_t)M_*FF_];

// ---------------- helpers ---------------------------------------------------
__device__ __forceinline__ uint32_t hx_smem_u32(const void* p) {
    uint32_t a;
    asm("{ .reg .u64 t; cvta.to.shared.u64 t, %1; cvt.u32.u64 %0, t; }" : "=r"(a) : "l"(p));
    return a;
}
#define HX_LDSM4(r, addr) \
    asm volatile("ldmatrix.sync.aligned.m8n8.x4.shared.b16 {%0,%1,%2,%3}, [%4];" \
        : "=r"((r)[0]), "=r"((r)[1]), "=r"((r)[2]), "=r"((r)[3]) : "r"(addr))
#define HX_LDSM4T(r, addr) \
    asm volatile("ldmatrix.sync.aligned.m8n8.x4.trans.shared.b16 {%0,%1,%2,%3}, [%4];" \
        : "=r"((r)[0]), "=r"((r)[1]), "=r"((r)[2]), "=r"((r)[3]) : "r"(addr))

#define HX_MMA(d, a, b0, b1) \
    asm volatile("mma.sync.aligned.m16n8k16.row.col.f32.f16.f16.f32 " \
        "{%0,%1,%2,%3}, {%4,%5,%6,%7}, {%8,%9}, {%0,%1,%2,%3};" \
        : "+f"((d)[0]), "+f"((d)[1]), "+f"((d)[2]), "+f"((d)[3]) \
        : "r"((a)[0]), "r"((a)[1]), "r"((a)[2]), "r"((a)[3]), "r"(b0), "r"(b1))

#define HX_CPASYNC16(dst, src) \
    asm volatile("cp.async.cg.shared.global [%0], [%1], 16;" :: "r"(dst), "l"(src) : "memory")
#define HX_CPCOMMIT() asm volatile("cp.async.commit_group;" ::: "memory")

__device__ __forceinline__ uint32_t hx_pkh(__half a, __half b) {
    __half2 t; t.x = a; t.y = b;
    return *(uint32_t*)&t;
}
__device__ __forceinline__ uint32_t hx_pkf(float a, float b) {
    return hx_pkh(__float2half_rn(a), __float2half_rn(b));
}
__device__ __forceinline__ uint2 hx_cvt4h(float4 v) {
    uint2 h;
    h.x = hx_pkf(v.x, v.y);
    h.y = hx_pkf(v.z, v.w);
    return h;
}

// ---------------- weight fp16 conversion ------------------------------------
__global__ void __launch_bounds__(256) hx_wsplit(
    const float* __restrict__ qw, const float* __restrict__ kw,
    const float* __restrict__ vw, const float* __restrict__ ow,
    const float* __restrict__ w1, const float* __restrict__ w2,
    __half* __restrict__ wh)
{
    const long stride = (long)gridDim.x * blockDim.x;
    for (long i = (long)blockIdx.x * blockDim.x + threadIdx.x;
         i * 4 < W_TOTAL; i += stride) {
        const long e = i * 4;
        const float* src; long off;
        if (e < OFF_W1) {
            const int m = (int)(e >> 22);
            src = (m == 0) ? qw : (m == 1) ? kw : (m == 2) ? vw : ow;
            off = e & 4194303L;
        } else if (e < OFF_W2) { src = w1; off = e - OFF_W1; }
        else                   { src = w2; off = e - OFF_W2; }
        float4 v = *(const float4*)(src + off);
        *(uint2*)(wh + e) = hx_cvt4h(v);
    }
}

// ---------------- fp16 tensor-core GEMM v7 ----------------------------------
// C[M,N] = fp16(A)[M,K] @ fp16(B)[N,K]^T, fp32 accumulate.
// CTA 128x256, K-chunk 64, 3 stages, 16 warps (4m x 4n), warp tile 32x64.
// Stage: A plane 128x144B, B plane 256x144B.
// EPI: 1 = +Res -> fp32 C, 2 = exact gelu -> fp16, 3 = QKV + xPos rope -> fp16
#define MM3_APL   18432
#define MM3_BPL   36864
#define MM3_STAGE (MM3_APL + MM3_BPL)   // 55296
#define MM3_SMEM  (3*MM3_STAGE)         // 165888

template<int EPI>
__global__ void __launch_bounds__(512, 1) mm3(
    int M, int N, int K,
    const __half* __restrict__ Ah,
    const __half* __restrict__ Bh,
    const float* __restrict__ Res,
    float* __restrict__ Cf,
    __half* __restrict__ Ch,
    __half* __restrict__ qt, __half* __restrict__ kt, __half* __restrict__ vt,
    const int* __restrict__ pidx,
    int tiles_n)
{
    extern __shared__ char smc[];
    const uint32_t smb = hx_smem_u32(smc);
    const int tid  = threadIdx.x;
    const int lane = tid & 31;
    const int warp = tid >> 5;     // 0..15
    const int wm = warp & 3;       // m offset wm*32
    const int wn = warp >> 2;      // n offset wn*64

    // supertile raster: 16 m-tiles per band
    const int SUPER = 16;
    const int per  = SUPER * tiles_n;
    const int band = blockIdx.x / per;
    const int rem  = blockIdx.x % per;
    const int mt  = band * SUPER + (rem % SUPER);
    int ntg = rem / SUPER;

    int sel = 0;
    if (EPI == 3) { sel = ntg >> 3; ntg &= 7; }
    const int nt = ntg;

    const long boff = (EPI == 3) ? (long)sel * 4194304L : 0L;
    const __half* pAh = Ah + (long)mt * 128 * K;
    const __half* pBh = Bh + boff + (long)nt * 256 * K;

    float acc[2][8][4];
#pragma unroll
    for (int i = 0; i < 2; i++)
#pragma unroll
        for (int j = 0; j < 8; j++)
#pragma unroll
            for (int r = 0; r < 4; r++) acc[i][j][r] = 0.f;

    auto issue_chunk = [&](int c, int st) {
        const uint32_t sb = smb + st * MM3_STAGE;
        // 3072 ops: A 1024 (128 rows x 8 segs) + B 2048 (256 rows x 8 segs)
#pragma unroll
        for (int q = 0; q < 6; q++) {
            const int op = tid + q * 512;
            if (op < 1024) {
                const int r = op >> 3, s = op & 7;
                HX_CPASYNC16(sb + r * 144 + s * 16, pAh + (long)r * K + c * 64 + s * 8);
            } else {
                const int o2 = op - 1024;
                const int r = o2 >> 3, s = o2 & 7;
                HX_CPASYNC16(sb + MM3_APL + r * 144 + s * 16,
                             pBh + (long)r * K + c * 64 + s * 8);
            }
        }
        HX_CPCOMMIT();
    };

    const int nch = K / 64;
    issue_chunk(0, 0);
    issue_chunk(1, 1);

    for (int c = 0; c < nch; c++) {
        const int st = c % 3;
        if (c + 1 < nch) { asm volatile("cp.async.wait_group 1;" ::: "memory"); }
        else             { asm volatile("cp.async.wait_group 0;" ::: "memory"); }
        __syncthreads();
        if (c + 2 < nch) issue_chunk(c + 2, (c + 2) % 3);

        const uint32_t stb = smb + st * MM3_STAGE;
#pragma unroll
        for (int ks = 0; ks < 4; ks++) {
            const uint32_t colb = ks * 32 + (lane >> 4) * 16;
            uint32_t ah[2][4], bh[4][4];
#pragma unroll
            for (int im = 0; im < 2; im++) {
                const uint32_t row = wm * 32 + im * 16 + (lane & 15);
                HX_LDSM4(ah[im], stb + row * 144 + colb);
            }
#pragma unroll
            for (int ib = 0; ib < 4; ib++) {
                const uint32_t row = wn * 64 + ib * 16 + (lane & 15);
                HX_LDSM4(bh[ib], stb + MM3_APL + row * 144 + colb);
            }
#pragma unroll
            for (int im = 0; im < 2; im++)
#pragma unroll
                for (int j = 0; j < 8; j++)
                    HX_MMA(acc[im][j], ah[im], bh[j>>1][j&1], bh[j>>1][(j&1)+2]);
        }
    }

    // ---- epilogue ----
    const int pos = (EPI == 3) ? pidx[0] : 0;
#pragma unroll
    for (int im = 0; im < 2; im++)
#pragma unroll
        for (int j = 0; j < 8; j++) {
            const long row0 = (long)mt * 128 + wm * 32 + im * 16 + (lane >> 2);
            const long col  = (long)nt * 256 + wn * 64 + j * 8 + (lane & 3) * 2;
            float2 v0 = { acc[im][j][0], acc[im][j][1] };   // row0,   (col, col+1)
            float2 v1 = { acc[im][j][2], acc[im][j][3] };   // row0+8, (col, col+1)
            if (EPI == 3) {
                const int h = (int)(col >> 7);
                const int d = (int)(col & 127);
                const int s0 = (int)(row0 & 1023), b0 = (int)(row0 >> 10);
                const int s1 = (int)((row0 + 8) & 1023), b1 = (int)((row0 + 8) >> 10);
                const long out0 = (((long)(b0*16 + h))*1024 + s0)*128 + d;
                const long out1 = (((long)(b1*16 + h))*1024 + s1)*128 + d;
                __half* dst = (sel == 0) ? qt : (sel == 1) ? kt : vt;
                if (sel == 0) {
                    *(uint32_t*)(dst + out0) = hx_pkf(v0.x, v0.y);
                    *(uint32_t*)(dst + out1) = hx_pkf(v1.x, v1.y);
                } else {
                    const float df    = 2.0f * (float)((d >> 1) + 1);
                    const float theta = expf(-(df * (1.0f/128.0f)) * 9.210340371976184f);
                    const float lz    = logf((df*(1.0f/64.0f) + 51.2f) * (1.0f/52.2f));
                    const float seq0 = (float)(pos + s0 - 512) * (1.0f/512.0f);
                    const float seq1 = (float)(pos + s1 - 512) * (1.0f/512.0f);
                    float sn0, cs0, sn1, cs1;
                    sincosf(seq0*theta, &sn0, &cs0);
                    sincosf(seq1*theta, &sn1, &cs1);
                    float t0 = expf(seq0*lz), t1 = expf(seq1*lz);
                    if (sel == 2) { t0 = 1.0f/t0; t1 = 1.0f/t1; }
                    const float x0 = (v0.x*cs0 - v0.y*sn0)*t0;
                    const float y0 = (v0.y*cs0 + v0.x*sn0)*t0;
                    const float x1 = (v1.x*cs1 - v1.y*sn1)*t1;
                    const float y1 = (v1.y*cs1 + v1.x*sn1)*t1;
                    *(uint32_t*)(dst + out0) = hx_pkf(x0, y0);
                    *(uint32_t*)(dst + out1) = hx_pkf(x1, y1);
                }
            } else {
                const long o0 = row0 * N + col;
                const long o1 = (row0 + 8) * N + col;
                if (EPI == 2) {
                    v0.x = 0.5f*v0.x*(1.0f + erff(v0.x*0.70710678118654752f));
                    v0.y = 0.5f*v0.y*(1.0f + erff(v0.y*0.70710678118654752f));
                    v1.x = 0.5f*v1.x*(1.0f + erff(v1.x*0.70710678118654752f));
                    v1.y = 0.5f*v1.y*(1.0f + erff(v1.y*0.70710678118654752f));
                    *(uint32_t*)(Ch + o0) = hx_pkf(v0.x, v0.y);
                    *(uint32_t*)(Ch + o1) = hx_pkf(v1.x, v1.y);
                } else {
                    const float2 r0 = *(const float2*)(Res + o0);
                    const float2 r1 = *(const float2*)(Res + o1);
                    v0.x += r0.x; v0.y += r0.y; v1.x += r1.x; v1.y += r1.y;
                    *(float2*)(Cf + o0) = v0;
                    *(float2*)(Cf + o1) = v1;
                }
            }
        }
}

// ---------------- LayerNorm -> fp16 plane -----------------------------------
__global__ void __launch_bounds__(256) hx_ln(const float* __restrict__ x,
                                             const float* __restrict__ w,
                                             __half* __restrict__ outh)
{
    const int row = blockIdx.x;
    const int tid = threadIdx.x;
    const float4* xr = (const float4*)(x + (long)row*HID_);
    float4 a = xr[tid];
    float4 b = xr[tid + 256];
    float s  = a.x+a.y+a.z+a.w + b.x+b.y+b.z+b.w;
    float s2 = a.x*a.x+a.y*a.y+a.z*a.z+a.w*a.w
             + b.x*b.x+b.y*b.y+b.z*b.z+b.w*b.w;
#pragma unroll
    for (int o = 16; o; o >>= 1) {
        s  += __shfl_xor_sync(0xffffffffu, s,  o);
        s2 += __shfl_xor_sync(0xffffffffu, s2, o);
    }
    __shared__ float sh[16];
    if ((tid & 31) == 0) { sh[tid >> 5] = s; sh[(tid >> 5) + 8] = s2; }
    __syncthreads();
    float ts = 0.f, ts2 = 0.f;
#pragma unroll
    for (int i = 0; i < 8; i++) { ts += sh[i]; ts2 += sh[i + 8]; }
    const float mean = ts * (1.0f/HID_);
    const float var  = ts2 * (1.0f/HID_) - mean*mean;
    const float rstd = rsqrtf(var + 1e-5f);

    const float4* wr = (const float4*)w;
    float4 w0 = wr[tid], w1v = wr[tid + 256];
    float4 o0, o1;
    o0.x = (a.x-mean)*rstd*w0.x;  o0.y = (a.y-mean)*rstd*w0.y;
    o0.z = (a.z-mean)*rstd*w0.z;  o0.w = (a.w-mean)*rstd*w0.w;
    o1.x = (b.x-mean)*rstd*w1v.x; o1.y = (b.y-mean)*rstd*w1v.y;
    o1.z = (b.z-mean)*rstd*w1v.z; o1.w = (b.w-mean)*rstd*w1v.w;

    *(uint2*)(outh + (long)row*HID_ + tid*4)       = hx_cvt4h(o0);
    *(uint2*)(outh + (long)row*HID_ + (tid+256)*4) = hx_cvt4h(o1);
}

// ---------------- fp16 tensor-core causal flash attention -------------------
#define AT_ROW    272
#define AT_Q      0
#define AT_QBYTES (128*AT_ROW)        // 34816
#define AT_KB     17408               // 64*272
#define AT_STAGE  (2*AT_KB)           // 34816
#define AT_SMEM   (AT_QBYTES + 2*AT_STAGE)  // 104448

__global__ void __launch_bounds__(256, 1) hx_attn16(
    const __half* __restrict__ qt, const __half* __restrict__ kt,
    const __half* __restrict__ vt, __half* __restrict__ ctxh)
{
    extern __shared__ char smc[];
    const uint32_t smb = hx_smem_u32(smc);
    const int tid = threadIdx.x, lane = tid & 31, warp = tid >> 5;
    const int qb = blockIdx.x;
    const int bh = blockIdx.y;
    const int b = bh >> 4, h = bh & 15;
    const int wrow = warp * 16;

    const __half* Qg = qt + ((long)bh*S_ + qb*128)*D_;
    const __half* Kg = kt + (long)bh*S_*D_;
    const __half* Vg = vt + (long)bh*S_*D_;

#pragma unroll
    for (int p = 0; p < 8; p++) {
        const int op = tid + p*256;
        const int r = op >> 4, s = op & 15;
        HX_CPASYNC16(smb + AT_Q + r*AT_ROW + s*16, Qg + (long)r*D_ + s*8);
    }
    auto issue_kv = [&](int j, int st) {
        const uint32_t sb = smb + AT_QBYTES + st*AT_STAGE;
#pragma unroll
        for (int p = 0; p < 8; p++) {
            const int op = tid + p*256;
            const int kv = op >> 10;
            const int rm = op & 1023;
            const int r = rm >> 4, s = rm & 15;
            const __half* src = (kv ? Vg : Kg) + (long)(j*64 + r)*D_ + s*8;
            HX_CPASYNC16(sb + kv*AT_KB + r*AT_ROW + s*16, src);
        }
        HX_CPCOMMIT();
    };

    const int njt = 2*qb + 2;
    issue_kv(0, 0);
    issue_kv(1, 1);
    asm volatile("cp.async.wait_group 1;" ::: "memory");
    __syncthreads();

    uint32_t qf[8][4];
#pragma unroll
    for (int kb = 0; kb < 8; kb++)
        HX_LDSM4(qf[kb], smb + AT_Q + (wrow + (lane & 15))*AT_ROW + kb*32 + (lane >> 4)*16);

    float o[16][4];
#pragma unroll
    for (int nd = 0; nd < 16; nd++)
#pragma unroll
        for (int r = 0; r < 4; r++) o[nd][r] = 0.f;
    float mi0 = -INFINITY, mi1 = -INFINITY, li0 = 0.f, li1 = 0.f;

    const float scale = 0.088388347648318447f;
    const int r0g = qb*128 + wrow + (lane >> 2);
    const int c0l = (lane & 3)*2;

    for (int j = 0; j < njt; j++) {
        const int st = j & 1;
        if (j > 0) {
            if (j + 1 < njt) { asm volatile("cp.async.wait_group 1;" ::: "memory"); }
            else             { asm volatile("cp.async.wait_group 0;" ::: "memory"); }
            __syncthreads();
        }
        const uint32_t kb_ = smb + AT_QBYTES + st*AT_STAGE;
        const uint32_t vb_ = kb_ + AT_KB;

        float sacc[8][4];
#pragma unroll
        for (int nb = 0; nb < 8; nb++)
#pragma unroll
            for (int r = 0; r < 4; r++) sacc[nb][r] = 0.f;
#pragma unroll
        for (int ng = 0; ng < 4; ng++) {
#pragma unroll
            for (int kb = 0; kb < 8; kb++) {
                uint32_t kf[4];
                HX_LDSM4(kf, kb_ + (ng*16 + (lane & 15))*AT_ROW + kb*32 + (lane >> 4)*16);
                HX_MMA(sacc[ng*2+0], qf[kb], kf[0], kf[2]);
                HX_MMA(sacc[ng*2+1], qf[kb], kf[1], kf[3]);
            }
        }

        float rmax0 = -INFINITY, rmax1 = -INFINITY;
#pragma unroll
        for (int nb = 0; nb < 8; nb++) {
            const int cg = j*64 + nb*8 + c0l;
            float v0 = sacc[nb][0]*scale; if (cg     > r0g)     v0 = -INFINITY;
            float v1 = sacc[nb][1]*scale; if (cg + 1 > r0g)     v1 = -INFINITY;
            float v2 = sacc[nb][2]*scale; if (cg     > r0g + 8) v2 = -INFINITY;
            float v3 = sacc[nb][3]*scale; if (cg + 1 > r0g + 8) v3 = -INFINITY;
            sacc[nb][0] = v0; sacc[nb][1] = v1; sacc[nb][2] = v2; sacc[nb][3] = v3;
            rmax0 = fmaxf(rmax0, fmaxf(v0, v1));
            rmax1 = fmaxf(rmax1, fmaxf(v2, v3));
        }
        rmax0 = fmaxf(rmax0, __shfl_xor_sync(0xffffffffu, rmax0, 1));
        rmax0 = fmaxf(rmax0, __shfl_xor_sync(0xffffffffu, rmax0, 2));
        rmax1 = fmaxf(rmax1, __shfl_xor_sync(0xffffffffu, rmax1, 1));
        rmax1 = fmaxf(rmax1, __shfl_xor_sync(0xffffffffu, rmax1, 2));
        const float mn0 = fmaxf(mi0, rmax0), mn1 = fmaxf(mi1, rmax1);
        const float a0 = expf(mi0 - mn0), a1 = expf(mi1 - mn1);
        float rs0 = 0.f, rs1 = 0.f;
#pragma unroll
        for (int nb = 0; nb < 8; nb++) {
            const float p0 = expf(sacc[nb][0] - mn0);
            const float p1 = expf(sacc[nb][1] - mn0);
            const float p2 = expf(sacc[nb][2] - mn1);
            const float p3 = expf(sacc[nb][3] - mn1);
            sacc[nb][0] = p0; sacc[nb][1] = p1; sacc[nb][2] = p2; sacc[nb][3] = p3;
            rs0 += p0 + p1; rs1 += p2 + p3;
        }
        rs0 += __shfl_xor_sync(0xffffffffu, rs0, 1);
        rs0 += __shfl_xor_sync(0xffffffffu, rs0, 2);
        rs1 += __shfl_xor_sync(0xffffffffu, rs1, 1);
        rs1 += __shfl_xor_sync(0xffffffffu, rs1, 2);
        li0 = li0*a0 + rs0; li1 = li1*a1 + rs1;
        mi0 = mn0; mi1 = mn1;
#pragma unroll
        for (int nd = 0; nd < 16; nd++) {
            o[nd][0] *= a0; o[nd][1] *= a0; o[nd][2] *= a1; o[nd][3] *= a1;
        }

        uint32_t pa[4][4];
#pragma unroll
        for (int kk = 0; kk < 4; kk++) {
            pa[kk][0] = hx_pkf(sacc[2*kk][0],   sacc[2*kk][1]);
            pa[kk][1] = hx_pkf(sacc[2*kk][2],   sacc[2*kk][3]);
            pa[kk][2] = hx_pkf(sacc[2*kk+1][0], sacc[2*kk+1][1]);
            pa[kk][3] = hx_pkf(sacc[2*kk+1][2], sacc[2*kk+1][3]);
        }

#pragma unroll
        for (int ndg = 0; ndg < 8; ndg++) {
#pragma unroll
            for (int kk = 0; kk < 4; kk++) {
                uint32_t vf[4];
                HX_LDSM4T(vf, vb_ + (kk*16 + (lane & 15))*AT_ROW + ndg*32 + (lane >> 4)*16);
                HX_MMA(o[ndg*2+0], pa[kk], vf[0], vf[1]);
                HX_MMA(o[ndg*2+1], pa[kk], vf[2], vf[3]);
            }
        }
        __syncthreads();
        if (j + 2 < njt) issue_kv(j + 2, st);
    }

    const float i0 = 1.f/li0, i1 = 1.f/li1;
    const long s0 = (long)(b*S_) + qb*128 + wrow + (lane >> 2);
    const long base0 = s0*HID_ + h*128 + c0l;
    const long base1 = (s0 + 8)*HID_ + h*128 + c0l;
#pragma unroll
    for (int nd = 0; nd < 16; nd++) {
        *(uint32_t*)(ctxh + base0 + nd*8) = hx_pkf(o[nd][0]*i0, o[nd][1]*i0);
        *(uint32_t*)(ctxh + base1 + nd*8) = hx_pkf(o[nd][2]*i1, o[nd][3]*i1);
    }
}

// ---------------- launch ----------------------------------------------------
extern "C" void kernel_launch(void* const* d_in, const int* in_sizes, int n_in,
                              void* d_out, int out_size)
{
    const float* acts_in = (const float*)d_in[0];
    const float* ln1_w   = (const float*)d_in[4];
    const float* ln2_w   = (const float*)d_in[5];
    const float* q_w     = (const float*)d_in[6];
    const float* k_w     = (const float*)d_in[7];
    const float* v_w     = (const float*)d_in[8];
    const float* o_w     = (const float*)d_in[9];
    const float* w1      = (const float*)d_in[10];
    const float* w2      = (const float*)d_in[11];
    const int*   p_index = (const int*)d_in[3];
    float* out = (float*)d_out;

    float *p_acts;
    __half *p_qt, *p_kt, *p_vt, *p_wh, *p_xnh, *p_ctxh, *p_hh;
    cudaGetSymbolAddress((void**)&p_acts, g_acts);
    cudaGetSymbolAddress((void**)&p_qt,   g_qt);
    cudaGetSymbolAddress((void**)&p_kt,   g_kt);
    cudaGetSymbolAddress((void**)&p_vt,   g_vt);
    cudaGetSymbolAddress((void**)&p_wh,   g_wh);
    cudaGetSymbolAddress((void**)&p_xnh,  g_xnh);
    cudaGetSymbolAddress((void**)&p_ctxh, g_ctxh);
    cudaGetSymbolAddress((void**)&p_hh,   g_hh);

    cudaFuncSetAttribute(mm3<1>, cudaFuncAttributeMaxDynamicSharedMemorySize, MM3_SMEM);
    cudaFuncSetAttribute(mm3<2>, cudaFuncAttributeMaxDynamicSharedMemorySize, MM3_SMEM);
    cudaFuncSetAttribute(mm3<3>, cudaFuncAttributeMaxDynamicSharedMemorySize, MM3_SMEM);
    cudaFuncSetAttribute(hx_attn16, cudaFuncAttributeMaxDynamicSharedMemorySize, AT_SMEM);

    // 0) weight fp16 conversion
    hx_wsplit<<<4096, 256>>>(q_w, k_w, v_w, o_w, w1, w2, p_wh);

    // 1) LN1 -> xn fp16
    hx_ln<<<M_, 256>>>(acts_in, ln1_w, p_xnh);

    // 2) fused QKV projection + xPos rope + transpose -> fp16 qt/kt/vt
    //    N=2048 per matrix, 8 n-tiles of 256 each, 24 total
    mm3<3><<<64*24, 512, MM3_SMEM>>>(M_, HID_, HID_,
        p_xnh, p_wh, nullptr, nullptr, nullptr,
        p_qt, p_kt, p_vt, p_index, 24);

    // 3) fp16 tensor-core causal flash attention -> ctx fp16
    hx_attn16<<<dim3(S_/128, B_*H_), 256, AT_SMEM>>>(p_qt, p_kt, p_vt, p_ctxh);

    // 4) O projection + residual -> acts fp32
    mm3<1><<<64*8, 512, MM3_SMEM>>>(M_, HID_, HID_,
        p_ctxh, p_wh + OFF_O, acts_in, p_acts, nullptr,
        nullptr, nullptr, nullptr, nullptr, 8);

    // 5) LN2 -> xn fp16 (reuse)
    hx_ln<<<M_, 256>>>(p_acts, ln2_w, p_xnh);

    // 6) FFN up + exact GELU -> h fp16
    mm3<2><<<64*32, 512, MM3_SMEM>>>(M_, FF_, HID_,
        p_xnh, p_wh + OFF_W1, nullptr, nullptr, p_hh,
        nullptr, nullptr, nullptr, nullptr, 32);

    // 7) FFN down + residual -> output acts
    mm3<1><<<64*8, 512, MM3_SMEM>>>(M_, HID_, FF_,
        p_hh, p_wh + OFF_W2, p_acts, out, nullptr,
        nullptr, nullptr, nullptr, nullptr, 8);

    // 8) pass-through caches
    const long actN = (long)M_*HID_;
    if (n_in > 2 && (long)out_size >= actN + (long)in_sizes[1] + (long)in_sizes[2]) {
        cudaMemcpyAsync(out + actN, d_in[1],
                        (size_t)in_sizes[1]*sizeof(float),
                        cudaMemcpyDeviceToDevice);
        cudaMemcpyAsync(out + actN + in_sizes[1], d_in[2],
                        (size_t)in_sizes[2]*sizeof(float),
                        cudaMemcpyDeviceToDevice);
    }
}

// round 13
// speedup vs baseline: 3.3953x; 1.1161x over previous
#include <cuda_runtime.h>
#include <cuda_fp16.h>
#include <cstdint>
#include <math.h>

// ---------------- problem constants ----------------
#define B_    8
#define S_    1024
#define HID_  2048
#define H_    16
#define D_    128
#define M_    (B_*S_)      // 8192 token rows
#define FF_   (4*HID_)     // 8192

// weight plane offsets (elements)
#define OFF_Q   0L
#define OFF_K   4194304L
#define OFF_V   8388608L
#define OFF_O   12582912L
#define OFF_W1  16777216L
#define OFF_W2  33554432L
#define W_TOTAL 50331648L

// ---------------- scratch (device globals; no allocations allowed) --------
__device__ float g_acts[(size_t)M_*HID_];
__device__ __half g_qt  [(size_t)M_*HID_];  // [B*H][S][D] fp16
__device__ __half g_kt  [(size_t)M_*HID_];
__device__ __half g_vt  [(size_t)M_*HID_];
__device__ __half g_wh  [W_TOTAL];          // fp16 weights
__device__ __half g_xnh [(size_t)M_*HID_];  // fp16 activations
__device__ __half g_ctxh[(size_t)M_*HID_];
__device__ __half g_hh  [(size_t)M_*FF_];

// ---------------- helpers ---------------------------------------------------
__device__ __forceinline__ uint32_t hx_smem_u32(const void* p) {
    uint32_t a;
    asm("{ .reg .u64 t; cvta.to.shared.u64 t, %1; cvt.u32.u64 %0, t; }" : "=r"(a) : "l"(p));
    return a;
}
#define HX_LDSM4(r, addr) \
    asm volatile("ldmatrix.sync.aligned.m8n8.x4.shared.b16 {%0,%1,%2,%3}, [%4];" \
        : "=r"((r)[0]), "=r"((r)[1]), "=r"((r)[2]), "=r"((r)[3]) : "r"(addr))
#define HX_LDSM4T(r, addr) \
    asm volatile("ldmatrix.sync.aligned.m8n8.x4.trans.shared.b16 {%0,%1,%2,%3}, [%4];" \
        : "=r"((r)[0]), "=r"((r)[1]), "=r"((r)[2]), "=r"((r)[3]) : "r"(addr))

#define HX_MMA(d, a, b0, b1) \
    asm volatile("mma.sync.aligned.m16n8k16.row.col.f32.f16.f16.f32 " \
        "{%0,%1,%2,%3}, {%4,%5,%6,%7}, {%8,%9}, {%0,%1,%2,%3};" \
        : "+f"((d)[0]), "+f"((d)[1]), "+f"((d)[2]), "+f"((d)[3]) \
        : "r"((a)[0]), "r"((a)[1]), "r"((a)[2]), "r"((a)[3]), "r"(b0), "r"(b1))

#define HX_CPASYNC16(dst, src) \
    asm volatile("cp.async.cg.shared.global [%0], [%1], 16;" :: "r"(dst), "l"(src) : "memory")
#define HX_CPCOMMIT() asm volatile("cp.async.commit_group;" ::: "memory")

__device__ __forceinline__ uint32_t hx_pkh(__half a, __half b) {
    __half2 t; t.x = a; t.y = b;
    return *(uint32_t*)&t;
}
__device__ __forceinline__ uint32_t hx_pkf(float a, float b) {
    return hx_pkh(__float2half_rn(a), __float2half_rn(b));
}
__device__ __forceinline__ uint2 hx_cvt4h(float4 v) {
    uint2 h;
    h.x = hx_pkf(v.x, v.y);
    h.y = hx_pkf(v.z, v.w);
    return h;
}

// ---------------- weight fp16 conversion ------------------------------------
__global__ void __launch_bounds__(256) hx_wsplit(
    const float* __restrict__ qw, const float* __restrict__ kw,
    const float* __restrict__ vw, const float* __restrict__ ow,
    const float* __restrict__ w1, const float* __restrict__ w2,
    __half* __restrict__ wh)
{
    const long stride = (long)gridDim.x * blockDim.x;
    for (long i = (long)blockIdx.x * blockDim.x + threadIdx.x;
         i * 4 < W_TOTAL; i += stride) {
        const long e = i * 4;
        const float* src; long off;
        if (e < OFF_W1) {
            const int m = (int)(e >> 22);
            src = (m == 0) ? qw : (m == 1) ? kw : (m == 2) ? vw : ow;
            off = e & 4194303L;
        } else if (e < OFF_W2) { src = w1; off = e - OFF_W1; }
        else                   { src = w2; off = e - OFF_W2; }
        float4 v = *(const float4*)(src + off);
        *(uint2*)(wh + e) = hx_cvt4h(v);
    }
}

// ---------------- fp16 tensor-core GEMM v8 (2 CTAs/SM) ----------------------
// C[M,N] = fp16(A)[M,K] @ fp16(B)[N,K]^T, fp32 accumulate.
// CTA 128x128, 256 threads, 8 warps (4m x 2n), warp tile 32x64.
// K-chunk 64, 3 stages of (A 128x144B + B 128x144B) = 110.6 KB -> 2 CTAs/SM.
// EPI: 1 = +Res -> fp32 C, 2 = exact gelu -> fp16, 3 = QKV + xPos rope -> fp16
#define MM4_PL    18432
#define MM4_STAGE (2*MM4_PL)      // 36864
#define MM4_SMEM  (3*MM4_STAGE)   // 110592

template<int EPI>
__global__ void __launch_bounds__(256, 2) mm4(
    int M, int N, int K,
    const __half* __restrict__ Ah,
    const __half* __restrict__ Bh,
    const float* __restrict__ Res,
    float* __restrict__ Cf,
    __half* __restrict__ Ch,
    __half* __restrict__ qt, __half* __restrict__ kt, __half* __restrict__ vt,
    const int* __restrict__ pidx,
    int tiles_n)
{
    extern __shared__ char smc[];
    const uint32_t smb = hx_smem_u32(smc);
    const int tid  = threadIdx.x;
    const int lane = tid & 31;
    const int warp = tid >> 5;     // 0..7
    const int wm = warp & 3;       // m offset wm*32
    const int wn = warp >> 2;      // n offset wn*64

    // supertile raster: 16 m-tiles per band
    const int SUPER = 16;
    const int per  = SUPER * tiles_n;
    const int band = blockIdx.x / per;
    const int rem  = blockIdx.x % per;
    const int mt  = band * SUPER + (rem % SUPER);
    int ntg = rem / SUPER;

    int sel = 0;
    if (EPI == 3) { sel = ntg >> 4; ntg &= 15; }
    const int nt = ntg;

    const long boff = (EPI == 3) ? (long)sel * 4194304L : 0L;
    const __half* pAh = Ah + (long)mt * 128 * K;
    const __half* pBh = Bh + boff + (long)nt * 128 * K;

    float acc[2][8][4];
#pragma unroll
    for (int i = 0; i < 2; i++)
#pragma unroll
        for (int j = 0; j < 8; j++)
#pragma unroll
            for (int r = 0; r < 4; r++) acc[i][j][r] = 0.f;

    auto issue_chunk = [&](int c, int st) {
        const uint32_t sb = smb + st * MM4_STAGE;
        // 2048 ops (2 planes x 128 rows x 8 segs), 8 per thread
#pragma unroll
        for (int q = 0; q < 8; q++) {
            const int op = tid + q * 256;        // 0..2047
            const int pl = op >> 10;             // 0=A, 1=B
            const int rm = op & 1023;
            const int r  = rm >> 3;              // 0..127
            const int s  = rm & 7;
            const __half* src = (pl ? pBh : pAh) + (long)r * K + c * 64 + s * 8;
            HX_CPASYNC16(sb + pl * MM4_PL + r * 144 + s * 16, src);
        }
        HX_CPCOMMIT();
    };

    const int nch = K / 64;
    issue_chunk(0, 0);
    issue_chunk(1, 1);

    for (int c = 0; c < nch; c++) {
        const int st = c % 3;
        if (c + 1 < nch) { asm volatile("cp.async.wait_group 1;" ::: "memory"); }
        else             { asm volatile("cp.async.wait_group 0;" ::: "memory"); }
        __syncthreads();
        if (c + 2 < nch) issue_chunk(c + 2, (c + 2) % 3);

        const uint32_t stb = smb + st * MM4_STAGE;
#pragma unroll
        for (int ks = 0; ks < 4; ks++) {
            const uint32_t colb = ks * 32 + (lane >> 4) * 16;
            uint32_t ah[2][4], bh[4][4];
#pragma unroll
            for (int im = 0; im < 2; im++) {
                const uint32_t row = wm * 32 + im * 16 + (lane & 15);
                HX_LDSM4(ah[im], stb + row * 144 + colb);
            }
#pragma unroll
            for (int ib = 0; ib < 4; ib++) {
                const uint32_t row = wn * 64 + ib * 16 + (lane & 15);
                HX_LDSM4(bh[ib], stb + MM4_PL + row * 144 + colb);
            }
#pragma unroll
            for (int im = 0; im < 2; im++)
#pragma unroll
                for (int j = 0; j < 8; j++)
                    HX_MMA(acc[im][j], ah[im], bh[j>>1][j&1], bh[j>>1][(j&1)+2]);
        }
    }

    // ---- epilogue ----
    const int pos = (EPI == 3) ? pidx[0] : 0;
#pragma unroll
    for (int im = 0; im < 2; im++)
#pragma unroll
        for (int j = 0; j < 8; j++) {
            const long row0 = (long)mt * 128 + wm * 32 + im * 16 + (lane >> 2);
            const long col  = (long)nt * 128 + wn * 64 + j * 8 + (lane & 3) * 2;
            float2 v0 = { acc[im][j][0], acc[im][j][1] };   // row0,   (col, col+1)
            float2 v1 = { acc[im][j][2], acc[im][j][3] };   // row0+8, (col, col+1)
            if (EPI == 3) {
                const int h = (int)(col >> 7);
                const int d = (int)(col & 127);
                const int s0 = (int)(row0 & 1023), b0 = (int)(row0 >> 10);
                const int s1 = (int)((row0 + 8) & 1023), b1 = (int)((row0 + 8) >> 10);
                const long out0 = (((long)(b0*16 + h))*1024 + s0)*128 + d;
                const long out1 = (((long)(b1*16 + h))*1024 + s1)*128 + d;
                __half* dst = (sel == 0) ? qt : (sel == 1) ? kt : vt;
                if (sel == 0) {
                    *(uint32_t*)(dst + out0) = hx_pkf(v0.x, v0.y);
                    *(uint32_t*)(dst + out1) = hx_pkf(v1.x, v1.y);
                } else {
                    const float df    = 2.0f * (float)((d >> 1) + 1);
                    const float theta = expf(-(df * (1.0f/128.0f)) * 9.210340371976184f);
                    const float lz    = logf((df*(1.0f/64.0f) + 51.2f) * (1.0f/52.2f));
                    const float seq0 = (float)(pos + s0 - 512) * (1.0f/512.0f);
                    const float seq1 = (float)(pos + s1 - 512) * (1.0f/512.0f);
                    float sn0, cs0, sn1, cs1;
                    sincosf(seq0*theta, &sn0, &cs0);
                    sincosf(seq1*theta, &sn1, &cs1);
                    float t0 = expf(seq0*lz), t1 = expf(seq1*lz);
                    if (sel == 2) { t0 = 1.0f/t0; t1 = 1.0f/t1; }
                    const float x0 = (v0.x*cs0 - v0.y*sn0)*t0;
                    const float y0 = (v0.y*cs0 + v0.x*sn0)*t0;
                    const float x1 = (v1.x*cs1 - v1.y*sn1)*t1;
                    const float y1 = (v1.y*cs1 + v1.x*sn1)*t1;
                    *(uint32_t*)(dst + out0) = hx_pkf(x0, y0);
                    *(uint32_t*)(dst + out1) = hx_pkf(x1, y1);
                }
            } else {
                const long o0 = row0 * N + col;
                const long o1 = (row0 + 8) * N + col;
                if (EPI == 2) {
                    v0.x = 0.5f*v0.x*(1.0f + erff(v0.x*0.70710678118654752f));
                    v0.y = 0.5f*v0.y*(1.0f + erff(v0.y*0.70710678118654752f));
                    v1.x = 0.5f*v1.x*(1.0f + erff(v1.x*0.70710678118654752f));
                    v1.y = 0.5f*v1.y*(1.0f + erff(v1.y*0.70710678118654752f));
                    *(uint32_t*)(Ch + o0) = hx_pkf(v0.x, v0.y);
                    *(uint32_t*)(Ch + o1) = hx_pkf(v1.x, v1.y);
                } else {
                    const float2 r0 = *(const float2*)(Res + o0);
                    const float2 r1 = *(const float2*)(Res + o1);
                    v0.x += r0.x; v0.y += r0.y; v1.x += r1.x; v1.y += r1.y;
                    *(float2*)(Cf + o0) = v0;
                    *(float2*)(Cf + o1) = v1;
                }
            }
        }
}

// ---------------- LayerNorm -> fp16 plane -----------------------------------
__global__ void __launch_bounds__(256) hx_ln(const float* __restrict__ x,
                                             const float* __restrict__ w,
                                             __half* __restrict__ outh)
{
    const int row = blockIdx.x;
    const int tid = threadIdx.x;
    const float4* xr = (const float4*)(x + (long)row*HID_);
    float4 a = xr[tid];
    float4 b = xr[tid + 256];
    float s  = a.x+a.y+a.z+a.w + b.x+b.y+b.z+b.w;
    float s2 = a.x*a.x+a.y*a.y+a.z*a.z+a.w*a.w
             + b.x*b.x+b.y*b.y+b.z*b.z+b.w*b.w;
#pragma unroll
    for (int o = 16; o; o >>= 1) {
        s  += __shfl_xor_sync(0xffffffffu, s,  o);
        s2 += __shfl_xor_sync(0xffffffffu, s2, o);
    }
    __shared__ float sh[16];
    if ((tid & 31) == 0) { sh[tid >> 5] = s; sh[(tid >> 5) + 8] = s2; }
    __syncthreads();
    float ts = 0.f, ts2 = 0.f;
#pragma unroll
    for (int i = 0; i < 8; i++) { ts += sh[i]; ts2 += sh[i + 8]; }
    const float mean = ts * (1.0f/HID_);
    const float var  = ts2 * (1.0f/HID_) - mean*mean;
    const float rstd = rsqrtf(var + 1e-5f);

    const float4* wr = (const float4*)w;
    float4 w0 = wr[tid], w1v = wr[tid + 256];
    float4 o0, o1;
    o0.x = (a.x-mean)*rstd*w0.x;  o0.y = (a.y-mean)*rstd*w0.y;
    o0.z = (a.z-mean)*rstd*w0.z;  o0.w = (a.w-mean)*rstd*w0.w;
    o1.x = (b.x-mean)*rstd*w1v.x; o1.y = (b.y-mean)*rstd*w1v.y;
    o1.z = (b.z-mean)*rstd*w1v.z; o1.w = (b.w-mean)*rstd*w1v.w;

    *(uint2*)(outh + (long)row*HID_ + tid*4)       = hx_cvt4h(o0);
    *(uint2*)(outh + (long)row*HID_ + (tid+256)*4) = hx_cvt4h(o1);
}

// ---------------- fp16 tensor-core causal flash attention -------------------
#define AT_ROW    272
#define AT_Q      0
#define AT_QBYTES (128*AT_ROW)        // 34816
#define AT_KB     17408               // 64*272
#define AT_STAGE  (2*AT_KB)           // 34816
#define AT_SMEM   (AT_QBYTES + 2*AT_STAGE)  // 104448

__global__ void __launch_bounds__(256, 1) hx_attn16(
    const __half* __restrict__ qt, const __half* __restrict__ kt,
    const __half* __restrict__ vt, __half* __restrict__ ctxh)
{
    extern __shared__ char smc[];
    const uint32_t smb = hx_smem_u32(smc);
    const int tid = threadIdx.x, lane = tid & 31, warp = tid >> 5;
    const int qb = blockIdx.x;
    const int bh = blockIdx.y;
    const int b = bh >> 4, h = bh & 15;
    const int wrow = warp * 16;

    const __half* Qg = qt + ((long)bh*S_ + qb*128)*D_;
    const __half* Kg = kt + (long)bh*S_*D_;
    const __half* Vg = vt + (long)bh*S_*D_;

#pragma unroll
    for (int p = 0; p < 8; p++) {
        const int op = tid + p*256;
        const int r = op >> 4, s = op & 15;
        HX_CPASYNC16(smb + AT_Q + r*AT_ROW + s*16, Qg + (long)r*D_ + s*8);
    }
    auto issue_kv = [&](int j, int st) {
        const uint32_t sb = smb + AT_QBYTES + st*AT_STAGE;
#pragma unroll
        for (int p = 0; p < 8; p++) {
            const int op = tid + p*256;
            const int kv = op >> 10;
            const int rm = op & 1023;
            const int r = rm >> 4, s = rm & 15;
            const __half* src = (kv ? Vg : Kg) + (long)(j*64 + r)*D_ + s*8;
            HX_CPASYNC16(sb + kv*AT_KB + r*AT_ROW + s*16, src);
        }
        HX_CPCOMMIT();
    };

    const int njt = 2*qb + 2;
    issue_kv(0, 0);
    issue_kv(1, 1);
    asm volatile("cp.async.wait_group 1;" ::: "memory");
    __syncthreads();

    uint32_t qf[8][4];
#pragma unroll
    for (int kb = 0; kb < 8; kb++)
        HX_LDSM4(qf[kb], smb + AT_Q + (wrow + (lane & 15))*AT_ROW + kb*32 + (lane >> 4)*16);

    float o[16][4];
#pragma unroll
    for (int nd = 0; nd < 16; nd++)
#pragma unroll
        for (int r = 0; r < 4; r++) o[nd][r] = 0.f;
    float mi0 = -INFINITY, mi1 = -INFINITY, li0 = 0.f, li1 = 0.f;

    const float scale = 0.088388347648318447f;
    const int r0g = qb*128 + wrow + (lane >> 2);
    const int c0l = (lane & 3)*2;

    for (int j = 0; j < njt; j++) {
        const int st = j & 1;
        if (j > 0) {
            if (j + 1 < njt) { asm volatile("cp.async.wait_group 1;" ::: "memory"); }
            else             { asm volatile("cp.async.wait_group 0;" ::: "memory"); }
            __syncthreads();
        }
        const uint32_t kb_ = smb + AT_QBYTES + st*AT_STAGE;
        const uint32_t vb_ = kb_ + AT_KB;

        float sacc[8][4];
#pragma unroll
        for (int nb = 0; nb < 8; nb++)
#pragma unroll
            for (int r = 0; r < 4; r++) sacc[nb][r] = 0.f;
#pragma unroll
        for (int ng = 0; ng < 4; ng++) {
#pragma unroll
            for (int kb = 0; kb < 8; kb++) {
                uint32_t kf[4];
                HX_LDSM4(kf, kb_ + (ng*16 + (lane & 15))*AT_ROW + kb*32 + (lane >> 4)*16);
                HX_MMA(sacc[ng*2+0], qf[kb], kf[0], kf[2]);
                HX_MMA(sacc[ng*2+1], qf[kb], kf[1], kf[3]);
            }
        }

        float rmax0 = -INFINITY, rmax1 = -INFINITY;
#pragma unroll
        for (int nb = 0; nb < 8; nb++) {
            const int cg = j*64 + nb*8 + c0l;
            float v0 = sacc[nb][0]*scale; if (cg     > r0g)     v0 = -INFINITY;
            float v1 = sacc[nb][1]*scale; if (cg + 1 > r0g)     v1 = -INFINITY;
            float v2 = sacc[nb][2]*scale; if (cg     > r0g + 8) v2 = -INFINITY;
            float v3 = sacc[nb][3]*scale; if (cg + 1 > r0g + 8) v3 = -INFINITY;
            sacc[nb][0] = v0; sacc[nb][1] = v1; sacc[nb][2] = v2; sacc[nb][3] = v3;
            rmax0 = fmaxf(rmax0, fmaxf(v0, v1));
            rmax1 = fmaxf(rmax1, fmaxf(v2, v3));
        }
        rmax0 = fmaxf(rmax0, __shfl_xor_sync(0xffffffffu, rmax0, 1));
        rmax0 = fmaxf(rmax0, __shfl_xor_sync(0xffffffffu, rmax0, 2));
        rmax1 = fmaxf(rmax1, __shfl_xor_sync(0xffffffffu, rmax1, 1));
        rmax1 = fmaxf(rmax1, __shfl_xor_sync(0xffffffffu, rmax1, 2));
        const float mn0 = fmaxf(mi0, rmax0), mn1 = fmaxf(mi1, rmax1);
        const float a0 = expf(mi0 - mn0), a1 = expf(mi1 - mn1);
        float rs0 = 0.f, rs1 = 0.f;
#pragma unroll
        for (int nb = 0; nb < 8; nb++) {
            const float p0 = expf(sacc[nb][0] - mn0);
            const float p1 = expf(sacc[nb][1] - mn0);
            const float p2 = expf(sacc[nb][2] - mn1);
            const float p3 = expf(sacc[nb][3] - mn1);
            sacc[nb][0] = p0; sacc[nb][1] = p1; sacc[nb][2] = p2; sacc[nb][3] = p3;
            rs0 += p0 + p1; rs1 += p2 + p3;
        }
        rs0 += __shfl_xor_sync(0xffffffffu, rs0, 1);
        rs0 += __shfl_xor_sync(0xffffffffu, rs0, 2);
        rs1 += __shfl_xor_sync(0xffffffffu, rs1, 1);
        rs1 += __shfl_xor_sync(0xffffffffu, rs1, 2);
        li0 = li0*a0 + rs0; li1 = li1*a1 + rs1;
        mi0 = mn0; mi1 = mn1;
#pragma unroll
        for (int nd = 0; nd < 16; nd++) {
            o[nd][0] *= a0; o[nd][1] *= a0; o[nd][2] *= a1; o[nd][3] *= a1;
        }

        uint32_t pa[4][4];
#pragma unroll
        for (int kk = 0; kk < 4; kk++) {
            pa[kk][0] = hx_pkf(sacc[2*kk][0],   sacc[2*kk][1]);
            pa[kk][1] = hx_pkf(sacc[2*kk][2],   sacc[2*kk][3]);
            pa[kk][2] = hx_pkf(sacc[2*kk+1][0], sacc[2*kk+1][1]);
            pa[kk][3] = hx_pkf(sacc[2*kk+1][2], sacc[2*kk+1][3]);
        }

#pragma unroll
        for (int ndg = 0; ndg < 8; ndg++) {
#pragma unroll
            for (int kk = 0; kk < 4; kk++) {
                uint32_t vf[4];
                HX_LDSM4T(vf, vb_ + (kk*16 + (lane & 15))*AT_ROW + ndg*32 + (lane >> 4)*16);
                HX_MMA(o[ndg*2+0], pa[kk], vf[0], vf[1]);
                HX_MMA(o[ndg*2+1], pa[kk], vf[2], vf[3]);
            }
        }
        __syncthreads();
        if (j + 2 < njt) issue_kv(j + 2, st);
    }

    const float i0 = 1.f/li0, i1 = 1.f/li1;
    const long s0 = (long)(b*S_) + qb*128 + wrow + (lane >> 2);
    const long base0 = s0*HID_ + h*128 + c0l;
    const long base1 = (s0 + 8)*HID_ + h*128 + c0l;
#pragma unroll
    for (int nd = 0; nd < 16; nd++) {
        *(uint32_t*)(ctxh + base0 + nd*8) = hx_pkf(o[nd][0]*i0, o[nd][1]*i0);
        *(uint32_t*)(ctxh + base1 + nd*8) = hx_pkf(o[nd][2]*i1, o[nd][3]*i1);
    }
}

// ---------------- launch ----------------------------------------------------
extern "C" void kernel_launch(void* const* d_in, const int* in_sizes, int n_in,
                              void* d_out, int out_size)
{
    const float* acts_in = (const float*)d_in[0];
    const float* ln1_w   = (const float*)d_in[4];
    const float* ln2_w   = (const float*)d_in[5];
    const float* q_w     = (const float*)d_in[6];
    const float* k_w     = (const float*)d_in[7];
    const float* v_w     = (const float*)d_in[8];
    const float* o_w     = (const float*)d_in[9];
    const float* w1      = (const float*)d_in[10];
    const float* w2      = (const float*)d_in[11];
    const int*   p_index = (const int*)d_in[3];
    float* out = (float*)d_out;

    float *p_acts;
    __half *p_qt, *p_kt, *p_vt, *p_wh, *p_xnh, *p_ctxh, *p_hh;
    cudaGetSymbolAddress((void**)&p_acts, g_acts);
    cudaGetSymbolAddress((void**)&p_qt,   g_qt);
    cudaGetSymbolAddress((void**)&p_kt,   g_kt);
    cudaGetSymbolAddress((void**)&p_vt,   g_vt);
    cudaGetSymbolAddress((void**)&p_wh,   g_wh);
    cudaGetSymbolAddress((void**)&p_xnh,  g_xnh);
    cudaGetSymbolAddress((void**)&p_ctxh, g_ctxh);
    cudaGetSymbolAddress((void**)&p_hh,   g_hh);

    cudaFuncSetAttribute(mm4<1>, cudaFuncAttributeMaxDynamicSharedMemorySize, MM4_SMEM);
    cudaFuncSetAttribute(mm4<2>, cudaFuncAttributeMaxDynamicSharedMemorySize, MM4_SMEM);
    cudaFuncSetAttribute(mm4<3>, cudaFuncAttributeMaxDynamicSharedMemorySize, MM4_SMEM);
    cudaFuncSetAttribute(hx_attn16, cudaFuncAttributeMaxDynamicSharedMemorySize, AT_SMEM);

    // 0) weight fp16 conversion
    hx_wsplit<<<4096, 256>>>(q_w, k_w, v_w, o_w, w1, w2, p_wh);

    // 1) LN1 -> xn fp16
    hx_ln<<<M_, 256>>>(acts_in, ln1_w, p_xnh);

    // 2) fused QKV projection + xPos rope + transpose -> fp16 qt/kt/vt
    //    16 n-tiles of 128 per matrix, 48 total
    mm4<3><<<64*48, 256, MM4_SMEM>>>(M_, HID_, HID_,
        p_xnh, p_wh, nullptr, nullptr, nullptr,
        p_qt, p_kt, p_vt, p_index, 48);

    // 3) fp16 tensor-core causal flash attention -> ctx fp16
    hx_attn16<<<dim3(S_/128, B_*H_), 256, AT_SMEM>>>(p_qt, p_kt, p_vt, p_ctxh);

    // 4) O projection + residual -> acts fp32
    mm4<1><<<64*16, 256, MM4_SMEM>>>(M_, HID_, HID_,
        p_ctxh, p_wh + OFF_O, acts_in, p_acts, nullptr,
        nullptr, nullptr, nullptr, nullptr, 16);

    // 5) LN2 -> xn fp16 (reuse)
    hx_ln<<<M_, 256>>>(p_acts, ln2_w, p_xnh);

    // 6) FFN up + exact GELU -> h fp16
    mm4<2><<<64*64, 256, MM4_SMEM>>>(M_, FF_, HID_,
        p_xnh, p_wh + OFF_W1, nullptr, nullptr, p_hh,
        nullptr, nullptr, nullptr, nullptr, 64);

    // 7) FFN down + residual -> output acts
    mm4<1><<<64*16, 256, MM4_SMEM>>>(M_, HID_, FF_,
        p_hh, p_wh + OFF_W2, p_acts, out, nullptr,
        nullptr, nullptr, nullptr, nullptr, 16);

    // 8) pass-through caches
    const long actN = (long)M_*HID_;
    if (n_in > 2 && (long)out_size >= actN + (long)in_sizes[1] + (long)in_sizes[2]) {
        cudaMemcpyAsync(out + actN, d_in[1],
                        (size_t)in_sizes[1]*sizeof(float),
                        cudaMemcpyDeviceToDevice);
        cudaMemcpyAsync(out + actN + in_sizes[1], d_in[2],
                        (size_t)in_sizes[2]*sizeof(float),
                        cudaMemcpyDeviceToDevice);
    }
}